// round 2
// baseline (speedup 1.0000x reference)
#include <cuda_runtime.h>

#define SQN 2048
#define HIDN 2048
#define NHD 16
#define HDIM 128
#define H3 6144

// Scratch (static device arrays; allocation APIs are banned)
__device__ float g_M[SQN * HIDN];       // svd_token @ svd_token^T
__device__ float g_X2[SQN * HIDN];      // hidden @ M
__device__ float g_mixed[SQN * H3];     // X2 @ qkv_w^T + b   (q|k|v interleaved per head)
__device__ float g_qp[SQN * HIDN];      // q @ S_h  (rotated q)
__device__ float g_ctx[SQN * HIDN];     // attention output (pre output-proj)
__device__ float g_S[NHD * HDIM * HDIM];   // svd_qk  @ svd_qk^T  per head
__device__ float g_P[NHD * HDIM * HDIM];   // svd_vlin @ svd_vlin^T per head
__device__ float g_W2[HIDN * HIDN];        // P_h @ dense_w[h] stacked

// ---------------------------------------------------------------------------
// Generic tiled SGEMM: C[z] = A[z] @ op(B[z]) (+bias). 128x128x8 tile, 8x8 micro.
// A: [M,K] row-major (lda). B: !TB -> [K,N] (ldb); TB -> stored [N,K] (ldb), used as B^T.
// All of M,N multiples of 128 and K multiple of 8 in this problem (no guards).
// ---------------------------------------------------------------------------
template <bool TB, bool BIAS>
__global__ __launch_bounds__(256) void sgemm_kernel(
    const float* __restrict__ A, int lda, long long sA,
    const float* __restrict__ B, int ldb, long long sB,
    float* __restrict__ C, int ldc, long long sC,
    const float* __restrict__ bias, int K)
{
    __shared__ float As[8][128];
    __shared__ float Bs[8][128];

    const float* Ab = A + (long long)blockIdx.z * sA;
    const float* Bb = B + (long long)blockIdx.z * sB;
    float* Cb = C + (long long)blockIdx.z * sC;

    const int m0 = blockIdx.y * 128;
    const int n0 = blockIdx.x * 128;
    const int tid = threadIdx.x;
    const int tx = tid & 15;
    const int ty = tid >> 4;

    float acc[8][8];
#pragma unroll
    for (int i = 0; i < 8; i++)
#pragma unroll
        for (int j = 0; j < 8; j++) acc[i][j] = 0.0f;

    const int arow = tid >> 1;
    const int ak = (tid & 1) * 4;

    for (int k0 = 0; k0 < K; k0 += 8) {
        // A tile -> As[k][m] (transposed store)
        float4 av = *(const float4*)(Ab + (long long)(m0 + arow) * lda + k0 + ak);
        As[ak + 0][arow] = av.x;
        As[ak + 1][arow] = av.y;
        As[ak + 2][arow] = av.z;
        As[ak + 3][arow] = av.w;
        if (!TB) {
            const int bk = tid >> 5;
            const int bn = (tid & 31) * 4;
            *(float4*)&Bs[bk][bn] =
                *(const float4*)(Bb + (long long)(k0 + bk) * ldb + n0 + bn);
        } else {
            const int bn = tid >> 1;
            const int bk = (tid & 1) * 4;
            float4 bv = *(const float4*)(Bb + (long long)(n0 + bn) * ldb + k0 + bk);
            Bs[bk + 0][bn] = bv.x;
            Bs[bk + 1][bn] = bv.y;
            Bs[bk + 2][bn] = bv.z;
            Bs[bk + 3][bn] = bv.w;
        }
        __syncthreads();
#pragma unroll
        for (int k = 0; k < 8; k++) {
            float a[8], b[8];
            *(float4*)&a[0] = *(const float4*)&As[k][ty * 8];
            *(float4*)&a[4] = *(const float4*)&As[k][ty * 8 + 4];
            *(float4*)&b[0] = *(const float4*)&Bs[k][tx * 8];
            *(float4*)&b[4] = *(const float4*)&Bs[k][tx * 8 + 4];
#pragma unroll
            for (int i = 0; i < 8; i++)
#pragma unroll
                for (int j = 0; j < 8; j++) acc[i][j] += a[i] * b[j];
        }
        __syncthreads();
    }

#pragma unroll
    for (int i = 0; i < 8; i++) {
        const long long row = m0 + ty * 8 + i;
#pragma unroll
        for (int j = 0; j < 8; j += 4) {
            const int col = n0 + tx * 8 + j;
            float4 v;
            v.x = acc[i][j + 0];
            v.y = acc[i][j + 1];
            v.z = acc[i][j + 2];
            v.w = acc[i][j + 3];
            if (BIAS) {
                v.x += bias[col + 0];
                v.y += bias[col + 1];
                v.z += bias[col + 2];
                v.w += bias[col + 3];
            }
            *(float4*)(Cb + row * ldc + col) = v;
        }
    }
}

// ---------------------------------------------------------------------------
// Causal flash attention. One block = one (64-row Q tile, head).
// Q' (rotated) from g_qp; K,V raw from g_mixed stripes. Online softmax.
// Smem: Qt[128][64] (d-major), Kt[128][64] (d-major), Vs[64][128], Ps[64][64].
// Thread map: 16x16; thread (ty,tx) owns S rows 4ty..+3, S cols 4tx..+3,
// O rows 4ty..+3, O cols tx+16j (j=0..7).
// ---------------------------------------------------------------------------
#define ATTN_SMEM ((128 * 64 + 128 * 64 + 64 * 128 + 64 * 64) * 4)

__global__ __launch_bounds__(256, 1) void attn_kernel(
    const float* __restrict__ qp, const float* __restrict__ mixed,
    float* __restrict__ ctx)
{
    extern __shared__ float sm[];
    float* Qt = sm;                  // [128][64]
    float* Kt = Qt + 128 * 64;       // [128][64]
    float* Vs = Kt + 128 * 64;       // [64][128]
    float* Ps = Vs + 64 * 128;       // [64][64]

    const int h = blockIdx.y;
    const int rb = blockIdx.x;
    const int r0 = rb * 64;
    const int tid = threadIdx.x;
    const int tx = tid & 15;
    const int ty = tid >> 4;

    const float* Q = qp + h * 128;             // row stride 2048
    const float* Kp = mixed + h * 384 + 128;   // row stride 6144
    const float* Vp = mixed + h * 384 + 256;   // row stride 6144

    // Load Q tile transposed: Qt[d][r]
#pragma unroll
    for (int it = 0; it < 8; it++) {
        const int idx = it * 256 + tid;  // 0..2047
        const int r = idx & 63;
        const int d4 = idx >> 6;  // 0..31
        float4 v = *(const float4*)(Q + (long long)(r0 + r) * 2048 + d4 * 4);
        Qt[(d4 * 4 + 0) * 64 + r] = v.x;
        Qt[(d4 * 4 + 1) * 64 + r] = v.y;
        Qt[(d4 * 4 + 2) * 64 + r] = v.z;
        Qt[(d4 * 4 + 3) * 64 + r] = v.w;
    }

    float m_i[4], l_i[4], acc[4][8];
#pragma unroll
    for (int i = 0; i < 4; i++) {
        m_i[i] = -1e30f;
        l_i[i] = 0.0f;
#pragma unroll
        for (int j = 0; j < 8; j++) acc[i][j] = 0.0f;
    }

    const float scale = 0.08838834764831845f;  // 1/sqrt(128)

    for (int kb = 0; kb <= rb; kb++) {
        __syncthreads();  // previous iter's smem reads done (also covers Qt on iter 0)
        const int c0 = kb * 64;

        // K tile transposed: Kt[d][c]
#pragma unroll
        for (int it = 0; it < 8; it++) {
            const int idx = it * 256 + tid;
            const int r = idx & 63;
            const int d4 = idx >> 6;
            float4 v = *(const float4*)(Kp + (long long)(c0 + r) * 6144 + d4 * 4);
            Kt[(d4 * 4 + 0) * 64 + r] = v.x;
            Kt[(d4 * 4 + 1) * 64 + r] = v.y;
            Kt[(d4 * 4 + 2) * 64 + r] = v.z;
            Kt[(d4 * 4 + 3) * 64 + r] = v.w;
        }
        // V tile row-major: Vs[c][d]
#pragma unroll
        for (int it = 0; it < 8; it++) {
            const int idx = it * 256 + tid;
            const int r = idx >> 5;   // 0..63
            const int d4 = idx & 31;  // 0..31
            *(float4*)&Vs[r * 128 + d4 * 4] =
                *(const float4*)(Vp + (long long)(c0 + r) * 6144 + d4 * 4);
        }
        __syncthreads();

        // S = Q K^T (64x64 tile, 4x4 per thread)
        float s[4][4];
#pragma unroll
        for (int i = 0; i < 4; i++)
#pragma unroll
            for (int j = 0; j < 4; j++) s[i][j] = 0.0f;

#pragma unroll 16
        for (int d = 0; d < 128; d++) {
            float4 qv = *(const float4*)&Qt[d * 64 + ty * 4];
            float4 kv = *(const float4*)&Kt[d * 64 + tx * 4];
            s[0][0] += qv.x * kv.x; s[0][1] += qv.x * kv.y; s[0][2] += qv.x * kv.z; s[0][3] += qv.x * kv.w;
            s[1][0] += qv.y * kv.x; s[1][1] += qv.y * kv.y; s[1][2] += qv.y * kv.z; s[1][3] += qv.y * kv.w;
            s[2][0] += qv.z * kv.x; s[2][1] += qv.z * kv.y; s[2][2] += qv.z * kv.z; s[2][3] += qv.z * kv.w;
            s[3][0] += qv.w * kv.x; s[3][1] += qv.w * kv.y; s[3][2] += qv.w * kv.z; s[3][3] += qv.w * kv.w;
        }
#pragma unroll
        for (int i = 0; i < 4; i++)
#pragma unroll
            for (int j = 0; j < 4; j++) s[i][j] *= scale;

        if (kb == rb) {  // diagonal tile: causal mask (col > row)
#pragma unroll
            for (int i = 0; i < 4; i++)
#pragma unroll
                for (int j = 0; j < 4; j++)
                    if (c0 + tx * 4 + j > r0 + ty * 4 + i) s[i][j] = -1e30f;
        }

        // Online softmax (row stats reduced across the 16 tx lanes)
#pragma unroll
        for (int i = 0; i < 4; i++) {
            float mx = fmaxf(fmaxf(s[i][0], s[i][1]), fmaxf(s[i][2], s[i][3]));
#pragma unroll
            for (int o = 1; o < 16; o <<= 1)
                mx = fmaxf(mx, __shfl_xor_sync(0xffffffffu, mx, o));
            const float mn = fmaxf(m_i[i], mx);
            float rs = 0.0f;
#pragma unroll
            for (int j = 0; j < 4; j++) {
                s[i][j] = __expf(s[i][j] - mn);
                rs += s[i][j];
            }
#pragma unroll
            for (int o = 1; o < 16; o <<= 1)
                rs += __shfl_xor_sync(0xffffffffu, rs, o);
            const float corr = __expf(m_i[i] - mn);
            l_i[i] = l_i[i] * corr + rs;
#pragma unroll
            for (int j = 0; j < 8; j++) acc[i][j] *= corr;
            m_i[i] = mn;
            *(float4*)&Ps[(ty * 4 + i) * 64 + tx * 4] =
                make_float4(s[i][0], s[i][1], s[i][2], s[i][3]);
        }
        __syncthreads();  // Ps visible to all

        // O += P @ V
#pragma unroll 4
        for (int c = 0; c < 64; c++) {
            const float p0 = Ps[(ty * 4 + 0) * 64 + c];
            const float p1 = Ps[(ty * 4 + 1) * 64 + c];
            const float p2 = Ps[(ty * 4 + 2) * 64 + c];
            const float p3 = Ps[(ty * 4 + 3) * 64 + c];
#pragma unroll
            for (int j = 0; j < 8; j++) {
                const float vv = Vs[c * 128 + tx + 16 * j];
                acc[0][j] += p0 * vv;
                acc[1][j] += p1 * vv;
                acc[2][j] += p2 * vv;
                acc[3][j] += p3 * vv;
            }
        }
    }

#pragma unroll
    for (int i = 0; i < 4; i++) {
        const float inv = 1.0f / l_i[i];
#pragma unroll
        for (int j = 0; j < 8; j++)
            ctx[(long long)(r0 + ty * 4 + i) * 2048 + h * 128 + tx + 16 * j] =
                acc[i][j] * inv;
    }
}

// ---------------------------------------------------------------------------
extern "C" void kernel_launch(void* const* d_in, const int* in_sizes, int n_in,
                              void* d_out, int out_size)
{
    (void)in_sizes; (void)n_in; (void)out_size;
    const float* hidden  = (const float*)d_in[0];
    // d_in[1] = causal mask (known analytically; unused)
    const float* qkv_w   = (const float*)d_in[2];
    const float* qkv_b   = (const float*)d_in[3];
    const float* svd_tok = (const float*)d_in[4];
    const float* svd_qk  = (const float*)d_in[5];
    const float* svd_vl  = (const float*)d_in[6];
    const float* dense_w = (const float*)d_in[7];
    const float* dense_b = (const float*)d_in[8];
    float* out = (float*)d_out;

    float *pM, *pX2, *pmx, *pqp, *pctx, *pS, *pP, *pW2;
    cudaGetSymbolAddress((void**)&pM, g_M);
    cudaGetSymbolAddress((void**)&pX2, g_X2);
    cudaGetSymbolAddress((void**)&pmx, g_mixed);
    cudaGetSymbolAddress((void**)&pqp, g_qp);
    cudaGetSymbolAddress((void**)&pctx, g_ctx);
    cudaGetSymbolAddress((void**)&pS, g_S);
    cudaGetSymbolAddress((void**)&pP, g_P);
    cudaGetSymbolAddress((void**)&pW2, g_W2);

    cudaFuncSetAttribute(attn_kernel, cudaFuncAttributeMaxDynamicSharedMemorySize,
                         ATTN_SMEM);

    const dim3 blk(256);

    // 1) M = svd_token @ svd_token^T                      [2048,2048]
    sgemm_kernel<true, false><<<dim3(16, 16, 1), blk>>>(
        svd_tok, 2048, 0, svd_tok, 2048, 0, pM, 2048, 0, nullptr, 2048);
    // 2) X2 = hidden @ M                                  [2048,2048]
    sgemm_kernel<false, false><<<dim3(16, 16, 1), blk>>>(
        hidden, 2048, 0, pM, 2048, 0, pX2, 2048, 0, nullptr, 2048);
    // 3) mixed = X2 @ qkv_w^T + qkv_b                     [2048,6144]
    sgemm_kernel<true, true><<<dim3(48, 16, 1), blk>>>(
        pX2, 2048, 0, qkv_w, 2048, 0, pmx, 6144, 0, qkv_b, 2048);
    // 4) S_h = svd_qk[h] @ svd_qk[h]^T                    16 x [128,128]
    sgemm_kernel<true, false><<<dim3(1, 1, 16), blk>>>(
        svd_qk, 128, 16384, svd_qk, 128, 16384, pS, 128, 16384, nullptr, 128);
    // 5) P_h = svd_vlin[h] @ svd_vlin[h]^T
    sgemm_kernel<true, false><<<dim3(1, 1, 16), blk>>>(
        svd_vl, 128, 16384, svd_vl, 128, 16384, pP, 128, 16384, nullptr, 128);
    // 6) W2_h = P_h @ dense_w[h]                          16 x [128,2048]
    sgemm_kernel<false, false><<<dim3(16, 1, 16), blk>>>(
        pP, 128, 16384, dense_w, 2048, 262144, pW2, 2048, 262144, nullptr, 128);
    // 7) q'_h = q_h @ S_h                                 16 x [2048,128]
    sgemm_kernel<false, false><<<dim3(1, 16, 16), blk>>>(
        pmx, 6144, 384, pS, 128, 16384, pqp, 2048, 128, nullptr, 128);
    // 8) ctx = causal softmax(q' k^T / sqrt(128)) @ v
    attn_kernel<<<dim3(32, 16), blk, ATTN_SMEM>>>(pqp, pmx, pctx);
    // 9) out = ctx @ W2 + dense_b                         [2048,2048]
    sgemm_kernel<false, true><<<dim3(16, 16, 1), blk>>>(
        pctx, 2048, 0, pW2, 2048, 0, out, 2048, 0, dense_b, 2048);
}

// round 4
// speedup vs baseline: 1.7936x; 1.7936x over previous
#include <cuda_runtime.h>
#include <cuda_bf16.h>

#define SQN 2048
#define HIDN 2048
#define NHD 16
#define HDIM 128
#define H3 6144

// ---------------- fp32 scratch ----------------
__device__ float g_M[SQN * HIDN];
__device__ float g_X2[SQN * HIDN];
__device__ float g_mixed[SQN * H3];
__device__ float g_qp[SQN * HIDN];
__device__ float g_ctx[SQN * HIDN];
__device__ float g_S[NHD * HDIM * HDIM];
__device__ float g_P[NHD * HDIM * HDIM];
__device__ float g_W2[HIDN * HIDN];

// ---------------- bf16 hi/lo scratch ----------------
__device__ __nv_bfloat16 g_Hh[SQN * HIDN],  g_Hl[SQN * HIDN];
__device__ __nv_bfloat16 g_Rh[HIDN * HIDN], g_Rl[HIDN * HIDN];
__device__ __nv_bfloat16 g_Mh[HIDN * HIDN], g_Ml[HIDN * HIDN];
__device__ __nv_bfloat16 g_X2h[SQN * HIDN], g_X2l[SQN * HIDN];
__device__ __nv_bfloat16 g_Wqh[H3 * HIDN],  g_Wql[H3 * HIDN];
__device__ __nv_bfloat16 g_Ch[SQN * HIDN],  g_Cl[SQN * HIDN];
__device__ __nv_bfloat16 g_W2Th[HIDN * HIDN], g_W2Tl[HIDN * HIDN];

__device__ __forceinline__ unsigned smem_u32(const void* p) {
    unsigned a;
    asm("{ .reg .u64 t; cvta.to.shared.u64 t, %1; cvt.u32.u64 %0, t; }"
        : "=r"(a) : "l"(p));
    return a;
}

#define LDM_X4(r, a)                                                          \
    asm volatile("ldmatrix.sync.aligned.m8n8.x4.shared.b16 {%0,%1,%2,%3}, [%4];" \
                 : "=r"((r)[0]), "=r"((r)[1]), "=r"((r)[2]), "=r"((r)[3])     \
                 : "r"(a))

#define MMA16816(d, a, b0, b1)                                                \
    asm volatile("mma.sync.aligned.m16n8k16.row.col.f32.bf16.bf16.f32 "       \
                 "{%0,%1,%2,%3}, {%4,%5,%6,%7}, {%8,%9}, {%0,%1,%2,%3};"      \
                 : "+f"((d)[0]), "+f"((d)[1]), "+f"((d)[2]), "+f"((d)[3])     \
                 : "r"((a)[0]), "r"((a)[1]), "r"((a)[2]), "r"((a)[3]),        \
                   "r"(b0), "r"(b1))

#define CP_ASYNC16(s, g) \
    asm volatile("cp.async.cg.shared.global [%0], [%1], 16;" :: "r"(s), "l"(g))
#define CP_COMMIT() asm volatile("cp.async.commit_group;" ::: "memory")
#define CP_WAIT1()  asm volatile("cp.async.wait_group 1;" ::: "memory")
#define CP_WAIT0()  asm volatile("cp.async.wait_group 0;" ::: "memory")

// ---------------------------------------------------------------------------
// bf16x3 split conversion: x -> (hi, lo) bf16
// ---------------------------------------------------------------------------
__global__ void cvt_split(const float4* __restrict__ in,
                          __nv_bfloat162* __restrict__ hi,
                          __nv_bfloat162* __restrict__ lo, int n4)
{
    int i = blockIdx.x * blockDim.x + threadIdx.x;
    if (i >= n4) return;
    float4 v = in[i];
    __nv_bfloat16 h0 = __float2bfloat16(v.x), h1 = __float2bfloat16(v.y);
    __nv_bfloat16 h2 = __float2bfloat16(v.z), h3 = __float2bfloat16(v.w);
    __nv_bfloat162 a, b;
    a.x = h0; a.y = h1; b.x = h2; b.y = h3;
    hi[i * 2] = a; hi[i * 2 + 1] = b;
    a.x = __float2bfloat16(v.x - __bfloat162float(h0));
    a.y = __float2bfloat16(v.y - __bfloat162float(h1));
    b.x = __float2bfloat16(v.z - __bfloat162float(h2));
    b.y = __float2bfloat16(v.w - __bfloat162float(h3));
    lo[i * 2] = a; lo[i * 2 + 1] = b;
}

// Transpose [2048,2048] fp32 -> hi/lo bf16 of the transpose
__global__ void trans_cvt(const float* __restrict__ in,
                          __nv_bfloat16* __restrict__ hi,
                          __nv_bfloat16* __restrict__ lo)
{
    __shared__ float t[32][33];
    int xi = blockIdx.x * 32 + threadIdx.x;
    int yi = blockIdx.y * 32 + threadIdx.y;
#pragma unroll
    for (int j = 0; j < 32; j += 8)
        t[threadIdx.y + j][threadIdx.x] = in[(size_t)(yi + j) * 2048 + xi];
    __syncthreads();
    int xo = blockIdx.y * 32 + threadIdx.x;
    int yo = blockIdx.x * 32 + threadIdx.y;
#pragma unroll
    for (int j = 0; j < 32; j += 8) {
        float v = t[threadIdx.x][threadIdx.y + j];
        __nv_bfloat16 h = __float2bfloat16(v);
        hi[(size_t)(yo + j) * 2048 + xo] = h;
        lo[(size_t)(yo + j) * 2048 + xo] = __float2bfloat16(v - __bfloat162float(h));
    }
}

// ---------------------------------------------------------------------------
// bf16x3 GEMM via mma.sync: C[M,N] = Ahl[M,K] @ Bhl[N,K]^T (+bias)
// BM=BN=128, BK=32, 8 warps (warp tile 32x64), cp.async double buffer.
// SMEM tile: 128 rows x 32 bf16, row pitch 40 bf16 (80B) -> bank-group step
// 5 mod 8 makes consecutive rows conflict-free for ldmatrix.
// ---------------------------------------------------------------------------
#define TILE_B 10240             // one 128x32 bf16 tile @ pitch 80B
#define STAGE_B (4 * TILE_B)     // Ahi | Alo | Bhi | Blo
#define GEMM_SMEM (2 * STAGE_B)  // 81920

__global__ __launch_bounds__(256, 1)
void mma_gemm(const __nv_bfloat16* __restrict__ Ah, const __nv_bfloat16* __restrict__ Al,
              const __nv_bfloat16* __restrict__ Bh, const __nv_bfloat16* __restrict__ Bl,
              float* __restrict__ C, int ldc, const float* __restrict__ bias,
              int K, int lda, int ldb)
{
    extern __shared__ __align__(16) char smem[];

    const int tid = threadIdx.x;
    const int wid = tid >> 5;
    const int lane = tid & 31;
    const int m0 = blockIdx.y * 128;
    const int n0 = blockIdx.x * 128;
    const int wm = (wid & 3) * 32;
    const int wn = (wid >> 2) * 64;

    float acc[2][8][4];
#pragma unroll
    for (int i = 0; i < 2; i++)
#pragma unroll
        for (int j = 0; j < 8; j++)
#pragma unroll
            for (int k = 0; k < 4; k++) acc[i][j][k] = 0.0f;

    const __nv_bfloat16* srcs[4] = {Ah, Al, Bh, Bl};
    const int lds[4] = {lda, lda, ldb, ldb};
    const int r0s[4] = {m0, m0, n0, n0};

    const unsigned smb = smem_u32(smem);

    auto issue_stage = [&](int t, int buf) {
        const int k0 = t * 32;
        const unsigned sb = smb + buf * STAGE_B;
#pragma unroll
        for (int i = 0; i < 8; i++) {
            const int id = i * 256 + tid;       // 0..2047
            const int tile = id >> 9;           // 0..3
            const int cid = id & 511;
            const int row = cid >> 2;           // 0..127
            const int c = cid & 3;              // 16B chunk in row
            const __nv_bfloat16* g =
                srcs[tile] + (size_t)(r0s[tile] + row) * lds[tile] + k0 + c * 8;
            const unsigned s = sb + tile * TILE_B + row * 80 + c * 16;
            CP_ASYNC16(s, g);
        }
        CP_COMMIT();
    };

    const int T = K >> 5;
    issue_stage(0, 0);

    // ldmatrix lane addressing (bytes)
    const unsigned a_lrow = (lane & 15) * 80 + (lane >> 4) * 16;
    const unsigned b_lrow = ((lane & 7) + ((lane >> 4) << 3)) * 80 + ((lane >> 3) & 1) * 16;

    for (int t = 0; t < T; t++) {
        if (t + 1 < T) { issue_stage(t + 1, (t + 1) & 1); CP_WAIT1(); }
        else            { CP_WAIT0(); }
        __syncthreads();

        const unsigned st = smb + (t & 1) * STAGE_B;
        const unsigned aH = st;                      // Ahi
        const unsigned aL = st + TILE_B;             // Alo
        const unsigned bH = st + 2 * TILE_B;         // Bhi
        const unsigned bL = st + 3 * TILE_B;         // Blo

#pragma unroll
        for (int p = 0; p < 3; p++) {
            const unsigned abase = (p == 2 ? aL : aH) + wm * 80 + a_lrow;
            const unsigned bbase = (p == 1 ? bL : bH) + wn * 80 + b_lrow;
#pragma unroll
            for (int ks = 0; ks < 2; ks++) {
                unsigned a[2][4], b[4][4];
#pragma unroll
                for (int mt = 0; mt < 2; mt++)
                    LDM_X4(a[mt], abase + mt * (16 * 80) + ks * 32);
#pragma unroll
                for (int ng = 0; ng < 4; ng++)
                    LDM_X4(b[ng], bbase + ng * (16 * 80) + ks * 32);
#pragma unroll
                for (int mt = 0; mt < 2; mt++)
#pragma unroll
                    for (int ng = 0; ng < 4; ng++) {
                        MMA16816(acc[mt][2 * ng],     a[mt], b[ng][0], b[ng][1]);
                        MMA16816(acc[mt][2 * ng + 1], a[mt], b[ng][2], b[ng][3]);
                    }
            }
        }
        __syncthreads();
    }

    // epilogue: direct coalesced float2 stores (+bias)
#pragma unroll
    for (int mt = 0; mt < 2; mt++) {
        const int m = m0 + wm + mt * 16 + (lane >> 2);
#pragma unroll
        for (int nt = 0; nt < 8; nt++) {
            const int n = n0 + wn + nt * 8 + (lane & 3) * 2;
            float bx = 0.0f, by = 0.0f;
            if (bias) { bx = bias[n]; by = bias[n + 1]; }
            float2 v0 = make_float2(acc[mt][nt][0] + bx, acc[mt][nt][1] + by);
            float2 v1 = make_float2(acc[mt][nt][2] + bx, acc[mt][nt][3] + by);
            *(float2*)(C + (size_t)m * ldc + n) = v0;
            *(float2*)(C + (size_t)(m + 8) * ldc + n) = v1;
        }
    }
}

// ---------------------------------------------------------------------------
// fp32 SGEMM (small GEMMs only): C[z] = A[z] @ op(B[z]) (+bias)
// ---------------------------------------------------------------------------
template <bool TB, bool BIAS>
__global__ __launch_bounds__(256) void sgemm_kernel(
    const float* __restrict__ A, int lda, long long sA,
    const float* __restrict__ B, int ldb, long long sB,
    float* __restrict__ C, int ldc, long long sC,
    const float* __restrict__ bias, int K)
{
    __shared__ float As[8][128];
    __shared__ float Bs[8][128];

    const float* Ab = A + (long long)blockIdx.z * sA;
    const float* Bb = B + (long long)blockIdx.z * sB;
    float* Cb = C + (long long)blockIdx.z * sC;

    const int m0 = blockIdx.y * 128;
    const int n0 = blockIdx.x * 128;
    const int tid = threadIdx.x;
    const int tx = tid & 15;
    const int ty = tid >> 4;

    float acc[8][8];
#pragma unroll
    for (int i = 0; i < 8; i++)
#pragma unroll
        for (int j = 0; j < 8; j++) acc[i][j] = 0.0f;

    const int arow = tid >> 1;
    const int ak = (tid & 1) * 4;

    for (int k0 = 0; k0 < K; k0 += 8) {
        float4 av = *(const float4*)(Ab + (long long)(m0 + arow) * lda + k0 + ak);
        As[ak + 0][arow] = av.x;
        As[ak + 1][arow] = av.y;
        As[ak + 2][arow] = av.z;
        As[ak + 3][arow] = av.w;
        if (!TB) {
            const int bk = tid >> 5;
            const int bn = (tid & 31) * 4;
            *(float4*)&Bs[bk][bn] =
                *(const float4*)(Bb + (long long)(k0 + bk) * ldb + n0 + bn);
        } else {
            const int bn = tid >> 1;
            const int bk = (tid & 1) * 4;
            float4 bv = *(const float4*)(Bb + (long long)(n0 + bn) * ldb + k0 + bk);
            Bs[bk + 0][bn] = bv.x;
            Bs[bk + 1][bn] = bv.y;
            Bs[bk + 2][bn] = bv.z;
            Bs[bk + 3][bn] = bv.w;
        }
        __syncthreads();
#pragma unroll
        for (int k = 0; k < 8; k++) {
            float a[8], b[8];
            *(float4*)&a[0] = *(const float4*)&As[k][ty * 8];
            *(float4*)&a[4] = *(const float4*)&As[k][ty * 8 + 4];
            *(float4*)&b[0] = *(const float4*)&Bs[k][tx * 8];
            *(float4*)&b[4] = *(const float4*)&Bs[k][tx * 8 + 4];
#pragma unroll
            for (int i = 0; i < 8; i++)
#pragma unroll
                for (int j = 0; j < 8; j++) acc[i][j] += a[i] * b[j];
        }
        __syncthreads();
    }

#pragma unroll
    for (int i = 0; i < 8; i++) {
        const long long row = m0 + ty * 8 + i;
#pragma unroll
        for (int j = 0; j < 8; j += 4) {
            const int col = n0 + tx * 8 + j;
            float4 v;
            v.x = acc[i][j + 0];
            v.y = acc[i][j + 1];
            v.z = acc[i][j + 2];
            v.w = acc[i][j + 3];
            if (BIAS) {
                v.x += bias[col + 0];
                v.y += bias[col + 1];
                v.z += bias[col + 2];
                v.w += bias[col + 3];
            }
            *(float4*)(Cb + row * ldc + col) = v;
        }
    }
}

// ---------------------------------------------------------------------------
// Causal flash attention (fp32), validated in round 2.
// ---------------------------------------------------------------------------
#define ATTN_SMEM ((128 * 64 + 128 * 64 + 64 * 128 + 64 * 64) * 4)

__global__ __launch_bounds__(256, 1) void attn_kernel(
    const float* __restrict__ qp, const float* __restrict__ mixed,
    float* __restrict__ ctx)
{
    extern __shared__ float sm[];
    float* Qt = sm;
    float* Kt = Qt + 128 * 64;
    float* Vs = Kt + 128 * 64;
    float* Ps = Vs + 64 * 128;

    const int h = blockIdx.y;
    const int rb = blockIdx.x;
    const int r0 = rb * 64;
    const int tid = threadIdx.x;
    const int tx = tid & 15;
    const int ty = tid >> 4;

    const float* Q = qp + h * 128;
    const float* Kp = mixed + h * 384 + 128;
    const float* Vp = mixed + h * 384 + 256;

#pragma unroll
    for (int it = 0; it < 8; it++) {
        const int idx = it * 256 + tid;
        const int r = idx & 63;
        const int d4 = idx >> 6;
        float4 v = *(const float4*)(Q + (long long)(r0 + r) * 2048 + d4 * 4);
        Qt[(d4 * 4 + 0) * 64 + r] = v.x;
        Qt[(d4 * 4 + 1) * 64 + r] = v.y;
        Qt[(d4 * 4 + 2) * 64 + r] = v.z;
        Qt[(d4 * 4 + 3) * 64 + r] = v.w;
    }

    float m_i[4], l_i[4], acc[4][8];
#pragma unroll
    for (int i = 0; i < 4; i++) {
        m_i[i] = -1e30f;
        l_i[i] = 0.0f;
#pragma unroll
        for (int j = 0; j < 8; j++) acc[i][j] = 0.0f;
    }

    const float scale = 0.08838834764831845f;

    for (int kb = 0; kb <= rb; kb++) {
        __syncthreads();
        const int c0 = kb * 64;

#pragma unroll
        for (int it = 0; it < 8; it++) {
            const int idx = it * 256 + tid;
            const int r = idx & 63;
            const int d4 = idx >> 6;
            float4 v = *(const float4*)(Kp + (long long)(c0 + r) * 6144 + d4 * 4);
            Kt[(d4 * 4 + 0) * 64 + r] = v.x;
            Kt[(d4 * 4 + 1) * 64 + r] = v.y;
            Kt[(d4 * 4 + 2) * 64 + r] = v.z;
            Kt[(d4 * 4 + 3) * 64 + r] = v.w;
        }
#pragma unroll
        for (int it = 0; it < 8; it++) {
            const int idx = it * 256 + tid;
            const int r = idx >> 5;
            const int d4 = idx & 31;
            *(float4*)&Vs[r * 128 + d4 * 4] =
                *(const float4*)(Vp + (long long)(c0 + r) * 6144 + d4 * 4);
        }
        __syncthreads();

        float s[4][4];
#pragma unroll
        for (int i = 0; i < 4; i++)
#pragma unroll
            for (int j = 0; j < 4; j++) s[i][j] = 0.0f;

#pragma unroll 16
        for (int d = 0; d < 128; d++) {
            float4 qv = *(const float4*)&Qt[d * 64 + ty * 4];
            float4 kv = *(const float4*)&Kt[d * 64 + tx * 4];
            s[0][0] += qv.x * kv.x; s[0][1] += qv.x * kv.y; s[0][2] += qv.x * kv.z; s[0][3] += qv.x * kv.w;
            s[1][0] += qv.y * kv.x; s[1][1] += qv.y * kv.y; s[1][2] += qv.y * kv.z; s[1][3] += qv.y * kv.w;
            s[2][0] += qv.z * kv.x; s[2][1] += qv.z * kv.y; s[2][2] += qv.z * kv.z; s[2][3] += qv.z * kv.w;
            s[3][0] += qv.w * kv.x; s[3][1] += qv.w * kv.y; s[3][2] += qv.w * kv.z; s[3][3] += qv.w * kv.w;
        }
#pragma unroll
        for (int i = 0; i < 4; i++)
#pragma unroll
            for (int j = 0; j < 4; j++) s[i][j] *= scale;

        if (kb == rb) {
#pragma unroll
            for (int i = 0; i < 4; i++)
#pragma unroll
                for (int j = 0; j < 4; j++)
                    if (c0 + tx * 4 + j > r0 + ty * 4 + i) s[i][j] = -1e30f;
        }

#pragma unroll
        for (int i = 0; i < 4; i++) {
            float mx = fmaxf(fmaxf(s[i][0], s[i][1]), fmaxf(s[i][2], s[i][3]));
#pragma unroll
            for (int o = 1; o < 16; o <<= 1)
                mx = fmaxf(mx, __shfl_xor_sync(0xffffffffu, mx, o));
            const float mn = fmaxf(m_i[i], mx);
            float rs = 0.0f;
#pragma unroll
            for (int j = 0; j < 4; j++) {
                s[i][j] = __expf(s[i][j] - mn);
                rs += s[i][j];
            }
#pragma unroll
            for (int o = 1; o < 16; o <<= 1)
                rs += __shfl_xor_sync(0xffffffffu, rs, o);
            const float corr = __expf(m_i[i] - mn);
            l_i[i] = l_i[i] * corr + rs;
#pragma unroll
            for (int j = 0; j < 8; j++) acc[i][j] *= corr;
            m_i[i] = mn;
            *(float4*)&Ps[(ty * 4 + i) * 64 + tx * 4] =
                make_float4(s[i][0], s[i][1], s[i][2], s[i][3]);
        }
        __syncthreads();

#pragma unroll 4
        for (int c = 0; c < 64; c++) {
            const float p0 = Ps[(ty * 4 + 0) * 64 + c];
            const float p1 = Ps[(ty * 4 + 1) * 64 + c];
            const float p2 = Ps[(ty * 4 + 2) * 64 + c];
            const float p3 = Ps[(ty * 4 + 3) * 64 + c];
#pragma unroll
            for (int j = 0; j < 8; j++) {
                const float vv = Vs[c * 128 + tx + 16 * j];
                acc[0][j] += p0 * vv;
                acc[1][j] += p1 * vv;
                acc[2][j] += p2 * vv;
                acc[3][j] += p3 * vv;
            }
        }
    }

#pragma unroll
    for (int i = 0; i < 4; i++) {
        const float inv = 1.0f / l_i[i];
#pragma unroll
        for (int j = 0; j < 8; j++)
            ctx[(long long)(r0 + ty * 4 + i) * 2048 + h * 128 + tx + 16 * j] =
                acc[i][j] * inv;
    }
}

// ---------------------------------------------------------------------------
extern "C" void kernel_launch(void* const* d_in, const int* in_sizes, int n_in,
                              void* d_out, int out_size)
{
    (void)in_sizes; (void)n_in; (void)out_size;
    const float* hidden  = (const float*)d_in[0];
    const float* qkv_w   = (const float*)d_in[2];
    const float* qkv_b   = (const float*)d_in[3];
    const float* svd_tok = (const float*)d_in[4];
    const float* svd_qk  = (const float*)d_in[5];
    const float* svd_vl  = (const float*)d_in[6];
    const float* dense_w = (const float*)d_in[7];
    const float* dense_b = (const float*)d_in[8];
    float* out = (float*)d_out;

    float *pM, *pX2, *pmx, *pqp, *pctx, *pS, *pP, *pW2;
    cudaGetSymbolAddress((void**)&pM, g_M);
    cudaGetSymbolAddress((void**)&pX2, g_X2);
    cudaGetSymbolAddress((void**)&pmx, g_mixed);
    cudaGetSymbolAddress((void**)&pqp, g_qp);
    cudaGetSymbolAddress((void**)&pctx, g_ctx);
    cudaGetSymbolAddress((void**)&pS, g_S);
    cudaGetSymbolAddress((void**)&pP, g_P);
    cudaGetSymbolAddress((void**)&pW2, g_W2);

    __nv_bfloat16 *pHh, *pHl, *pRh, *pRl, *pMh, *pMl, *pX2h, *pX2l;
    __nv_bfloat16 *pWqh, *pWql, *pCh, *pCl, *pW2Th, *pW2Tl;
    cudaGetSymbolAddress((void**)&pHh, g_Hh);   cudaGetSymbolAddress((void**)&pHl, g_Hl);
    cudaGetSymbolAddress((void**)&pRh, g_Rh);   cudaGetSymbolAddress((void**)&pRl, g_Rl);
    cudaGetSymbolAddress((void**)&pMh, g_Mh);   cudaGetSymbolAddress((void**)&pMl, g_Ml);
    cudaGetSymbolAddress((void**)&pX2h, g_X2h); cudaGetSymbolAddress((void**)&pX2l, g_X2l);
    cudaGetSymbolAddress((void**)&pWqh, g_Wqh); cudaGetSymbolAddress((void**)&pWql, g_Wql);
    cudaGetSymbolAddress((void**)&pCh, g_Ch);   cudaGetSymbolAddress((void**)&pCl, g_Cl);
    cudaGetSymbolAddress((void**)&pW2Th, g_W2Th); cudaGetSymbolAddress((void**)&pW2Tl, g_W2Tl);

    cudaFuncSetAttribute(mma_gemm, cudaFuncAttributeMaxDynamicSharedMemorySize, GEMM_SMEM);
    cudaFuncSetAttribute(attn_kernel, cudaFuncAttributeMaxDynamicSharedMemorySize, ATTN_SMEM);

    const dim3 blk(256);
    const int N4_2048 = (2048 * 2048) / 4;
    const int N4_W = (6144 * 2048) / 4;

    // input conversions
    cvt_split<<<N4_2048 / 256, 256>>>((const float4*)hidden, (__nv_bfloat162*)pHh, (__nv_bfloat162*)pHl, N4_2048);
    cvt_split<<<N4_2048 / 256, 256>>>((const float4*)svd_tok, (__nv_bfloat162*)pRh, (__nv_bfloat162*)pRl, N4_2048);
    cvt_split<<<N4_W / 256, 256>>>((const float4*)qkv_w, (__nv_bfloat162*)pWqh, (__nv_bfloat162*)pWql, N4_W);

    // 1) M = R @ R^T  (bf16x3 mma)
    mma_gemm<<<dim3(16, 16), blk, GEMM_SMEM>>>(pRh, pRl, pRh, pRl, pM, 2048, nullptr, 2048, 2048, 2048);
    cvt_split<<<N4_2048 / 256, 256>>>((const float4*)pM, (__nv_bfloat162*)pMh, (__nv_bfloat162*)pMl, N4_2048);
    // 2) X2 = hidden @ M  (M symmetric -> A @ M^T)
    mma_gemm<<<dim3(16, 16), blk, GEMM_SMEM>>>(pHh, pHl, pMh, pMl, pX2, 2048, nullptr, 2048, 2048, 2048);
    cvt_split<<<N4_2048 / 256, 256>>>((const float4*)pX2, (__nv_bfloat162*)pX2h, (__nv_bfloat162*)pX2l, N4_2048);
    // 3) mixed = X2 @ qkv_w^T + qkv_b
    mma_gemm<<<dim3(48, 16), blk, GEMM_SMEM>>>(pX2h, pX2l, pWqh, pWql, pmx, 6144, qkv_b, 2048, 2048, 2048);

    // 4) S_h = svd_qk[h] @ svd_qk[h]^T
    sgemm_kernel<true, false><<<dim3(1, 1, 16), blk>>>(
        svd_qk, 128, 16384, svd_qk, 128, 16384, pS, 128, 16384, nullptr, 128);
    // 5) P_h = svd_vlin[h] @ svd_vlin[h]^T
    sgemm_kernel<true, false><<<dim3(1, 1, 16), blk>>>(
        svd_vl, 128, 16384, svd_vl, 128, 16384, pP, 128, 16384, nullptr, 128);
    // 6) W2_h = P_h @ dense_w[h]
    sgemm_kernel<false, false><<<dim3(16, 1, 16), blk>>>(
        pP, 128, 16384, dense_w, 2048, 262144, pW2, 2048, 262144, nullptr, 128);
    trans_cvt<<<dim3(64, 64), dim3(32, 8)>>>(pW2, pW2Th, pW2Tl);
    // 7) q'_h = q_h @ S_h
    sgemm_kernel<false, false><<<dim3(1, 16, 16), blk>>>(
        pmx, 6144, 384, pS, 128, 16384, pqp, 2048, 128, nullptr, 128);
    // 8) ctx = causal softmax(q' k^T / sqrt(128)) @ v
    attn_kernel<<<dim3(32, 16), blk, ATTN_SMEM>>>(pqp, pmx, pctx);
    cvt_split<<<N4_2048 / 256, 256>>>((const float4*)pctx, (__nv_bfloat162*)pCh, (__nv_bfloat162*)pCl, N4_2048);
    // 9) out = ctx @ W2 + dense_b
    mma_gemm<<<dim3(16, 16), blk, GEMM_SMEM>>>(pCh, pCl, pW2Th, pW2Tl, out, 2048, dense_b, 2048, 2048, 2048);
}

// round 5
// speedup vs baseline: 2.4089x; 1.3431x over previous
#include <cuda_runtime.h>
#include <cuda_bf16.h>

#define SQN 2048
#define HIDN 2048
#define NHD 16
#define HDIM 128
#define H3 6144

// ---------------- fp32 scratch ----------------
__device__ float g_M[SQN * HIDN];
__device__ float g_X2[SQN * HIDN];
__device__ float g_mixed[SQN * H3];
__device__ float g_qp[SQN * HIDN];
__device__ float g_S[NHD * HDIM * HDIM];
__device__ float g_P[NHD * HDIM * HDIM];
__device__ float g_W2[HIDN * HIDN];

// ---------------- bf16 hi/lo scratch ----------------
__device__ __nv_bfloat16 g_Hh[SQN * HIDN],  g_Hl[SQN * HIDN];
__device__ __nv_bfloat16 g_Rh[HIDN * HIDN], g_Rl[HIDN * HIDN];
__device__ __nv_bfloat16 g_Mh[HIDN * HIDN], g_Ml[HIDN * HIDN];
__device__ __nv_bfloat16 g_X2h[SQN * HIDN], g_X2l[SQN * HIDN];
__device__ __nv_bfloat16 g_Wqh[H3 * HIDN],  g_Wql[H3 * HIDN];
__device__ __nv_bfloat16 g_Ch[SQN * HIDN],  g_Cl[SQN * HIDN];
__device__ __nv_bfloat16 g_W2Th[HIDN * HIDN], g_W2Tl[HIDN * HIDN];
__device__ __nv_bfloat16 g_qph[SQN * HIDN], g_qpl[SQN * HIDN];
__device__ __nv_bfloat16 g_Kh[NHD * SQN * HDIM], g_Kl[NHD * SQN * HDIM];
__device__ __nv_bfloat16 g_Vth[NHD * HDIM * SQN], g_Vtl[NHD * HDIM * SQN];

__device__ __forceinline__ unsigned smem_u32(const void* p) {
    unsigned a;
    asm("{ .reg .u64 t; cvta.to.shared.u64 t, %1; cvt.u32.u64 %0, t; }"
        : "=r"(a) : "l"(p));
    return a;
}

#define LDM_X4(r, a)                                                          \
    asm volatile("ldmatrix.sync.aligned.m8n8.x4.shared.b16 {%0,%1,%2,%3}, [%4];" \
                 : "=r"((r)[0]), "=r"((r)[1]), "=r"((r)[2]), "=r"((r)[3])     \
                 : "r"(a))

#define MMA16816(d, a, b0, b1)                                                \
    asm volatile("mma.sync.aligned.m16n8k16.row.col.f32.bf16.bf16.f32 "       \
                 "{%0,%1,%2,%3}, {%4,%5,%6,%7}, {%8,%9}, {%0,%1,%2,%3};"      \
                 : "+f"((d)[0]), "+f"((d)[1]), "+f"((d)[2]), "+f"((d)[3])     \
                 : "r"((a)[0]), "r"((a)[1]), "r"((a)[2]), "r"((a)[3]),        \
                   "r"(b0), "r"(b1))

#define CP_ASYNC16(s, g) \
    asm volatile("cp.async.cg.shared.global [%0], [%1], 16;" :: "r"(s), "l"(g))
#define CP_COMMIT() asm volatile("cp.async.commit_group;" ::: "memory")
#define CP_WAIT2()  asm volatile("cp.async.wait_group 2;" ::: "memory")
#define CP_WAIT1()  asm volatile("cp.async.wait_group 1;" ::: "memory")
#define CP_WAIT0()  asm volatile("cp.async.wait_group 0;" ::: "memory")

__device__ __forceinline__ unsigned pack_bf16(float lo, float hi) {
    unsigned r;
    asm("cvt.rn.bf16x2.f32 %0, %1, %2;" : "=r"(r) : "f"(hi), "f"(lo));
    return r;
}
__device__ __forceinline__ unsigned pack_res(float lo, float hi, unsigned hp) {
    __nv_bfloat162 h = *reinterpret_cast<__nv_bfloat162*>(&hp);
    return pack_bf16(lo - __bfloat162float(h.x), hi - __bfloat162float(h.y));
}

// ---------------------------------------------------------------------------
// bf16x3 split conversion: x -> (hi, lo)
// ---------------------------------------------------------------------------
__global__ void cvt_split(const float4* __restrict__ in,
                          __nv_bfloat162* __restrict__ hi,
                          __nv_bfloat162* __restrict__ lo, int n4)
{
    int i = blockIdx.x * blockDim.x + threadIdx.x;
    if (i >= n4) return;
    float4 v = in[i];
    __nv_bfloat16 h0 = __float2bfloat16(v.x), h1 = __float2bfloat16(v.y);
    __nv_bfloat16 h2 = __float2bfloat16(v.z), h3 = __float2bfloat16(v.w);
    __nv_bfloat162 a, b;
    a.x = h0; a.y = h1; b.x = h2; b.y = h3;
    hi[i * 2] = a; hi[i * 2 + 1] = b;
    a.x = __float2bfloat16(v.x - __bfloat162float(h0));
    a.y = __float2bfloat16(v.y - __bfloat162float(h1));
    b.x = __float2bfloat16(v.z - __bfloat162float(h2));
    b.y = __float2bfloat16(v.w - __bfloat162float(h3));
    lo[i * 2] = a; lo[i * 2 + 1] = b;
}

// Transpose [2048,2048] fp32 -> hi/lo bf16 of the transpose
__global__ void trans_cvt(const float* __restrict__ in,
                          __nv_bfloat16* __restrict__ hi,
                          __nv_bfloat16* __restrict__ lo)
{
    __shared__ float t[32][33];
    int xi = blockIdx.x * 32 + threadIdx.x;
    int yi = blockIdx.y * 32 + threadIdx.y;
#pragma unroll
    for (int j = 0; j < 32; j += 8)
        t[threadIdx.y + j][threadIdx.x] = in[(size_t)(yi + j) * 2048 + xi];
    __syncthreads();
    int xo = blockIdx.y * 32 + threadIdx.x;
    int yo = blockIdx.x * 32 + threadIdx.y;
#pragma unroll
    for (int j = 0; j < 32; j += 8) {
        float v = t[threadIdx.x][threadIdx.y + j];
        __nv_bfloat16 h = __float2bfloat16(v);
        hi[(size_t)(yo + j) * 2048 + xo] = h;
        lo[(size_t)(yo + j) * 2048 + xo] = __float2bfloat16(v - __bfloat162float(h));
    }
}

// K stripe split: mixed[t, h*384+128+d] -> Kh/Kl [h][t][d]
__global__ void split_k(const float* __restrict__ mixed,
                        __nv_bfloat16* __restrict__ Kh_,
                        __nv_bfloat16* __restrict__ Kl_)
{
    int i = blockIdx.x * 256 + threadIdx.x;      // 16*2048*32 float4
    int d4 = i & 31;
    int tt = (i >> 5) & 2047;
    int hh = i >> 16;
    float4 v = *(const float4*)(mixed + (size_t)tt * 6144 + hh * 384 + 128 + d4 * 4);
    size_t o = ((size_t)hh * 2048 + tt) * 128 + d4 * 4;
    unsigned p0 = pack_bf16(v.x, v.y), p1 = pack_bf16(v.z, v.w);
    *(unsigned*)(Kh_ + o) = p0;
    *(unsigned*)(Kh_ + o + 2) = p1;
    *(unsigned*)(Kl_ + o) = pack_res(v.x, v.y, p0);
    *(unsigned*)(Kl_ + o + 2) = pack_res(v.z, v.w, p1);
}

// V stripe transpose+split: mixed[t, h*384+256+e] -> Vth/Vtl [h][e][t]
__global__ void vtrans_split(const float* __restrict__ mixed,
                             __nv_bfloat16* __restrict__ Vth_,
                             __nv_bfloat16* __restrict__ Vtl_)
{
    __shared__ float tl[32][33];
    int hh = blockIdx.z;
    int e0 = blockIdx.y * 32, t0 = blockIdx.x * 32;
    int tx = threadIdx.x, ty = threadIdx.y;
#pragma unroll
    for (int j = 0; j < 32; j += 8)
        tl[ty + j][tx] = mixed[(size_t)(t0 + ty + j) * 6144 + hh * 384 + 256 + e0 + tx];
    __syncthreads();
#pragma unroll
    for (int j = 0; j < 32; j += 8) {
        float v = tl[tx][ty + j];
        size_t o = ((size_t)hh * 128 + e0 + ty + j) * 2048 + t0 + tx;
        __nv_bfloat16 hb = __float2bfloat16(v);
        Vth_[o] = hb;
        Vtl_[o] = __float2bfloat16(v - __bfloat162float(hb));
    }
}

// ---------------------------------------------------------------------------
// bf16x3 GEMM via mma.sync, fragment-reuse mainloop, 3-stage cp.async.
// C[M,N] = Ahl[M,K] @ Bhl[N,K]^T (+bias). BM=BN=128, BK=32, 8 warps (32x64).
// SMEM pitch 80B (5 mod 8) -> conflict-free ldmatrix.
// ---------------------------------------------------------------------------
#define TILE_B 10240
#define STAGE_B (4 * TILE_B)
#define GEMM_SMEM (3 * STAGE_B)

__global__ __launch_bounds__(256, 1)
void mma_gemm(const __nv_bfloat16* __restrict__ Ah, const __nv_bfloat16* __restrict__ Al,
              const __nv_bfloat16* __restrict__ Bh, const __nv_bfloat16* __restrict__ Bl,
              float* __restrict__ C, int ldc, const float* __restrict__ bias,
              int K, int lda, int ldb)
{
    extern __shared__ __align__(16) char smem[];

    const int tid = threadIdx.x;
    const int wid = tid >> 5;
    const int lane = tid & 31;
    const int m0 = blockIdx.y * 128;
    const int n0 = blockIdx.x * 128;
    const int wm = (wid & 3) * 32;
    const int wn = (wid >> 2) * 64;

    float acc[2][8][4];
#pragma unroll
    for (int i = 0; i < 2; i++)
#pragma unroll
        for (int j = 0; j < 8; j++)
#pragma unroll
            for (int k = 0; k < 4; k++) acc[i][j][k] = 0.0f;

    const __nv_bfloat16* srcs[4] = {Ah, Al, Bh, Bl};
    const int lds[4] = {lda, lda, ldb, ldb};
    const int r0s[4] = {m0, m0, n0, n0};

    const unsigned smb = smem_u32(smem);

    auto issue_stage = [&](int t, int buf) {
        const int k0 = t * 32;
        const unsigned sb = smb + buf * STAGE_B;
#pragma unroll
        for (int i = 0; i < 8; i++) {
            const int id = i * 256 + tid;
            const int tile = id >> 9;
            const int cid = id & 511;
            const int row = cid >> 2;
            const int c = cid & 3;
            const __nv_bfloat16* g =
                srcs[tile] + (size_t)(r0s[tile] + row) * lds[tile] + k0 + c * 8;
            CP_ASYNC16(sb + tile * TILE_B + row * 80 + c * 16, g);
        }
        CP_COMMIT();
    };

    const int T = K >> 5;
    issue_stage(0, 0);
    issue_stage(1, 1);

    const unsigned a_lrow = (lane & 15) * 80 + (lane >> 4) * 16;
    const unsigned b_lrow = ((lane & 7) + ((lane >> 4) << 3)) * 80 + ((lane >> 3) & 1) * 16;

    for (int t = 0; t < T; t++) {
        if (t + 2 < T) { issue_stage(t + 2, (t + 2) % 3); CP_WAIT2(); }
        else if (t + 1 < T) { CP_WAIT1(); }
        else { CP_WAIT0(); }
        __syncthreads();

        const unsigned st = smb + (t % 3) * STAGE_B;
        const unsigned aHb = st + wm * 80 + a_lrow;
        const unsigned aLb = st + TILE_B + wm * 80 + a_lrow;
        const unsigned bHb = st + 2 * TILE_B + wn * 80 + b_lrow;
        const unsigned bLb = st + 3 * TILE_B + wn * 80 + b_lrow;

#pragma unroll
        for (int ks = 0; ks < 2; ks++) {
            unsigned aH[2][4], aL[2][4], bH[4][4], bL[4][4];
#pragma unroll
            for (int mt = 0; mt < 2; mt++) {
                LDM_X4(aH[mt], aHb + mt * (16 * 80) + ks * 32);
                LDM_X4(aL[mt], aLb + mt * (16 * 80) + ks * 32);
            }
#pragma unroll
            for (int ng = 0; ng < 4; ng++) {
                LDM_X4(bH[ng], bHb + ng * (16 * 80) + ks * 32);
                LDM_X4(bL[ng], bLb + ng * (16 * 80) + ks * 32);
            }
#pragma unroll
            for (int mt = 0; mt < 2; mt++)
#pragma unroll
                for (int ng = 0; ng < 4; ng++) {
                    MMA16816(acc[mt][2 * ng],     aH[mt], bH[ng][0], bH[ng][1]);
                    MMA16816(acc[mt][2 * ng + 1], aH[mt], bH[ng][2], bH[ng][3]);
                    MMA16816(acc[mt][2 * ng],     aH[mt], bL[ng][0], bL[ng][1]);
                    MMA16816(acc[mt][2 * ng + 1], aH[mt], bL[ng][2], bL[ng][3]);
                    MMA16816(acc[mt][2 * ng],     aL[mt], bH[ng][0], bH[ng][1]);
                    MMA16816(acc[mt][2 * ng + 1], aL[mt], bH[ng][2], bH[ng][3]);
                }
        }
        __syncthreads();
    }

#pragma unroll
    for (int mt = 0; mt < 2; mt++) {
        const int m = m0 + wm + mt * 16 + (lane >> 2);
#pragma unroll
        for (int nt = 0; nt < 8; nt++) {
            const int n = n0 + wn + nt * 8 + (lane & 3) * 2;
            float bx = 0.0f, by = 0.0f;
            if (bias) { bx = bias[n]; by = bias[n + 1]; }
            float2 v0 = make_float2(acc[mt][nt][0] + bx, acc[mt][nt][1] + by);
            float2 v1 = make_float2(acc[mt][nt][2] + bx, acc[mt][nt][3] + by);
            *(float2*)(C + (size_t)m * ldc + n) = v0;
            *(float2*)(C + (size_t)(m + 8) * ldc + n) = v1;
        }
    }
}

// ---------------------------------------------------------------------------
// fp32 SGEMM (small GEMMs only)
// ---------------------------------------------------------------------------
template <bool TB, bool BIAS>
__global__ __launch_bounds__(256) void sgemm_kernel(
    const float* __restrict__ A, int lda, long long sA,
    const float* __restrict__ B, int ldb, long long sB,
    float* __restrict__ C, int ldc, long long sC,
    const float* __restrict__ bias, int K)
{
    __shared__ float As[8][128];
    __shared__ float Bs[8][128];

    const float* Ab = A + (long long)blockIdx.z * sA;
    const float* Bb = B + (long long)blockIdx.z * sB;
    float* Cb = C + (long long)blockIdx.z * sC;

    const int m0 = blockIdx.y * 128;
    const int n0 = blockIdx.x * 128;
    const int tid = threadIdx.x;
    const int tx = tid & 15;
    const int ty = tid >> 4;

    float acc[8][8];
#pragma unroll
    for (int i = 0; i < 8; i++)
#pragma unroll
        for (int j = 0; j < 8; j++) acc[i][j] = 0.0f;

    const int arow = tid >> 1;
    const int ak = (tid & 1) * 4;

    for (int k0 = 0; k0 < K; k0 += 8) {
        float4 av = *(const float4*)(Ab + (long long)(m0 + arow) * lda + k0 + ak);
        As[ak + 0][arow] = av.x;
        As[ak + 1][arow] = av.y;
        As[ak + 2][arow] = av.z;
        As[ak + 3][arow] = av.w;
        if (!TB) {
            const int bk = tid >> 5;
            const int bn = (tid & 31) * 4;
            *(float4*)&Bs[bk][bn] =
                *(const float4*)(Bb + (long long)(k0 + bk) * ldb + n0 + bn);
        } else {
            const int bn = tid >> 1;
            const int bk = (tid & 1) * 4;
            float4 bv = *(const float4*)(Bb + (long long)(n0 + bn) * ldb + k0 + bk);
            Bs[bk + 0][bn] = bv.x;
            Bs[bk + 1][bn] = bv.y;
            Bs[bk + 2][bn] = bv.z;
            Bs[bk + 3][bn] = bv.w;
        }
        __syncthreads();
#pragma unroll
        for (int k = 0; k < 8; k++) {
            float a[8], b[8];
            *(float4*)&a[0] = *(const float4*)&As[k][ty * 8];
            *(float4*)&a[4] = *(const float4*)&As[k][ty * 8 + 4];
            *(float4*)&b[0] = *(const float4*)&Bs[k][tx * 8];
            *(float4*)&b[4] = *(const float4*)&Bs[k][tx * 8 + 4];
#pragma unroll
            for (int i = 0; i < 8; i++)
#pragma unroll
                for (int j = 0; j < 8; j++) acc[i][j] += a[i] * b[j];
        }
        __syncthreads();
    }

#pragma unroll
    for (int i = 0; i < 8; i++) {
        const long long row = m0 + ty * 8 + i;
#pragma unroll
        for (int j = 0; j < 8; j += 4) {
            const int col = n0 + tx * 8 + j;
            float4 v;
            v.x = acc[i][j + 0];
            v.y = acc[i][j + 1];
            v.z = acc[i][j + 2];
            v.w = acc[i][j + 3];
            if (BIAS) {
                v.x += bias[col + 0];
                v.y += bias[col + 1];
                v.z += bias[col + 2];
                v.w += bias[col + 3];
            }
            *(float4*)(Cb + row * ldc + col) = v;
        }
    }
}

// ---------------------------------------------------------------------------
// Tensor-core causal flash attention (bf16x3 on QK^T and PV).
// Block = 128 Q rows x 1 head; K tiles of 64. 8 warps, each 16 Q rows (FA2).
// Writes ctx directly as hi/lo bf16 into g_Ch/g_Cl.
// ---------------------------------------------------------------------------
#define AQ_PITCH 272            // 17 x 16B, conflict-free ldmatrix
#define AV_PITCH 144            // 9 x 16B
#define SQH_B (128 * AQ_PITCH)  // 34816 per hi/lo
#define SKH_B (64 * AQ_PITCH)   // 17408
#define SVH_B (128 * AV_PITCH)  // 18432
#define KV_STAGE (2 * SKH_B + 2 * SVH_B)          // 71680
#define ATTN2_SMEM (2 * SQH_B + 2 * KV_STAGE)     // 212992

__global__ __launch_bounds__(256, 1) void attn_mma(
    const __nv_bfloat16* __restrict__ qph, const __nv_bfloat16* __restrict__ qpl,
    const __nv_bfloat16* __restrict__ Kh_, const __nv_bfloat16* __restrict__ Kl_,
    const __nv_bfloat16* __restrict__ Vth_, const __nv_bfloat16* __restrict__ Vtl_,
    __nv_bfloat16* __restrict__ Ch_, __nv_bfloat16* __restrict__ Cl_)
{
    extern __shared__ __align__(16) char sm[];
    const int h = blockIdx.y;
    const int rb = (int)gridDim.x - 1 - (int)blockIdx.x;  // big blocks first
    const int r0 = rb * 128;
    const int tid = threadIdx.x;
    const int wid = tid >> 5;
    const int lane = tid & 31;

    const unsigned sQh = smem_u32(sm);
    const unsigned sQl = sQh + SQH_B;
    const unsigned sKV0 = sQl + SQH_B;

    // Q tile loads (hi+lo): 128 rows x 256B
    {
        const __nv_bfloat16* gq = qph + (size_t)r0 * 2048 + h * 128;
        const __nv_bfloat16* gql = qpl + (size_t)r0 * 2048 + h * 128;
#pragma unroll
        for (int it = 0; it < 8; it++) {
            int id = it * 256 + tid;
            int row = id >> 4, c = id & 15;
            CP_ASYNC16(sQh + row * AQ_PITCH + c * 16, gq + (size_t)row * 2048 + c * 8);
            CP_ASYNC16(sQl + row * AQ_PITCH + c * 16, gql + (size_t)row * 2048 + c * 8);
        }
    }
    const __nv_bfloat16* gK = Kh_ + (size_t)h * 2048 * 128;
    const __nv_bfloat16* gKl = Kl_ + (size_t)h * 2048 * 128;
    const __nv_bfloat16* gV = Vth_ + (size_t)h * 128 * 2048;
    const __nv_bfloat16* gVl = Vtl_ + (size_t)h * 128 * 2048;

    auto issue_kv = [&](int t, int buf) {
        const int t0 = t * 64;
        const unsigned sb = sKV0 + buf * KV_STAGE;
#pragma unroll
        for (int it = 0; it < 4; it++) {      // K: 64 rows x 16 chunks, hi+lo
            int id = it * 256 + tid;
            int row = id >> 4, c = id & 15;
            CP_ASYNC16(sb + row * AQ_PITCH + c * 16, gK + (size_t)(t0 + row) * 128 + c * 8);
            CP_ASYNC16(sb + SKH_B + row * AQ_PITCH + c * 16, gKl + (size_t)(t0 + row) * 128 + c * 8);
        }
#pragma unroll
        for (int it = 0; it < 4; it++) {      // V: 128 rows x 8 chunks, hi+lo
            int id = it * 256 + tid;
            int row = id >> 3, c = id & 7;
            CP_ASYNC16(sb + 2 * SKH_B + row * AV_PITCH + c * 16, gV + (size_t)row * 2048 + t0 + c * 8);
            CP_ASYNC16(sb + 2 * SKH_B + SVH_B + row * AV_PITCH + c * 16, gVl + (size_t)row * 2048 + t0 + c * 8);
        }
    };

    issue_kv(0, 0);
    CP_COMMIT();   // group 0 = Q + KV(0)

    float sacc[8][4];
    float Oacc[16][4];
#pragma unroll
    for (int i = 0; i < 16; i++)
#pragma unroll
        for (int j = 0; j < 4; j++) Oacc[i][j] = 0.0f;
    float m1 = -1e30f, m2 = -1e30f, l1 = 0.0f, l2 = 0.0f;

    const int gr1 = r0 + wid * 16 + (lane >> 2);
    const int gr2 = gr1 + 8;
    const float scale = 0.08838834764831845f;

    const unsigned a_off = (lane & 15) * AQ_PITCH + (lane >> 4) * 16;
    const unsigned kb_off = ((lane & 7) + ((lane >> 4) << 3)) * AQ_PITCH + ((lane >> 3) & 1) * 16;
    const unsigned vb_off = ((lane & 7) + ((lane >> 4) << 3)) * AV_PITCH + ((lane >> 3) & 1) * 16;
    const unsigned aQh_b = sQh + wid * 16 * AQ_PITCH + a_off;
    const unsigned aQl_b = sQl + wid * 16 * AQ_PITCH + a_off;

    const int T = 2 * rb + 2;
    for (int t = 0; t < T; t++) {
        if (t + 1 < T) { issue_kv(t + 1, (t + 1) & 1); CP_COMMIT(); CP_WAIT1(); }
        else { CP_WAIT0(); }
        __syncthreads();

        const unsigned sb = sKV0 + (t & 1) * KV_STAGE;
        const unsigned kh_b = sb + kb_off;
        const unsigned kl_b = sb + SKH_B + kb_off;

#pragma unroll
        for (int i = 0; i < 8; i++)
#pragma unroll
            for (int j = 0; j < 4; j++) sacc[i][j] = 0.0f;

        // S = Q' K^T (bf16x3)
#pragma unroll
        for (int kd = 0; kd < 8; kd++) {
            unsigned qh[4], ql[4];
            LDM_X4(qh, aQh_b + kd * 32);
            LDM_X4(ql, aQl_b + kd * 32);
#pragma unroll
            for (int ng = 0; ng < 4; ng++) {
                unsigned bh[4], bl[4];
                LDM_X4(bh, kh_b + ng * (16 * AQ_PITCH) + kd * 32);
                LDM_X4(bl, kl_b + ng * (16 * AQ_PITCH) + kd * 32);
                MMA16816(sacc[2 * ng],     qh, bh[0], bh[1]);
                MMA16816(sacc[2 * ng + 1], qh, bh[2], bh[3]);
                MMA16816(sacc[2 * ng],     qh, bl[0], bl[1]);
                MMA16816(sacc[2 * ng + 1], qh, bl[2], bl[3]);
                MMA16816(sacc[2 * ng],     ql, bh[0], bh[1]);
                MMA16816(sacc[2 * ng + 1], ql, bh[2], bh[3]);
            }
        }

        const int c0 = t * 64;
#pragma unroll
        for (int nt = 0; nt < 8; nt++)
#pragma unroll
            for (int j = 0; j < 4; j++) sacc[nt][j] *= scale;

        if (t >= 2 * rb) {   // diagonal tiles: mask col > row
#pragma unroll
            for (int nt = 0; nt < 8; nt++) {
                int col = c0 + nt * 8 + (lane & 3) * 2;
                if (col     > gr1) sacc[nt][0] = -1e30f;
                if (col + 1 > gr1) sacc[nt][1] = -1e30f;
                if (col     > gr2) sacc[nt][2] = -1e30f;
                if (col + 1 > gr2) sacc[nt][3] = -1e30f;
            }
        }

        // online softmax (rows gr1, gr2; stats across lane%4 group)
        float mx1 = -1e30f, mx2 = -1e30f;
#pragma unroll
        for (int nt = 0; nt < 8; nt++) {
            mx1 = fmaxf(mx1, fmaxf(sacc[nt][0], sacc[nt][1]));
            mx2 = fmaxf(mx2, fmaxf(sacc[nt][2], sacc[nt][3]));
        }
        mx1 = fmaxf(mx1, __shfl_xor_sync(0xffffffffu, mx1, 1));
        mx1 = fmaxf(mx1, __shfl_xor_sync(0xffffffffu, mx1, 2));
        mx2 = fmaxf(mx2, __shfl_xor_sync(0xffffffffu, mx2, 1));
        mx2 = fmaxf(mx2, __shfl_xor_sync(0xffffffffu, mx2, 2));
        const float mn1 = fmaxf(m1, mx1), mn2 = fmaxf(m2, mx2);
        const float corr1 = __expf(m1 - mn1), corr2 = __expf(m2 - mn2);
        m1 = mn1; m2 = mn2;
        float rs1 = 0.0f, rs2 = 0.0f;
#pragma unroll
        for (int nt = 0; nt < 8; nt++) {
            sacc[nt][0] = __expf(sacc[nt][0] - m1); rs1 += sacc[nt][0];
            sacc[nt][1] = __expf(sacc[nt][1] - m1); rs1 += sacc[nt][1];
            sacc[nt][2] = __expf(sacc[nt][2] - m2); rs2 += sacc[nt][2];
            sacc[nt][3] = __expf(sacc[nt][3] - m2); rs2 += sacc[nt][3];
        }
        rs1 += __shfl_xor_sync(0xffffffffu, rs1, 1);
        rs1 += __shfl_xor_sync(0xffffffffu, rs1, 2);
        rs2 += __shfl_xor_sync(0xffffffffu, rs2, 1);
        rs2 += __shfl_xor_sync(0xffffffffu, rs2, 2);
        l1 = l1 * corr1 + rs1;
        l2 = l2 * corr2 + rs2;
#pragma unroll
        for (int nt = 0; nt < 16; nt++) {
            Oacc[nt][0] *= corr1; Oacc[nt][1] *= corr1;
            Oacc[nt][2] *= corr2; Oacc[nt][3] *= corr2;
        }

        // O += P V (bf16x3; P fragments built in-register from sacc)
        const unsigned vh_b = sb + 2 * SKH_B + vb_off;
        const unsigned vl_b = sb + 2 * SKH_B + SVH_B + vb_off;
#pragma unroll
        for (int kt = 0; kt < 4; kt++) {
            unsigned ph[4], pl[4];
            ph[0] = pack_bf16(sacc[2 * kt][0], sacc[2 * kt][1]);
            ph[1] = pack_bf16(sacc[2 * kt][2], sacc[2 * kt][3]);
            ph[2] = pack_bf16(sacc[2 * kt + 1][0], sacc[2 * kt + 1][1]);
            ph[3] = pack_bf16(sacc[2 * kt + 1][2], sacc[2 * kt + 1][3]);
            pl[0] = pack_res(sacc[2 * kt][0], sacc[2 * kt][1], ph[0]);
            pl[1] = pack_res(sacc[2 * kt][2], sacc[2 * kt][3], ph[1]);
            pl[2] = pack_res(sacc[2 * kt + 1][0], sacc[2 * kt + 1][1], ph[2]);
            pl[3] = pack_res(sacc[2 * kt + 1][2], sacc[2 * kt + 1][3], ph[3]);
#pragma unroll
            for (int ng = 0; ng < 8; ng++) {
                unsigned vh[4], vl[4];
                LDM_X4(vh, vh_b + ng * (16 * AV_PITCH) + kt * 32);
                LDM_X4(vl, vl_b + ng * (16 * AV_PITCH) + kt * 32);
                MMA16816(Oacc[2 * ng],     ph, vh[0], vh[1]);
                MMA16816(Oacc[2 * ng + 1], ph, vh[2], vh[3]);
                MMA16816(Oacc[2 * ng],     ph, vl[0], vl[1]);
                MMA16816(Oacc[2 * ng + 1], ph, vl[2], vl[3]);
                MMA16816(Oacc[2 * ng],     pl, vh[0], vh[1]);
                MMA16816(Oacc[2 * ng + 1], pl, vh[2], vh[3]);
            }
        }
        __syncthreads();
    }

    // epilogue: normalize and store ctx as hi/lo bf16
    const float inv1 = 1.0f / l1, inv2 = 1.0f / l2;
#pragma unroll
    for (int nt = 0; nt < 16; nt++) {
        const int colb = h * 128 + nt * 8 + (lane & 3) * 2;
        float o0 = Oacc[nt][0] * inv1, o1 = Oacc[nt][1] * inv1;
        unsigned hp = pack_bf16(o0, o1);
        *(unsigned*)(Ch_ + (size_t)gr1 * 2048 + colb) = hp;
        *(unsigned*)(Cl_ + (size_t)gr1 * 2048 + colb) = pack_res(o0, o1, hp);
        o0 = Oacc[nt][2] * inv2; o1 = Oacc[nt][3] * inv2;
        hp = pack_bf16(o0, o1);
        *(unsigned*)(Ch_ + (size_t)gr2 * 2048 + colb) = hp;
        *(unsigned*)(Cl_ + (size_t)gr2 * 2048 + colb) = pack_res(o0, o1, hp);
    }
}

// ---------------------------------------------------------------------------
extern "C" void kernel_launch(void* const* d_in, const int* in_sizes, int n_in,
                              void* d_out, int out_size)
{
    (void)in_sizes; (void)n_in; (void)out_size;
    const float* hidden  = (const float*)d_in[0];
    const float* qkv_w   = (const float*)d_in[2];
    const float* qkv_b   = (const float*)d_in[3];
    const float* svd_tok = (const float*)d_in[4];
    const float* svd_qk  = (const float*)d_in[5];
    const float* svd_vl  = (const float*)d_in[6];
    const float* dense_w = (const float*)d_in[7];
    const float* dense_b = (const float*)d_in[8];
    float* out = (float*)d_out;

    float *pM, *pX2, *pmx, *pqp, *pS, *pP, *pW2;
    cudaGetSymbolAddress((void**)&pM, g_M);
    cudaGetSymbolAddress((void**)&pX2, g_X2);
    cudaGetSymbolAddress((void**)&pmx, g_mixed);
    cudaGetSymbolAddress((void**)&pqp, g_qp);
    cudaGetSymbolAddress((void**)&pS, g_S);
    cudaGetSymbolAddress((void**)&pP, g_P);
    cudaGetSymbolAddress((void**)&pW2, g_W2);

    __nv_bfloat16 *pHh, *pHl, *pRh, *pRl, *pMh, *pMl, *pX2h, *pX2l;
    __nv_bfloat16 *pWqh, *pWql, *pCh, *pCl, *pW2Th, *pW2Tl;
    __nv_bfloat16 *pqph, *pqpl, *pKh, *pKl, *pVth, *pVtl;
    cudaGetSymbolAddress((void**)&pHh, g_Hh);   cudaGetSymbolAddress((void**)&pHl, g_Hl);
    cudaGetSymbolAddress((void**)&pRh, g_Rh);   cudaGetSymbolAddress((void**)&pRl, g_Rl);
    cudaGetSymbolAddress((void**)&pMh, g_Mh);   cudaGetSymbolAddress((void**)&pMl, g_Ml);
    cudaGetSymbolAddress((void**)&pX2h, g_X2h); cudaGetSymbolAddress((void**)&pX2l, g_X2l);
    cudaGetSymbolAddress((void**)&pWqh, g_Wqh); cudaGetSymbolAddress((void**)&pWql, g_Wql);
    cudaGetSymbolAddress((void**)&pCh, g_Ch);   cudaGetSymbolAddress((void**)&pCl, g_Cl);
    cudaGetSymbolAddress((void**)&pW2Th, g_W2Th); cudaGetSymbolAddress((void**)&pW2Tl, g_W2Tl);
    cudaGetSymbolAddress((void**)&pqph, g_qph); cudaGetSymbolAddress((void**)&pqpl, g_qpl);
    cudaGetSymbolAddress((void**)&pKh, g_Kh);   cudaGetSymbolAddress((void**)&pKl, g_Kl);
    cudaGetSymbolAddress((void**)&pVth, g_Vth); cudaGetSymbolAddress((void**)&pVtl, g_Vtl);

    cudaFuncSetAttribute(mma_gemm, cudaFuncAttributeMaxDynamicSharedMemorySize, GEMM_SMEM);
    cudaFuncSetAttribute(attn_mma, cudaFuncAttributeMaxDynamicSharedMemorySize, ATTN2_SMEM);

    const dim3 blk(256);
    const int N4_2048 = (2048 * 2048) / 4;
    const int N4_W = (6144 * 2048) / 4;

    // input conversions
    cvt_split<<<N4_2048 / 256, 256>>>((const float4*)hidden, (__nv_bfloat162*)pHh, (__nv_bfloat162*)pHl, N4_2048);
    cvt_split<<<N4_2048 / 256, 256>>>((const float4*)svd_tok, (__nv_bfloat162*)pRh, (__nv_bfloat162*)pRl, N4_2048);
    cvt_split<<<N4_W / 256, 256>>>((const float4*)qkv_w, (__nv_bfloat162*)pWqh, (__nv_bfloat162*)pWql, N4_W);

    // 1) M = R @ R^T
    mma_gemm<<<dim3(16, 16), blk, GEMM_SMEM>>>(pRh, pRl, pRh, pRl, pM, 2048, nullptr, 2048, 2048, 2048);
    cvt_split<<<N4_2048 / 256, 256>>>((const float4*)pM, (__nv_bfloat162*)pMh, (__nv_bfloat162*)pMl, N4_2048);
    // 2) X2 = hidden @ M  (M symmetric)
    mma_gemm<<<dim3(16, 16), blk, GEMM_SMEM>>>(pHh, pHl, pMh, pMl, pX2, 2048, nullptr, 2048, 2048, 2048);
    cvt_split<<<N4_2048 / 256, 256>>>((const float4*)pX2, (__nv_bfloat162*)pX2h, (__nv_bfloat162*)pX2l, N4_2048);
    // 3) mixed = X2 @ qkv_w^T + qkv_b
    mma_gemm<<<dim3(48, 16), blk, GEMM_SMEM>>>(pX2h, pX2l, pWqh, pWql, pmx, 6144, qkv_b, 2048, 2048, 2048);

    // K/V prep for attention
    split_k<<<4096, 256>>>(pmx, pKh, pKl);
    vtrans_split<<<dim3(64, 4, 16), dim3(32, 8)>>>(pmx, pVth, pVtl);

    // 4) S_h = svd_qk[h] @ svd_qk[h]^T ; P_h = svd_vlin[h] @ svd_vlin[h]^T
    sgemm_kernel<true, false><<<dim3(1, 1, 16), blk>>>(
        svd_qk, 128, 16384, svd_qk, 128, 16384, pS, 128, 16384, nullptr, 128);
    sgemm_kernel<true, false><<<dim3(1, 1, 16), blk>>>(
        svd_vl, 128, 16384, svd_vl, 128, 16384, pP, 128, 16384, nullptr, 128);
    // 5) W2_h = P_h @ dense_w[h]; transpose+split
    sgemm_kernel<false, false><<<dim3(16, 1, 16), blk>>>(
        pP, 128, 16384, dense_w, 2048, 262144, pW2, 2048, 262144, nullptr, 128);
    trans_cvt<<<dim3(64, 64), dim3(32, 8)>>>(pW2, pW2Th, pW2Tl);
    // 6) q'_h = q_h @ S_h ; split
    sgemm_kernel<false, false><<<dim3(1, 16, 16), blk>>>(
        pmx, 6144, 384, pS, 128, 16384, pqp, 2048, 128, nullptr, 128);
    cvt_split<<<N4_2048 / 256, 256>>>((const float4*)pqp, (__nv_bfloat162*)pqph, (__nv_bfloat162*)pqpl, N4_2048);

    // 7) ctx = causal flash attention (tensor cores), writes Ch/Cl
    attn_mma<<<dim3(16, 16), blk, ATTN2_SMEM>>>(pqph, pqpl, pKh, pKl, pVth, pVtl, pCh, pCl);

    // 8) out = ctx @ W2 + dense_b
    mma_gemm<<<dim3(16, 16), blk, GEMM_SMEM>>>(pCh, pCl, pW2Th, pW2Tl, out, 2048, dense_b, 2048, 2048, 2048);
}

// round 8
// speedup vs baseline: 2.7060x; 1.1233x over previous
#include <cuda_runtime.h>
#include <cuda_bf16.h>

#define SQN 2048
#define HIDN 2048
#define NHD 16
#define HDIM 128
#define H3 6144

// ---------------- fp32 scratch ----------------
__device__ float g_mixed[SQN * H3];
__device__ float g_S[NHD * HDIM * HDIM];
__device__ float g_P[NHD * HDIM * HDIM];
__device__ float g_W2[HIDN * HIDN];

// ---------------- bf16 hi/lo scratch ----------------
__device__ __nv_bfloat16 g_Hh[SQN * HIDN],  g_Hl[SQN * HIDN];
__device__ __nv_bfloat16 g_Rh[HIDN * HIDN], g_Rl[HIDN * HIDN];
__device__ __nv_bfloat16 g_Mh[HIDN * HIDN], g_Ml[HIDN * HIDN];
__device__ __nv_bfloat16 g_X2h[SQN * HIDN], g_X2l[SQN * HIDN];
__device__ __nv_bfloat16 g_Wqh[H3 * HIDN],  g_Wql[H3 * HIDN];
__device__ __nv_bfloat16 g_Ch[SQN * HIDN],  g_Cl[SQN * HIDN];
__device__ __nv_bfloat16 g_W2Th[HIDN * HIDN], g_W2Tl[HIDN * HIDN];
__device__ __nv_bfloat16 g_qph[SQN * HIDN], g_qpl[SQN * HIDN];
__device__ __nv_bfloat16 g_Kh[NHD * SQN * HDIM], g_Kl[NHD * SQN * HDIM];
__device__ __nv_bfloat16 g_Vth[NHD * HDIM * SQN], g_Vtl[NHD * HDIM * SQN];

__device__ __forceinline__ unsigned smem_u32(const void* p) {
    unsigned a;
    asm("{ .reg .u64 t; cvta.to.shared.u64 t, %1; cvt.u32.u64 %0, t; }"
        : "=r"(a) : "l"(p));
    return a;
}

#define LDM_X4(r, a)                                                          \
    asm volatile("ldmatrix.sync.aligned.m8n8.x4.shared.b16 {%0,%1,%2,%3}, [%4];" \
                 : "=r"((r)[0]), "=r"((r)[1]), "=r"((r)[2]), "=r"((r)[3])     \
                 : "r"(a))

#define MMA16816(d, a, b0, b1)                                                \
    asm volatile("mma.sync.aligned.m16n8k16.row.col.f32.bf16.bf16.f32 "       \
                 "{%0,%1,%2,%3}, {%4,%5,%6,%7}, {%8,%9}, {%0,%1,%2,%3};"      \
                 : "+f"((d)[0]), "+f"((d)[1]), "+f"((d)[2]), "+f"((d)[3])     \
                 : "r"((a)[0]), "r"((a)[1]), "r"((a)[2]), "r"((a)[3]),        \
                   "r"(b0), "r"(b1))

#define CP_ASYNC16(s, g) \
    asm volatile("cp.async.cg.shared.global [%0], [%1], 16;" :: "r"(s), "l"(g))
#define CP_COMMIT() asm volatile("cp.async.commit_group;" ::: "memory")
#define CP_WAIT1()  asm volatile("cp.async.wait_group 1;" ::: "memory")
#define CP_WAIT0()  asm volatile("cp.async.wait_group 0;" ::: "memory")

__device__ __forceinline__ unsigned pack_bf16(float lo, float hi) {
    unsigned r;
    asm("cvt.rn.bf16x2.f32 %0, %1, %2;" : "=r"(r) : "f"(hi), "f"(lo));
    return r;
}
__device__ __forceinline__ unsigned pack_res(float lo, float hi, unsigned hp) {
    __nv_bfloat162 h = *reinterpret_cast<__nv_bfloat162*>(&hp);
    return pack_bf16(lo - __bfloat162float(h.x), hi - __bfloat162float(h.y));
}

// ---------------------------------------------------------------------------
// bf16x3 split conversion: x -> (hi, lo)
// ---------------------------------------------------------------------------
__global__ void cvt_split(const float4* __restrict__ in,
                          __nv_bfloat162* __restrict__ hi,
                          __nv_bfloat162* __restrict__ lo, int n4)
{
    int i = blockIdx.x * blockDim.x + threadIdx.x;
    if (i >= n4) return;
    float4 v = in[i];
    __nv_bfloat16 h0 = __float2bfloat16(v.x), h1 = __float2bfloat16(v.y);
    __nv_bfloat16 h2 = __float2bfloat16(v.z), h3 = __float2bfloat16(v.w);
    __nv_bfloat162 a, b;
    a.x = h0; a.y = h1; b.x = h2; b.y = h3;
    hi[i * 2] = a; hi[i * 2 + 1] = b;
    a.x = __float2bfloat16(v.x - __bfloat162float(h0));
    a.y = __float2bfloat16(v.y - __bfloat162float(h1));
    b.x = __float2bfloat16(v.z - __bfloat162float(h2));
    b.y = __float2bfloat16(v.w - __bfloat162float(h3));
    lo[i * 2] = a; lo[i * 2 + 1] = b;
}

// Transpose [2048,2048] fp32 -> hi/lo bf16 of the transpose
__global__ void trans_cvt(const float* __restrict__ in,
                          __nv_bfloat16* __restrict__ hi,
                          __nv_bfloat16* __restrict__ lo)
{
    __shared__ float t[32][33];
    int xi = blockIdx.x * 32 + threadIdx.x;
    int yi = blockIdx.y * 32 + threadIdx.y;
#pragma unroll
    for (int j = 0; j < 32; j += 8)
        t[threadIdx.y + j][threadIdx.x] = in[(size_t)(yi + j) * 2048 + xi];
    __syncthreads();
    int xo = blockIdx.y * 32 + threadIdx.x;
    int yo = blockIdx.x * 32 + threadIdx.y;
#pragma unroll
    for (int j = 0; j < 32; j += 8) {
        float v = t[threadIdx.x][threadIdx.y + j];
        __nv_bfloat16 h = __float2bfloat16(v);
        hi[(size_t)(yo + j) * 2048 + xo] = h;
        lo[(size_t)(yo + j) * 2048 + xo] = __float2bfloat16(v - __bfloat162float(h));
    }
}

// K stripe split: mixed[t, h*384+128+d] -> Kh/Kl [h][t][d]
__global__ void split_k(const float* __restrict__ mixed,
                        __nv_bfloat16* __restrict__ Kh_,
                        __nv_bfloat16* __restrict__ Kl_)
{
    int i = blockIdx.x * 256 + threadIdx.x;
    int d4 = i & 31;
    int tt = (i >> 5) & 2047;
    int hh = i >> 16;
    float4 v = *(const float4*)(mixed + (size_t)tt * 6144 + hh * 384 + 128 + d4 * 4);
    size_t o = ((size_t)hh * 2048 + tt) * 128 + d4 * 4;
    unsigned p0 = pack_bf16(v.x, v.y), p1 = pack_bf16(v.z, v.w);
    *(unsigned*)(Kh_ + o) = p0;
    *(unsigned*)(Kh_ + o + 2) = p1;
    *(unsigned*)(Kl_ + o) = pack_res(v.x, v.y, p0);
    *(unsigned*)(Kl_ + o + 2) = pack_res(v.z, v.w, p1);
}

// V stripe transpose+split: mixed[t, h*384+256+e] -> Vth/Vtl [h][e][t]
__global__ void vtrans_split(const float* __restrict__ mixed,
                             __nv_bfloat16* __restrict__ Vth_,
                             __nv_bfloat16* __restrict__ Vtl_)
{
    __shared__ float tl[32][33];
    int hh = blockIdx.z;
    int e0 = blockIdx.y * 32, t0 = blockIdx.x * 32;
    int tx = threadIdx.x, ty = threadIdx.y;
#pragma unroll
    for (int j = 0; j < 32; j += 8)
        tl[ty + j][tx] = mixed[(size_t)(t0 + ty + j) * 6144 + hh * 384 + 256 + e0 + tx];
    __syncthreads();
#pragma unroll
    for (int j = 0; j < 32; j += 8) {
        float v = tl[tx][ty + j];
        size_t o = ((size_t)hh * 128 + e0 + ty + j) * 2048 + t0 + tx;
        __nv_bfloat16 hb = __float2bfloat16(v);
        Vth_[o] = hb;
        Vtl_[o] = __float2bfloat16(v - __bfloat162float(hb));
    }
}

// ---------------------------------------------------------------------------
// bf16x3 GEMM via mma.sync. 2-stage cp.async, 2 CTAs/SM.
// C[M,N] = Ahl[M,K] @ Bhl[N,K]^T (+bias). BM=BN=128, BK=32, 8 warps (32x64).
// Output: fp32 C, or hi/lo bf16 (Coh/Col) if Coh != null.
// ---------------------------------------------------------------------------
#define TILE_B 10240
#define STAGE_B (4 * TILE_B)
#define GEMM_SMEM (2 * STAGE_B)   // 81920

__global__ __launch_bounds__(256, 2)
void mma_gemm(const __nv_bfloat16* __restrict__ Ah, const __nv_bfloat16* __restrict__ Al,
              const __nv_bfloat16* __restrict__ Bh, const __nv_bfloat16* __restrict__ Bl,
              float* __restrict__ C, __nv_bfloat16* __restrict__ Coh,
              __nv_bfloat16* __restrict__ Col, int ldc,
              const float* __restrict__ bias, int K, int lda, int ldb)
{
    extern __shared__ __align__(16) char smem[];

    const int tid = threadIdx.x;
    const int wid = tid >> 5;
    const int lane = tid & 31;
    const int m0 = blockIdx.y * 128;
    const int n0 = blockIdx.x * 128;
    const int wm = (wid & 3) * 32;
    const int wn = (wid >> 2) * 64;

    float acc[2][8][4];
#pragma unroll
    for (int i = 0; i < 2; i++)
#pragma unroll
        for (int j = 0; j < 8; j++)
#pragma unroll
            for (int k = 0; k < 4; k++) acc[i][j][k] = 0.0f;

    const __nv_bfloat16* srcs[4] = {Ah, Al, Bh, Bl};
    const int lds[4] = {lda, lda, ldb, ldb};
    const int r0s[4] = {m0, m0, n0, n0};

    const unsigned smb = smem_u32(smem);

    auto issue_stage = [&](int t, int buf) {
        const int k0 = t * 32;
        const unsigned sb = smb + buf * STAGE_B;
#pragma unroll
        for (int i = 0; i < 8; i++) {
            const int id = i * 256 + tid;
            const int tile = id >> 9;
            const int cid = id & 511;
            const int row = cid >> 2;
            const int c = cid & 3;
            const __nv_bfloat16* g =
                srcs[tile] + (size_t)(r0s[tile] + row) * lds[tile] + k0 + c * 8;
            CP_ASYNC16(sb + tile * TILE_B + row * 80 + c * 16, g);
        }
        CP_COMMIT();
    };

    const int T = K >> 5;
    issue_stage(0, 0);

    const unsigned a_lrow = (lane & 15) * 80 + (lane >> 4) * 16;
    const unsigned b_lrow = ((lane & 7) + ((lane >> 4) << 3)) * 80 + ((lane >> 3) & 1) * 16;

    for (int t = 0; t < T; t++) {
        if (t + 1 < T) { issue_stage(t + 1, (t + 1) & 1); CP_WAIT1(); }
        else { CP_WAIT0(); }
        __syncthreads();

        const unsigned st = smb + (t & 1) * STAGE_B;
        const unsigned aHb = st + wm * 80 + a_lrow;
        const unsigned aLb = st + TILE_B + wm * 80 + a_lrow;
        const unsigned bHb = st + 2 * TILE_B + wn * 80 + b_lrow;
        const unsigned bLb = st + 3 * TILE_B + wn * 80 + b_lrow;

#pragma unroll
        for (int ks = 0; ks < 2; ks++) {
            unsigned aH[2][4], aL[2][4];
#pragma unroll
            for (int mt = 0; mt < 2; mt++) {
                LDM_X4(aH[mt], aHb + mt * (16 * 80) + ks * 32);
                LDM_X4(aL[mt], aLb + mt * (16 * 80) + ks * 32);
            }
#pragma unroll
            for (int ng = 0; ng < 4; ng++) {
                unsigned bH[4], bL[4];
                LDM_X4(bH, bHb + ng * (16 * 80) + ks * 32);
                LDM_X4(bL, bLb + ng * (16 * 80) + ks * 32);
#pragma unroll
                for (int mt = 0; mt < 2; mt++) {
                    MMA16816(acc[mt][2 * ng],     aH[mt], bH[0], bH[1]);
                    MMA16816(acc[mt][2 * ng + 1], aH[mt], bH[2], bH[3]);
                    MMA16816(acc[mt][2 * ng],     aH[mt], bL[0], bL[1]);
                    MMA16816(acc[mt][2 * ng + 1], aH[mt], bL[2], bL[3]);
                    MMA16816(acc[mt][2 * ng],     aL[mt], bH[0], bH[1]);
                    MMA16816(acc[mt][2 * ng + 1], aL[mt], bH[2], bH[3]);
                }
            }
        }
        __syncthreads();
    }

#pragma unroll
    for (int mt = 0; mt < 2; mt++) {
        const int m = m0 + wm + mt * 16 + (lane >> 2);
#pragma unroll
        for (int nt = 0; nt < 8; nt++) {
            const int n = n0 + wn + nt * 8 + (lane & 3) * 2;
            float bx = 0.0f, by = 0.0f;
            if (bias) { bx = bias[n]; by = bias[n + 1]; }
            float v00 = acc[mt][nt][0] + bx, v01 = acc[mt][nt][1] + by;
            float v10 = acc[mt][nt][2] + bx, v11 = acc[mt][nt][3] + by;
            if (Coh) {
                unsigned hp = pack_bf16(v00, v01);
                *(unsigned*)(Coh + (size_t)m * ldc + n) = hp;
                *(unsigned*)(Col + (size_t)m * ldc + n) = pack_res(v00, v01, hp);
                hp = pack_bf16(v10, v11);
                *(unsigned*)(Coh + (size_t)(m + 8) * ldc + n) = hp;
                *(unsigned*)(Col + (size_t)(m + 8) * ldc + n) = pack_res(v10, v11, hp);
            } else {
                *(float2*)(C + (size_t)m * ldc + n) = make_float2(v00, v01);
                *(float2*)(C + (size_t)(m + 8) * ldc + n) = make_float2(v10, v11);
            }
        }
    }
}

// ---------------------------------------------------------------------------
// fp32 SGEMM (small GEMMs). Optional bf16 hi/lo output.
// Batch offset is applied as an ELEMENT offset (zoff), rows stay local.
// ---------------------------------------------------------------------------
template <bool TB, bool OUTBF>
__global__ __launch_bounds__(256) void sgemm_kernel(
    const float* __restrict__ A, int lda, long long sA,
    const float* __restrict__ B, int ldb, long long sB,
    float* __restrict__ C, __nv_bfloat16* __restrict__ Coh,
    __nv_bfloat16* __restrict__ Col, int ldc, long long sC, int K)
{
    __shared__ float As[8][128];
    __shared__ float Bs[8][128];

    const float* Ab = A + (long long)blockIdx.z * sA;
    const float* Bb = B + (long long)blockIdx.z * sB;
    const long long zoff = (long long)blockIdx.z * sC;

    const int m0 = blockIdx.y * 128;
    const int n0 = blockIdx.x * 128;
    const int tid = threadIdx.x;
    const int tx = tid & 15;
    const int ty = tid >> 4;

    float acc[8][8];
#pragma unroll
    for (int i = 0; i < 8; i++)
#pragma unroll
        for (int j = 0; j < 8; j++) acc[i][j] = 0.0f;

    const int arow = tid >> 1;
    const int ak = (tid & 1) * 4;

    for (int k0 = 0; k0 < K; k0 += 8) {
        float4 av = *(const float4*)(Ab + (long long)(m0 + arow) * lda + k0 + ak);
        As[ak + 0][arow] = av.x;
        As[ak + 1][arow] = av.y;
        As[ak + 2][arow] = av.z;
        As[ak + 3][arow] = av.w;
        if (!TB) {
            const int bk = tid >> 5;
            const int bn = (tid & 31) * 4;
            *(float4*)&Bs[bk][bn] =
                *(const float4*)(Bb + (long long)(k0 + bk) * ldb + n0 + bn);
        } else {
            const int bn = tid >> 1;
            const int bk = (tid & 1) * 4;
            float4 bv = *(const float4*)(Bb + (long long)(n0 + bn) * ldb + k0 + bk);
            Bs[bk + 0][bn] = bv.x;
            Bs[bk + 1][bn] = bv.y;
            Bs[bk + 2][bn] = bv.z;
            Bs[bk + 3][bn] = bv.w;
        }
        __syncthreads();
#pragma unroll
        for (int k = 0; k < 8; k++) {
            float a[8], b[8];
            *(float4*)&a[0] = *(const float4*)&As[k][ty * 8];
            *(float4*)&a[4] = *(const float4*)&As[k][ty * 8 + 4];
            *(float4*)&b[0] = *(const float4*)&Bs[k][tx * 8];
            *(float4*)&b[4] = *(const float4*)&Bs[k][tx * 8 + 4];
#pragma unroll
            for (int i = 0; i < 8; i++)
#pragma unroll
                for (int j = 0; j < 8; j++) acc[i][j] += a[i] * b[j];
        }
        __syncthreads();
    }

#pragma unroll
    for (int i = 0; i < 8; i++) {
        const int row = m0 + ty * 8 + i;
        const long long base = zoff + (long long)row * ldc;
#pragma unroll
        for (int j = 0; j < 8; j += 2) {
            const int col = n0 + tx * 8 + j;
            if (OUTBF) {
                unsigned hp = pack_bf16(acc[i][j], acc[i][j + 1]);
                *(unsigned*)(Coh + base + col) = hp;
                *(unsigned*)(Col + base + col) = pack_res(acc[i][j], acc[i][j + 1], hp);
            } else {
                *(float2*)(C + base + col) = make_float2(acc[i][j], acc[i][j + 1]);
            }
        }
    }
}

// ---------------------------------------------------------------------------
// Tensor-core causal flash attention (bf16x3). 128 Q rows x head per block.
// ---------------------------------------------------------------------------
#define AQ_PITCH 272
#define AV_PITCH 144
#define SQH_B (128 * AQ_PITCH)
#define SKH_B (64 * AQ_PITCH)
#define SVH_B (128 * AV_PITCH)
#define KV_STAGE (2 * SKH_B + 2 * SVH_B)
#define ATTN2_SMEM (2 * SQH_B + 2 * KV_STAGE)

__global__ __launch_bounds__(256, 1) void attn_mma(
    const __nv_bfloat16* __restrict__ qph, const __nv_bfloat16* __restrict__ qpl,
    const __nv_bfloat16* __restrict__ Kh_, const __nv_bfloat16* __restrict__ Kl_,
    const __nv_bfloat16* __restrict__ Vth_, const __nv_bfloat16* __restrict__ Vtl_,
    __nv_bfloat16* __restrict__ Ch_, __nv_bfloat16* __restrict__ Cl_)
{
    extern __shared__ __align__(16) char sm[];
    const int h = blockIdx.y;
    const int rb = (int)gridDim.x - 1 - (int)blockIdx.x;
    const int r0 = rb * 128;
    const int tid = threadIdx.x;
    const int wid = tid >> 5;
    const int lane = tid & 31;

    const unsigned sQh = smem_u32(sm);
    const unsigned sQl = sQh + SQH_B;
    const unsigned sKV0 = sQl + SQH_B;

    {
        const __nv_bfloat16* gq = qph + (size_t)r0 * 2048 + h * 128;
        const __nv_bfloat16* gql = qpl + (size_t)r0 * 2048 + h * 128;
#pragma unroll
        for (int it = 0; it < 8; it++) {
            int id = it * 256 + tid;
            int row = id >> 4, c = id & 15;
            CP_ASYNC16(sQh + row * AQ_PITCH + c * 16, gq + (size_t)row * 2048 + c * 8);
            CP_ASYNC16(sQl + row * AQ_PITCH + c * 16, gql + (size_t)row * 2048 + c * 8);
        }
    }
    const __nv_bfloat16* gK = Kh_ + (size_t)h * 2048 * 128;
    const __nv_bfloat16* gKl = Kl_ + (size_t)h * 2048 * 128;
    const __nv_bfloat16* gV = Vth_ + (size_t)h * 128 * 2048;
    const __nv_bfloat16* gVl = Vtl_ + (size_t)h * 128 * 2048;

    auto issue_kv = [&](int t, int buf) {
        const int t0 = t * 64;
        const unsigned sb = sKV0 + buf * KV_STAGE;
#pragma unroll
        for (int it = 0; it < 4; it++) {
            int id = it * 256 + tid;
            int row = id >> 4, c = id & 15;
            CP_ASYNC16(sb + row * AQ_PITCH + c * 16, gK + (size_t)(t0 + row) * 128 + c * 8);
            CP_ASYNC16(sb + SKH_B + row * AQ_PITCH + c * 16, gKl + (size_t)(t0 + row) * 128 + c * 8);
        }
#pragma unroll
        for (int it = 0; it < 4; it++) {
            int id = it * 256 + tid;
            int row = id >> 3, c = id & 7;
            CP_ASYNC16(sb + 2 * SKH_B + row * AV_PITCH + c * 16, gV + (size_t)row * 2048 + t0 + c * 8);
            CP_ASYNC16(sb + 2 * SKH_B + SVH_B + row * AV_PITCH + c * 16, gVl + (size_t)row * 2048 + t0 + c * 8);
        }
    };

    issue_kv(0, 0);
    CP_COMMIT();

    float sacc[8][4];
    float Oacc[16][4];
#pragma unroll
    for (int i = 0; i < 16; i++)
#pragma unroll
        for (int j = 0; j < 4; j++) Oacc[i][j] = 0.0f;
    float m1 = -1e30f, m2 = -1e30f, l1 = 0.0f, l2 = 0.0f;

    const int gr1 = r0 + wid * 16 + (lane >> 2);
    const int gr2 = gr1 + 8;
    const float scale = 0.08838834764831845f;

    const unsigned a_off = (lane & 15) * AQ_PITCH + (lane >> 4) * 16;
    const unsigned kb_off = ((lane & 7) + ((lane >> 4) << 3)) * AQ_PITCH + ((lane >> 3) & 1) * 16;
    const unsigned vb_off = ((lane & 7) + ((lane >> 4) << 3)) * AV_PITCH + ((lane >> 3) & 1) * 16;
    const unsigned aQh_b = sQh + wid * 16 * AQ_PITCH + a_off;
    const unsigned aQl_b = sQl + wid * 16 * AQ_PITCH + a_off;

    const int T = 2 * rb + 2;
    for (int t = 0; t < T; t++) {
        if (t + 1 < T) { issue_kv(t + 1, (t + 1) & 1); CP_COMMIT(); CP_WAIT1(); }
        else { CP_WAIT0(); }
        __syncthreads();

        const unsigned sb = sKV0 + (t & 1) * KV_STAGE;
        const unsigned kh_b = sb + kb_off;
        const unsigned kl_b = sb + SKH_B + kb_off;

#pragma unroll
        for (int i = 0; i < 8; i++)
#pragma unroll
            for (int j = 0; j < 4; j++) sacc[i][j] = 0.0f;

#pragma unroll
        for (int kd = 0; kd < 8; kd++) {
            unsigned qh[4], ql[4];
            LDM_X4(qh, aQh_b + kd * 32);
            LDM_X4(ql, aQl_b + kd * 32);
#pragma unroll
            for (int ng = 0; ng < 4; ng++) {
                unsigned bh[4], bl[4];
                LDM_X4(bh, kh_b + ng * (16 * AQ_PITCH) + kd * 32);
                LDM_X4(bl, kl_b + ng * (16 * AQ_PITCH) + kd * 32);
                MMA16816(sacc[2 * ng],     qh, bh[0], bh[1]);
                MMA16816(sacc[2 * ng + 1], qh, bh[2], bh[3]);
                MMA16816(sacc[2 * ng],     qh, bl[0], bl[1]);
                MMA16816(sacc[2 * ng + 1], qh, bl[2], bl[3]);
                MMA16816(sacc[2 * ng],     ql, bh[0], bh[1]);
                MMA16816(sacc[2 * ng + 1], ql, bh[2], bh[3]);
            }
        }

        const int c0 = t * 64;
#pragma unroll
        for (int nt = 0; nt < 8; nt++)
#pragma unroll
            for (int j = 0; j < 4; j++) sacc[nt][j] *= scale;

        if (t >= 2 * rb) {
#pragma unroll
            for (int nt = 0; nt < 8; nt++) {
                int col = c0 + nt * 8 + (lane & 3) * 2;
                if (col     > gr1) sacc[nt][0] = -1e30f;
                if (col + 1 > gr1) sacc[nt][1] = -1e30f;
                if (col     > gr2) sacc[nt][2] = -1e30f;
                if (col + 1 > gr2) sacc[nt][3] = -1e30f;
            }
        }

        float mx1 = -1e30f, mx2 = -1e30f;
#pragma unroll
        for (int nt = 0; nt < 8; nt++) {
            mx1 = fmaxf(mx1, fmaxf(sacc[nt][0], sacc[nt][1]));
            mx2 = fmaxf(mx2, fmaxf(sacc[nt][2], sacc[nt][3]));
        }
        mx1 = fmaxf(mx1, __shfl_xor_sync(0xffffffffu, mx1, 1));
        mx1 = fmaxf(mx1, __shfl_xor_sync(0xffffffffu, mx1, 2));
        mx2 = fmaxf(mx2, __shfl_xor_sync(0xffffffffu, mx2, 1));
        mx2 = fmaxf(mx2, __shfl_xor_sync(0xffffffffu, mx2, 2));
        const float mn1 = fmaxf(m1, mx1), mn2 = fmaxf(m2, mx2);
        const float corr1 = __expf(m1 - mn1), corr2 = __expf(m2 - mn2);
        m1 = mn1; m2 = mn2;
        float rs1 = 0.0f, rs2 = 0.0f;
#pragma unroll
        for (int nt = 0; nt < 8; nt++) {
            sacc[nt][0] = __expf(sacc[nt][0] - m1); rs1 += sacc[nt][0];
            sacc[nt][1] = __expf(sacc[nt][1] - m1); rs1 += sacc[nt][1];
            sacc[nt][2] = __expf(sacc[nt][2] - m2); rs2 += sacc[nt][2];
            sacc[nt][3] = __expf(sacc[nt][3] - m2); rs2 += sacc[nt][3];
        }
        rs1 += __shfl_xor_sync(0xffffffffu, rs1, 1);
        rs1 += __shfl_xor_sync(0xffffffffu, rs1, 2);
        rs2 += __shfl_xor_sync(0xffffffffu, rs2, 1);
        rs2 += __shfl_xor_sync(0xffffffffu, rs2, 2);
        l1 = l1 * corr1 + rs1;
        l2 = l2 * corr2 + rs2;
#pragma unroll
        for (int nt = 0; nt < 16; nt++) {
            Oacc[nt][0] *= corr1; Oacc[nt][1] *= corr1;
            Oacc[nt][2] *= corr2; Oacc[nt][3] *= corr2;
        }

        const unsigned vh_b = sb + 2 * SKH_B + vb_off;
        const unsigned vl_b = sb + 2 * SKH_B + SVH_B + vb_off;
#pragma unroll
        for (int kt = 0; kt < 4; kt++) {
            unsigned ph[4], pl[4];
            ph[0] = pack_bf16(sacc[2 * kt][0], sacc[2 * kt][1]);
            ph[1] = pack_bf16(sacc[2 * kt][2], sacc[2 * kt][3]);
            ph[2] = pack_bf16(sacc[2 * kt + 1][0], sacc[2 * kt + 1][1]);
            ph[3] = pack_bf16(sacc[2 * kt + 1][2], sacc[2 * kt + 1][3]);
            pl[0] = pack_res(sacc[2 * kt][0], sacc[2 * kt][1], ph[0]);
            pl[1] = pack_res(sacc[2 * kt][2], sacc[2 * kt][3], ph[1]);
            pl[2] = pack_res(sacc[2 * kt + 1][0], sacc[2 * kt + 1][1], ph[2]);
            pl[3] = pack_res(sacc[2 * kt + 1][2], sacc[2 * kt + 1][3], ph[3]);
#pragma unroll
            for (int ng = 0; ng < 8; ng++) {
                unsigned vh[4], vl[4];
                LDM_X4(vh, vh_b + ng * (16 * AV_PITCH) + kt * 32);
                LDM_X4(vl, vl_b + ng * (16 * AV_PITCH) + kt * 32);
                MMA16816(Oacc[2 * ng],     ph, vh[0], vh[1]);
                MMA16816(Oacc[2 * ng + 1], ph, vh[2], vh[3]);
                MMA16816(Oacc[2 * ng],     ph, vl[0], vl[1]);
                MMA16816(Oacc[2 * ng + 1], ph, vl[2], vl[3]);
                MMA16816(Oacc[2 * ng],     pl, vh[0], vh[1]);
                MMA16816(Oacc[2 * ng + 1], pl, vh[2], vh[3]);
            }
        }
        __syncthreads();
    }

    const float inv1 = 1.0f / l1, inv2 = 1.0f / l2;
#pragma unroll
    for (int nt = 0; nt < 16; nt++) {
        const int colb = h * 128 + nt * 8 + (lane & 3) * 2;
        float o0 = Oacc[nt][0] * inv1, o1 = Oacc[nt][1] * inv1;
        unsigned hp = pack_bf16(o0, o1);
        *(unsigned*)(Ch_ + (size_t)gr1 * 2048 + colb) = hp;
        *(unsigned*)(Cl_ + (size_t)gr1 * 2048 + colb) = pack_res(o0, o1, hp);
        o0 = Oacc[nt][2] * inv2; o1 = Oacc[nt][3] * inv2;
        hp = pack_bf16(o0, o1);
        *(unsigned*)(Ch_ + (size_t)gr2 * 2048 + colb) = hp;
        *(unsigned*)(Cl_ + (size_t)gr2 * 2048 + colb) = pack_res(o0, o1, hp);
    }
}

// ---------------------------------------------------------------------------
extern "C" void kernel_launch(void* const* d_in, const int* in_sizes, int n_in,
                              void* d_out, int out_size)
{
    (void)in_sizes; (void)n_in; (void)out_size;
    const float* hidden  = (const float*)d_in[0];
    const float* qkv_w   = (const float*)d_in[2];
    const float* qkv_b   = (const float*)d_in[3];
    const float* svd_tok = (const float*)d_in[4];
    const float* svd_qk  = (const float*)d_in[5];
    const float* svd_vl  = (const float*)d_in[6];
    const float* dense_w = (const float*)d_in[7];
    const float* dense_b = (const float*)d_in[8];
    float* out = (float*)d_out;

    float *pmx, *pS, *pP, *pW2;
    cudaGetSymbolAddress((void**)&pmx, g_mixed);
    cudaGetSymbolAddress((void**)&pS, g_S);
    cudaGetSymbolAddress((void**)&pP, g_P);
    cudaGetSymbolAddress((void**)&pW2, g_W2);

    __nv_bfloat16 *pHh, *pHl, *pRh, *pRl, *pMh, *pMl, *pX2h, *pX2l;
    __nv_bfloat16 *pWqh, *pWql, *pCh, *pCl, *pW2Th, *pW2Tl;
    __nv_bfloat16 *pqph, *pqpl, *pKh, *pKl, *pVth, *pVtl;
    cudaGetSymbolAddress((void**)&pHh, g_Hh);   cudaGetSymbolAddress((void**)&pHl, g_Hl);
    cudaGetSymbolAddress((void**)&pRh, g_Rh);   cudaGetSymbolAddress((void**)&pRl, g_Rl);
    cudaGetSymbolAddress((void**)&pMh, g_Mh);   cudaGetSymbolAddress((void**)&pMl, g_Ml);
    cudaGetSymbolAddress((void**)&pX2h, g_X2h); cudaGetSymbolAddress((void**)&pX2l, g_X2l);
    cudaGetSymbolAddress((void**)&pWqh, g_Wqh); cudaGetSymbolAddress((void**)&pWql, g_Wql);
    cudaGetSymbolAddress((void**)&pCh, g_Ch);   cudaGetSymbolAddress((void**)&pCl, g_Cl);
    cudaGetSymbolAddress((void**)&pW2Th, g_W2Th); cudaGetSymbolAddress((void**)&pW2Tl, g_W2Tl);
    cudaGetSymbolAddress((void**)&pqph, g_qph); cudaGetSymbolAddress((void**)&pqpl, g_qpl);
    cudaGetSymbolAddress((void**)&pKh, g_Kh);   cudaGetSymbolAddress((void**)&pKl, g_Kl);
    cudaGetSymbolAddress((void**)&pVth, g_Vth); cudaGetSymbolAddress((void**)&pVtl, g_Vtl);

    cudaFuncSetAttribute(mma_gemm, cudaFuncAttributeMaxDynamicSharedMemorySize, GEMM_SMEM);
    cudaFuncSetAttribute(attn_mma, cudaFuncAttributeMaxDynamicSharedMemorySize, ATTN2_SMEM);

    const dim3 blk(256);
    const int N4_2048 = (2048 * 2048) / 4;
    const int N4_W = (6144 * 2048) / 4;

    // input conversions
    cvt_split<<<N4_2048 / 256, 256>>>((const float4*)hidden, (__nv_bfloat162*)pHh, (__nv_bfloat162*)pHl, N4_2048);
    cvt_split<<<N4_2048 / 256, 256>>>((const float4*)svd_tok, (__nv_bfloat162*)pRh, (__nv_bfloat162*)pRl, N4_2048);
    cvt_split<<<N4_W / 256, 256>>>((const float4*)qkv_w, (__nv_bfloat162*)pWqh, (__nv_bfloat162*)pWql, N4_W);

    // 1) M = R @ R^T -> hi/lo bf16 directly
    mma_gemm<<<dim3(16, 16), blk, GEMM_SMEM>>>(pRh, pRl, pRh, pRl,
        nullptr, pMh, pMl, 2048, nullptr, 2048, 2048, 2048);
    // 2) X2 = hidden @ M^T (M symmetric) -> hi/lo bf16 directly
    mma_gemm<<<dim3(16, 16), blk, GEMM_SMEM>>>(pHh, pHl, pMh, pMl,
        nullptr, pX2h, pX2l, 2048, nullptr, 2048, 2048, 2048);
    // 3) mixed = X2 @ qkv_w^T + qkv_b (fp32)
    mma_gemm<<<dim3(48, 16), blk, GEMM_SMEM>>>(pX2h, pX2l, pWqh, pWql,
        pmx, nullptr, nullptr, 6144, qkv_b, 2048, 2048, 2048);

    // K/V prep
    split_k<<<4096, 256>>>(pmx, pKh, pKl);
    vtrans_split<<<dim3(64, 4, 16), dim3(32, 8)>>>(pmx, pVth, pVtl);

    // 4) S_h, P_h (fp32)
    sgemm_kernel<true, false><<<dim3(1, 1, 16), blk>>>(
        svd_qk, 128, 16384, svd_qk, 128, 16384, pS, nullptr, nullptr, 128, 16384, 128);
    sgemm_kernel<true, false><<<dim3(1, 1, 16), blk>>>(
        svd_vl, 128, 16384, svd_vl, 128, 16384, pP, nullptr, nullptr, 128, 16384, 128);
    // 5) W2_h = P_h @ dense_w[h] (fp32), then transpose+split
    sgemm_kernel<false, false><<<dim3(16, 1, 16), blk>>>(
        pP, 128, 16384, dense_w, 2048, 262144, pW2, nullptr, nullptr, 2048, 262144, 128);
    trans_cvt<<<dim3(64, 64), dim3(32, 8)>>>(pW2, pW2Th, pW2Tl);
    // 6) q'_h = q_h @ S_h -> hi/lo bf16 directly (per-head column offset sC=128)
    sgemm_kernel<false, true><<<dim3(1, 16, 16), blk>>>(
        pmx, 6144, 384, pS, 128, 16384, nullptr, pqph, pqpl, 2048, 128, 128);

    // 7) attention -> Ch/Cl
    attn_mma<<<dim3(16, 16), blk, ATTN2_SMEM>>>(pqph, pqpl, pKh, pKl, pVth, pVtl, pCh, pCl);

    // 8) out = ctx @ W2 + dense_b
    mma_gemm<<<dim3(16, 16), blk, GEMM_SMEM>>>(pCh, pCl, pW2Th, pW2Tl,
        out, nullptr, nullptr, 2048, dense_b, 2048, 2048, 2048);
}

// round 11
// speedup vs baseline: 3.3748x; 1.2471x over previous
#include <cuda_runtime.h>
#include <cuda_bf16.h>
#include <cuda_fp16.h>

#define SQN 2048
#define HIDN 2048
#define NHD 16
#define HDIM 128
#define H3 6144

// ---------------- fp32 scratch ----------------
__device__ float g_S[NHD * HDIM * HDIM];
__device__ float g_P[NHD * HDIM * HDIM];
__device__ float g_W2[HIDN * HIDN];
__device__ float g_bmod[H3];

// ---------------- fp16 hi/lo scratch (GEMM operands) ----------------
__device__ __half g_Hh[SQN * HIDN],  g_Hl[SQN * HIDN];
__device__ __half g_Rh[HIDN * HIDN], g_Rl[HIDN * HIDN];
__device__ __half g_Mh[HIDN * HIDN], g_Ml[HIDN * HIDN];
__device__ __half g_X2h[SQN * HIDN], g_X2l[SQN * HIDN];
__device__ __half g_Wqh[H3 * HIDN],  g_Wql[H3 * HIDN];
__device__ __half g_Ch[SQN * HIDN],  g_Cl[SQN * HIDN];
__device__ __half g_W2Th[HIDN * HIDN], g_W2Tl[HIDN * HIDN];

// ---------------- bf16 hi/lo scratch (attention operands) ----------------
__device__ __nv_bfloat16 g_Qh[NHD * SQN * HDIM], g_Ql[NHD * SQN * HDIM];
__device__ __nv_bfloat16 g_Kh[NHD * SQN * HDIM], g_Kl[NHD * SQN * HDIM];
__device__ __nv_bfloat16 g_Vh[NHD * SQN * HDIM], g_Vl[NHD * SQN * HDIM];
__device__ __nv_bfloat16 g_Vth[NHD * HDIM * SQN], g_Vtl[NHD * HDIM * SQN];

__device__ __forceinline__ unsigned smem_u32(const void* p) {
    unsigned a;
    asm("{ .reg .u64 t; cvta.to.shared.u64 t, %1; cvt.u32.u64 %0, t; }"
        : "=r"(a) : "l"(p));
    return a;
}

#define LDM_X4(r, a)                                                          \
    asm volatile("ldmatrix.sync.aligned.m8n8.x4.shared.b16 {%0,%1,%2,%3}, [%4];" \
                 : "=r"((r)[0]), "=r"((r)[1]), "=r"((r)[2]), "=r"((r)[3])     \
                 : "r"(a))

#define MMA_BF(d, a, b0, b1)                                                  \
    asm volatile("mma.sync.aligned.m16n8k16.row.col.f32.bf16.bf16.f32 "       \
                 "{%0,%1,%2,%3}, {%4,%5,%6,%7}, {%8,%9}, {%0,%1,%2,%3};"      \
                 : "+f"((d)[0]), "+f"((d)[1]), "+f"((d)[2]), "+f"((d)[3])     \
                 : "r"((a)[0]), "r"((a)[1]), "r"((a)[2]), "r"((a)[3]),        \
                   "r"(b0), "r"(b1))

#define MMA_FP(d, a, b0, b1)                                                  \
    asm volatile("mma.sync.aligned.m16n8k16.row.col.f32.f16.f16.f32 "         \
                 "{%0,%1,%2,%3}, {%4,%5,%6,%7}, {%8,%9}, {%0,%1,%2,%3};"      \
                 : "+f"((d)[0]), "+f"((d)[1]), "+f"((d)[2]), "+f"((d)[3])     \
                 : "r"((a)[0]), "r"((a)[1]), "r"((a)[2]), "r"((a)[3]),        \
                   "r"(b0), "r"(b1))

#define CP_ASYNC16(s, g) \
    asm volatile("cp.async.cg.shared.global [%0], [%1], 16;" :: "r"(s), "l"(g))
#define CP_COMMIT() asm volatile("cp.async.commit_group;" ::: "memory")
#define CP_WAIT2()  asm volatile("cp.async.wait_group 2;" ::: "memory")
#define CP_WAIT1()  asm volatile("cp.async.wait_group 1;" ::: "memory")
#define CP_WAIT0()  asm volatile("cp.async.wait_group 0;" ::: "memory")

__device__ __forceinline__ unsigned pack_bf16(float lo, float hi) {
    unsigned r;
    asm("cvt.rn.bf16x2.f32 %0, %1, %2;" : "=r"(r) : "f"(hi), "f"(lo));
    return r;
}
__device__ __forceinline__ unsigned pack_res_bf(float lo, float hi, unsigned hp) {
    __nv_bfloat162 h = *reinterpret_cast<__nv_bfloat162*>(&hp);
    return pack_bf16(lo - __bfloat162float(h.x), hi - __bfloat162float(h.y));
}
__device__ __forceinline__ unsigned pack_f16(float lo, float hi) {
    unsigned r;
    asm("cvt.rn.f16x2.f32 %0, %1, %2;" : "=r"(r) : "f"(hi), "f"(lo));
    return r;
}
__device__ __forceinline__ unsigned pack_res_f16(float lo, float hi, unsigned hp) {
    __half2 h = *reinterpret_cast<__half2*>(&hp);
    return pack_f16(lo - __half2float(h.x), hi - __half2float(h.y));
}

// ---------------------------------------------------------------------------
// fp16x2 split conversion: x -> (hi, lo)
// ---------------------------------------------------------------------------
__global__ void cvt_split_f16(const float4* __restrict__ in,
                              __half2* __restrict__ hi,
                              __half2* __restrict__ lo, int n4)
{
    int i = blockIdx.x * blockDim.x + threadIdx.x;
    if (i >= n4) return;
    float4 v = in[i];
    __half h0 = __float2half(v.x), h1 = __float2half(v.y);
    __half h2 = __float2half(v.z), h3 = __float2half(v.w);
    __half2 a, b;
    a.x = h0; a.y = h1; b.x = h2; b.y = h3;
    hi[i * 2] = a; hi[i * 2 + 1] = b;
    a.x = __float2half(v.x - __half2float(h0));
    a.y = __float2half(v.y - __half2float(h1));
    b.x = __float2half(v.z - __half2float(h2));
    b.y = __float2half(v.w - __half2float(h3));
    lo[i * 2] = a; lo[i * 2 + 1] = b;
}

// Transpose [2048,2048] fp32 -> hi/lo fp16 of the transpose
__global__ void trans_cvt_f16(const float* __restrict__ in,
                              __half* __restrict__ hi,
                              __half* __restrict__ lo)
{
    __shared__ float t[32][33];
    int xi = blockIdx.x * 32 + threadIdx.x;
    int yi = blockIdx.y * 32 + threadIdx.y;
#pragma unroll
    for (int j = 0; j < 32; j += 8)
        t[threadIdx.y + j][threadIdx.x] = in[(size_t)(yi + j) * 2048 + xi];
    __syncthreads();
    int xo = blockIdx.y * 32 + threadIdx.x;
    int yo = blockIdx.x * 32 + threadIdx.y;
#pragma unroll
    for (int j = 0; j < 32; j += 8) {
        float v = t[threadIdx.x][threadIdx.y + j];
        __half h = __float2half(v);
        hi[(size_t)(yo + j) * 2048 + xo] = h;
        lo[(size_t)(yo + j) * 2048 + xo] = __float2half(v - __half2float(h));
    }
}

// V transpose (bf16, hi+lo): [h][t][d] -> [h][d][t]
__global__ void vtrans_bf(const __nv_bfloat16* __restrict__ Vh_,
                          const __nv_bfloat16* __restrict__ Vl_,
                          __nv_bfloat16* __restrict__ Vth_,
                          __nv_bfloat16* __restrict__ Vtl_)
{
    __shared__ __nv_bfloat16 th[32][33], tl[32][33];
    int hh = blockIdx.z;
    int e0 = blockIdx.y * 32, t0 = blockIdx.x * 32;
    int tx = threadIdx.x, ty = threadIdx.y;
#pragma unroll
    for (int j = 0; j < 32; j += 8) {
        size_t idx = ((size_t)hh * 2048 + t0 + ty + j) * 128 + e0 + tx;
        th[ty + j][tx] = Vh_[idx];
        tl[ty + j][tx] = Vl_[idx];
    }
    __syncthreads();
#pragma unroll
    for (int j = 0; j < 32; j += 8) {
        size_t o = ((size_t)hh * 128 + e0 + ty + j) * 2048 + t0 + tx;
        Vth_[o] = th[tx][ty + j];
        Vtl_[o] = tl[tx][ty + j];
    }
}

// rotated bias: bmod[h*384+e] = sum_d S_h[d][e]*b[h*384+d] for e<128, else b
__global__ void bias_rot(const float* __restrict__ S, const float* __restrict__ b,
                         float* __restrict__ bmod)
{
    int e = blockIdx.x * 256 + threadIdx.x;
    if (e >= H3) return;
    int h = e / 384, r = e - h * 384;
    if (r < 128) {
        const float* Sh = S + h * 16384;
        const float* bh = b + h * 384;
        float s = 0.0f;
#pragma unroll 8
        for (int d = 0; d < 128; d++) s += Sh[d * 128 + r] * bh[d];
        bmod[e] = s;
    } else {
        bmod[e] = b[e];
    }
}

// ---------------------------------------------------------------------------
// fp16x2 GEMM via mma.sync (2 passes: (Ah+Al)@Bh^T). 3-stage cp.async,
// 2 CTAs/SM. BM=BN=128, BK=32, 8 warps (32x64 warp tile).
// OM: 0 = fp32 C (+bias), 1 = fp16 hi/lo pair, 2 = QKV bf16 stripes (+bias).
// ---------------------------------------------------------------------------
#define TILE_B 10240
#define STAGE_B (3 * TILE_B)      // Ah | Al | Bh
#define GEMM_SMEM (3 * STAGE_B)   // 92160

template <int OM>
__global__ __launch_bounds__(256, 2)
void mma_gemm(const __half* __restrict__ Ah, const __half* __restrict__ Al,
              const __half* __restrict__ Bh,
              float* __restrict__ C, __half* __restrict__ Coh,
              __half* __restrict__ Col, int ldc,
              const float* __restrict__ bias, int K, int lda, int ldb)
{
    extern __shared__ __align__(16) char smem[];

    const int tid = threadIdx.x;
    const int wid = tid >> 5;
    const int lane = tid & 31;
    const int m0 = blockIdx.y * 128;
    const int n0 = blockIdx.x * 128;
    const int wm = (wid & 3) * 32;
    const int wn = (wid >> 2) * 64;

    float acc[2][8][4];
#pragma unroll
    for (int i = 0; i < 2; i++)
#pragma unroll
        for (int j = 0; j < 8; j++)
#pragma unroll
            for (int k = 0; k < 4; k++) acc[i][j][k] = 0.0f;

    const __half* srcs[3] = {Ah, Al, Bh};
    const int lds[3] = {lda, lda, ldb};
    const int r0s[3] = {m0, m0, n0};

    const unsigned smb = smem_u32(smem);

    auto issue_stage = [&](int t, int buf) {
        const int k0 = t * 32;
        const unsigned sb = smb + buf * STAGE_B;
#pragma unroll
        for (int i = 0; i < 6; i++) {
            const int id = i * 256 + tid;       // 0..1535
            const int tile = id >> 9;           // 0..2
            const int cid = id & 511;
            const int row = cid >> 2;
            const int c = cid & 3;
            const __half* g =
                srcs[tile] + (size_t)(r0s[tile] + row) * lds[tile] + k0 + c * 8;
            CP_ASYNC16(sb + tile * TILE_B + row * 80 + c * 16, g);
        }
        CP_COMMIT();
    };

    const int T = K >> 5;
    issue_stage(0, 0);
    issue_stage(1, 1);

    const unsigned a_lrow = (lane & 15) * 80 + (lane >> 4) * 16;
    const unsigned b_lrow = ((lane & 7) + ((lane >> 4) << 3)) * 80 + ((lane >> 3) & 1) * 16;

    for (int t = 0; t < T; t++) {
        if (t + 2 < T) { issue_stage(t + 2, (t + 2) % 3); CP_WAIT2(); }
        else if (t + 1 < T) { CP_WAIT1(); }
        else { CP_WAIT0(); }
        __syncthreads();

        const unsigned st = smb + (t % 3) * STAGE_B;
        const unsigned aHb = st + wm * 80 + a_lrow;
        const unsigned aLb = st + TILE_B + wm * 80 + a_lrow;
        const unsigned bHb = st + 2 * TILE_B + wn * 80 + b_lrow;

#pragma unroll
        for (int ks = 0; ks < 2; ks++) {
            unsigned aH[2][4], aL[2][4];
#pragma unroll
            for (int mt = 0; mt < 2; mt++) {
                LDM_X4(aH[mt], aHb + mt * (16 * 80) + ks * 32);
                LDM_X4(aL[mt], aLb + mt * (16 * 80) + ks * 32);
            }
#pragma unroll
            for (int ng = 0; ng < 4; ng++) {
                unsigned bH[4];
                LDM_X4(bH, bHb + ng * (16 * 80) + ks * 32);
#pragma unroll
                for (int mt = 0; mt < 2; mt++) {
                    MMA_FP(acc[mt][2 * ng],     aH[mt], bH[0], bH[1]);
                    MMA_FP(acc[mt][2 * ng + 1], aH[mt], bH[2], bH[3]);
                    MMA_FP(acc[mt][2 * ng],     aL[mt], bH[0], bH[1]);
                    MMA_FP(acc[mt][2 * ng + 1], aL[mt], bH[2], bH[3]);
                }
            }
        }
        __syncthreads();
    }

#pragma unroll
    for (int mt = 0; mt < 2; mt++) {
        const int m = m0 + wm + mt * 16 + (lane >> 2);
#pragma unroll
        for (int nt = 0; nt < 8; nt++) {
            const int n = n0 + wn + nt * 8 + (lane & 3) * 2;
            float bx = 0.0f, by = 0.0f;
            if (OM != 1 && bias) { bx = bias[n]; by = bias[n + 1]; }
            float v00 = acc[mt][nt][0] + bx, v01 = acc[mt][nt][1] + by;
            float v10 = acc[mt][nt][2] + bx, v11 = acc[mt][nt][3] + by;
            if (OM == 0) {
                *(float2*)(C + (size_t)m * ldc + n) = make_float2(v00, v01);
                *(float2*)(C + (size_t)(m + 8) * ldc + n) = make_float2(v10, v11);
            } else if (OM == 1) {
                unsigned hp = pack_f16(v00, v01);
                *(unsigned*)(Coh + (size_t)m * ldc + n) = hp;
                *(unsigned*)(Col + (size_t)m * ldc + n) = pack_res_f16(v00, v01, hp);
                hp = pack_f16(v10, v11);
                *(unsigned*)(Coh + (size_t)(m + 8) * ldc + n) = hp;
                *(unsigned*)(Col + (size_t)(m + 8) * ldc + n) = pack_res_f16(v10, v11, hp);
            } else {
                const int h = n / 384;
                const int r = n - h * 384;
                const int stp = r >> 7;
                const int d = r & 127;
                __nv_bfloat16* Dh = (stp == 0) ? g_Qh : ((stp == 1) ? g_Kh : g_Vh);
                __nv_bfloat16* Dl = (stp == 0) ? g_Ql : ((stp == 1) ? g_Kl : g_Vl);
                size_t o = ((size_t)h * 2048 + m) * 128 + d;
                unsigned hp = pack_bf16(v00, v01);
                *(unsigned*)(Dh + o) = hp;
                *(unsigned*)(Dl + o) = pack_res_bf(v00, v01, hp);
                o += 8 * 128;
                hp = pack_bf16(v10, v11);
                *(unsigned*)(Dh + o) = hp;
                *(unsigned*)(Dl + o) = pack_res_bf(v10, v11, hp);
            }
        }
    }
}

// ---------------------------------------------------------------------------
// fp32 SGEMM (small GEMMs). OM: 0 fp32, 1 fp16 hi/lo pairs.
// ---------------------------------------------------------------------------
template <bool TB, int OM>
__global__ __launch_bounds__(256) void sgemm_kernel(
    const float* __restrict__ A, int lda, long long sA,
    const float* __restrict__ B, int ldb, long long sB,
    float* __restrict__ C, __half* __restrict__ Coh,
    __half* __restrict__ Col, int ldc, long long sC, int K)
{
    __shared__ float As[8][128];
    __shared__ float Bs[8][128];

    const float* Ab = A + (long long)blockIdx.z * sA;
    const float* Bb = B + (long long)blockIdx.z * sB;
    const long long zoff = (long long)blockIdx.z * sC;

    const int m0 = blockIdx.y * 128;
    const int n0 = blockIdx.x * 128;
    const int tid = threadIdx.x;
    const int tx = tid & 15;
    const int ty = tid >> 4;

    float acc[8][8];
#pragma unroll
    for (int i = 0; i < 8; i++)
#pragma unroll
        for (int j = 0; j < 8; j++) acc[i][j] = 0.0f;

    const int arow = tid >> 1;
    const int ak = (tid & 1) * 4;

    for (int k0 = 0; k0 < K; k0 += 8) {
        float4 av = *(const float4*)(Ab + (long long)(m0 + arow) * lda + k0 + ak);
        As[ak + 0][arow] = av.x;
        As[ak + 1][arow] = av.y;
        As[ak + 2][arow] = av.z;
        As[ak + 3][arow] = av.w;
        if (!TB) {
            const int bk = tid >> 5;
            const int bn = (tid & 31) * 4;
            *(float4*)&Bs[bk][bn] =
                *(const float4*)(Bb + (long long)(k0 + bk) * ldb + n0 + bn);
        } else {
            const int bn = tid >> 1;
            const int bk = (tid & 1) * 4;
            float4 bv = *(const float4*)(Bb + (long long)(n0 + bn) * ldb + k0 + bk);
            Bs[bk + 0][bn] = bv.x;
            Bs[bk + 1][bn] = bv.y;
            Bs[bk + 2][bn] = bv.z;
            Bs[bk + 3][bn] = bv.w;
        }
        __syncthreads();
#pragma unroll
        for (int k = 0; k < 8; k++) {
            float a[8], b[8];
            *(float4*)&a[0] = *(const float4*)&As[k][ty * 8];
            *(float4*)&a[4] = *(const float4*)&As[k][ty * 8 + 4];
            *(float4*)&b[0] = *(const float4*)&Bs[k][tx * 8];
            *(float4*)&b[4] = *(const float4*)&Bs[k][tx * 8 + 4];
#pragma unroll
            for (int i = 0; i < 8; i++)
#pragma unroll
                for (int j = 0; j < 8; j++) acc[i][j] += a[i] * b[j];
        }
        __syncthreads();
    }

#pragma unroll
    for (int i = 0; i < 8; i++) {
        const int row = m0 + ty * 8 + i;
        const long long base = zoff + (long long)row * ldc;
#pragma unroll
        for (int j = 0; j < 8; j += 2) {
            const int col = n0 + tx * 8 + j;
            if (OM == 1) {
                unsigned hp = pack_f16(acc[i][j], acc[i][j + 1]);
                *(unsigned*)(Coh + base + col) = hp;
                *(unsigned*)(Col + base + col) = pack_res_f16(acc[i][j], acc[i][j + 1], hp);
            } else {
                *(float2*)(C + base + col) = make_float2(acc[i][j], acc[i][j + 1]);
            }
        }
    }
}

// ---------------------------------------------------------------------------
// Tensor-core causal flash attention (bf16x3). 128 Q rows x head per block.
// Inputs: Q/K bf16 hi/lo [h][t][d]; Vt bf16 hi/lo [h][d][t].
// Output: ctx as fp16 hi/lo [t][2048] for the final GEMM.
// ---------------------------------------------------------------------------
#define AQ_PITCH 272
#define AV_PITCH 144
#define SQH_B (128 * AQ_PITCH)
#define SKH_B (64 * AQ_PITCH)
#define SVH_B (128 * AV_PITCH)
#define KV_STAGE (2 * SKH_B + 2 * SVH_B)
#define ATTN2_SMEM (2 * SQH_B + 2 * KV_STAGE)

__global__ __launch_bounds__(256, 1) void attn_mma(
    const __nv_bfloat16* __restrict__ Qh_, const __nv_bfloat16* __restrict__ Ql_,
    const __nv_bfloat16* __restrict__ Kh_, const __nv_bfloat16* __restrict__ Kl_,
    const __nv_bfloat16* __restrict__ Vth_, const __nv_bfloat16* __restrict__ Vtl_,
    __half* __restrict__ Ch_, __half* __restrict__ Cl_)
{
    extern __shared__ __align__(16) char sm[];
    const int h = blockIdx.y;
    const int rb = (int)gridDim.x - 1 - (int)blockIdx.x;
    const int r0 = rb * 128;
    const int tid = threadIdx.x;
    const int wid = tid >> 5;
    const int lane = tid & 31;

    const unsigned sQh = smem_u32(sm);
    const unsigned sQl = sQh + SQH_B;
    const unsigned sKV0 = sQl + SQH_B;

    {
        const __nv_bfloat16* gq = Qh_ + ((size_t)h * 2048 + r0) * 128;
        const __nv_bfloat16* gql = Ql_ + ((size_t)h * 2048 + r0) * 128;
#pragma unroll
        for (int it = 0; it < 8; it++) {
            int id = it * 256 + tid;
            int row = id >> 4, c = id & 15;
            CP_ASYNC16(sQh + row * AQ_PITCH + c * 16, gq + (size_t)row * 128 + c * 8);
            CP_ASYNC16(sQl + row * AQ_PITCH + c * 16, gql + (size_t)row * 128 + c * 8);
        }
    }
    const __nv_bfloat16* gK = Kh_ + (size_t)h * 2048 * 128;
    const __nv_bfloat16* gKl = Kl_ + (size_t)h * 2048 * 128;
    const __nv_bfloat16* gV = Vth_ + (size_t)h * 128 * 2048;
    const __nv_bfloat16* gVl = Vtl_ + (size_t)h * 128 * 2048;

    auto issue_kv = [&](int t, int buf) {
        const int t0 = t * 64;
        const unsigned sb = sKV0 + buf * KV_STAGE;
#pragma unroll
        for (int it = 0; it < 4; it++) {
            int id = it * 256 + tid;
            int row = id >> 4, c = id & 15;
            CP_ASYNC16(sb + row * AQ_PITCH + c * 16, gK + (size_t)(t0 + row) * 128 + c * 8);
            CP_ASYNC16(sb + SKH_B + row * AQ_PITCH + c * 16, gKl + (size_t)(t0 + row) * 128 + c * 8);
        }
#pragma unroll
        for (int it = 0; it < 4; it++) {
            int id = it * 256 + tid;
            int row = id >> 3, c = id & 7;
            CP_ASYNC16(sb + 2 * SKH_B + row * AV_PITCH + c * 16, gV + (size_t)row * 2048 + t0 + c * 8);
            CP_ASYNC16(sb + 2 * SKH_B + SVH_B + row * AV_PITCH + c * 16, gVl + (size_t)row * 2048 + t0 + c * 8);
        }
    };

    issue_kv(0, 0);
    CP_COMMIT();

    float sacc[8][4];
    float Oacc[16][4];
#pragma unroll
    for (int i = 0; i < 16; i++)
#pragma unroll
        for (int j = 0; j < 4; j++) Oacc[i][j] = 0.0f;
    float m1 = -1e30f, m2 = -1e30f, l1 = 0.0f, l2 = 0.0f;

    const int gr1 = r0 + wid * 16 + (lane >> 2);
    const int gr2 = gr1 + 8;
    const float scale = 0.08838834764831845f;

    const unsigned a_off = (lane & 15) * AQ_PITCH + (lane >> 4) * 16;
    const unsigned kb_off = ((lane & 7) + ((lane >> 4) << 3)) * AQ_PITCH + ((lane >> 3) & 1) * 16;
    const unsigned vb_off = ((lane & 7) + ((lane >> 4) << 3)) * AV_PITCH + ((lane >> 3) & 1) * 16;
    const unsigned aQh_b = sQh + wid * 16 * AQ_PITCH + a_off;
    const unsigned aQl_b = sQl + wid * 16 * AQ_PITCH + a_off;

    const int T = 2 * rb + 2;
    for (int t = 0; t < T; t++) {
        if (t + 1 < T) { issue_kv(t + 1, (t + 1) & 1); CP_COMMIT(); CP_WAIT1(); }
        else { CP_WAIT0(); }
        __syncthreads();

        const unsigned sb = sKV0 + (t & 1) * KV_STAGE;
        const unsigned kh_b = sb + kb_off;
        const unsigned kl_b = sb + SKH_B + kb_off;

#pragma unroll
        for (int i = 0; i < 8; i++)
#pragma unroll
            for (int j = 0; j < 4; j++) sacc[i][j] = 0.0f;

#pragma unroll
        for (int kd = 0; kd < 8; kd++) {
            unsigned qh[4], ql[4];
            LDM_X4(qh, aQh_b + kd * 32);
            LDM_X4(ql, aQl_b + kd * 32);
#pragma unroll
            for (int ng = 0; ng < 4; ng++) {
                unsigned bh[4], bl[4];
                LDM_X4(bh, kh_b + ng * (16 * AQ_PITCH) + kd * 32);
                LDM_X4(bl, kl_b + ng * (16 * AQ_PITCH) + kd * 32);
                MMA_BF(sacc[2 * ng],     qh, bh[0], bh[1]);
                MMA_BF(sacc[2 * ng + 1], qh, bh[2], bh[3]);
                MMA_BF(sacc[2 * ng],     qh, bl[0], bl[1]);
                MMA_BF(sacc[2 * ng + 1], qh, bl[2], bl[3]);
                MMA_BF(sacc[2 * ng],     ql, bh[0], bh[1]);
                MMA_BF(sacc[2 * ng + 1], ql, bh[2], bh[3]);
            }
        }

        const int c0 = t * 64;
#pragma unroll
        for (int nt = 0; nt < 8; nt++)
#pragma unroll
            for (int j = 0; j < 4; j++) sacc[nt][j] *= scale;

        if (t >= 2 * rb) {
#pragma unroll
            for (int nt = 0; nt < 8; nt++) {
                int col = c0 + nt * 8 + (lane & 3) * 2;
                if (col     > gr1) sacc[nt][0] = -1e30f;
                if (col + 1 > gr1) sacc[nt][1] = -1e30f;
                if (col     > gr2) sacc[nt][2] = -1e30f;
                if (col + 1 > gr2) sacc[nt][3] = -1e30f;
            }
        }

        float mx1 = -1e30f, mx2 = -1e30f;
#pragma unroll
        for (int nt = 0; nt < 8; nt++) {
            mx1 = fmaxf(mx1, fmaxf(sacc[nt][0], sacc[nt][1]));
            mx2 = fmaxf(mx2, fmaxf(sacc[nt][2], sacc[nt][3]));
        }
        mx1 = fmaxf(mx1, __shfl_xor_sync(0xffffffffu, mx1, 1));
        mx1 = fmaxf(mx1, __shfl_xor_sync(0xffffffffu, mx1, 2));
        mx2 = fmaxf(mx2, __shfl_xor_sync(0xffffffffu, mx2, 1));
        mx2 = fmaxf(mx2, __shfl_xor_sync(0xffffffffu, mx2, 2));
        const float mn1 = fmaxf(m1, mx1), mn2 = fmaxf(m2, mx2);
        const float corr1 = __expf(m1 - mn1), corr2 = __expf(m2 - mn2);
        m1 = mn1; m2 = mn2;
        float rs1 = 0.0f, rs2 = 0.0f;
#pragma unroll
        for (int nt = 0; nt < 8; nt++) {
            sacc[nt][0] = __expf(sacc[nt][0] - m1); rs1 += sacc[nt][0];
            sacc[nt][1] = __expf(sacc[nt][1] - m1); rs1 += sacc[nt][1];
            sacc[nt][2] = __expf(sacc[nt][2] - m2); rs2 += sacc[nt][2];
            sacc[nt][3] = __expf(sacc[nt][3] - m2); rs2 += sacc[nt][3];
        }
        rs1 += __shfl_xor_sync(0xffffffffu, rs1, 1);
        rs1 += __shfl_xor_sync(0xffffffffu, rs1, 2);
        rs2 += __shfl_xor_sync(0xffffffffu, rs2, 1);
        rs2 += __shfl_xor_sync(0xffffffffu, rs2, 2);
        l1 = l1 * corr1 + rs1;
        l2 = l2 * corr2 + rs2;
#pragma unroll
        for (int nt = 0; nt < 16; nt++) {
            Oacc[nt][0] *= corr1; Oacc[nt][1] *= corr1;
            Oacc[nt][2] *= corr2; Oacc[nt][3] *= corr2;
        }

        const unsigned vh_b = sb + 2 * SKH_B + vb_off;
        const unsigned vl_b = sb + 2 * SKH_B + SVH_B + vb_off;
#pragma unroll
        for (int kt = 0; kt < 4; kt++) {
            unsigned ph[4], pl[4];
            ph[0] = pack_bf16(sacc[2 * kt][0], sacc[2 * kt][1]);
            ph[1] = pack_bf16(sacc[2 * kt][2], sacc[2 * kt][3]);
            ph[2] = pack_bf16(sacc[2 * kt + 1][0], sacc[2 * kt + 1][1]);
            ph[3] = pack_bf16(sacc[2 * kt + 1][2], sacc[2 * kt + 1][3]);
            pl[0] = pack_res_bf(sacc[2 * kt][0], sacc[2 * kt][1], ph[0]);
            pl[1] = pack_res_bf(sacc[2 * kt][2], sacc[2 * kt][3], ph[1]);
            pl[2] = pack_res_bf(sacc[2 * kt + 1][0], sacc[2 * kt + 1][1], ph[2]);
            pl[3] = pack_res_bf(sacc[2 * kt + 1][2], sacc[2 * kt + 1][3], ph[3]);
#pragma unroll
            for (int ng = 0; ng < 8; ng++) {
                unsigned vh[4], vl[4];
                LDM_X4(vh, vh_b + ng * (16 * AV_PITCH) + kt * 32);
                LDM_X4(vl, vl_b + ng * (16 * AV_PITCH) + kt * 32);
                MMA_BF(Oacc[2 * ng],     ph, vh[0], vh[1]);
                MMA_BF(Oacc[2 * ng + 1], ph, vh[2], vh[3]);
                MMA_BF(Oacc[2 * ng],     ph, vl[0], vl[1]);
                MMA_BF(Oacc[2 * ng + 1], ph, vl[2], vl[3]);
                MMA_BF(Oacc[2 * ng],     pl, vh[0], vh[1]);
                MMA_BF(Oacc[2 * ng + 1], pl, vh[2], vh[3]);
            }
        }
        __syncthreads();
    }

    const float inv1 = 1.0f / l1, inv2 = 1.0f / l2;
#pragma unroll
    for (int nt = 0; nt < 16; nt++) {
        const int colb = h * 128 + nt * 8 + (lane & 3) * 2;
        float o0 = Oacc[nt][0] * inv1, o1 = Oacc[nt][1] * inv1;
        unsigned hp = pack_f16(o0, o1);
        *(unsigned*)(Ch_ + (size_t)gr1 * 2048 + colb) = hp;
        *(unsigned*)(Cl_ + (size_t)gr1 * 2048 + colb) = pack_res_f16(o0, o1, hp);
        o0 = Oacc[nt][2] * inv2; o1 = Oacc[nt][3] * inv2;
        hp = pack_f16(o0, o1);
        *(unsigned*)(Ch_ + (size_t)gr2 * 2048 + colb) = hp;
        *(unsigned*)(Cl_ + (size_t)gr2 * 2048 + colb) = pack_res_f16(o0, o1, hp);
    }
}

// ---------------------------------------------------------------------------
extern "C" void kernel_launch(void* const* d_in, const int* in_sizes, int n_in,
                              void* d_out, int out_size)
{
    (void)in_sizes; (void)n_in; (void)out_size;
    const float* hidden  = (const float*)d_in[0];
    const float* qkv_w   = (const float*)d_in[2];
    const float* qkv_b   = (const float*)d_in[3];
    const float* svd_tok = (const float*)d_in[4];
    const float* svd_qk  = (const float*)d_in[5];
    const float* svd_vl  = (const float*)d_in[6];
    const float* dense_w = (const float*)d_in[7];
    const float* dense_b = (const float*)d_in[8];
    float* out = (float*)d_out;

    float *pS, *pP, *pW2, *pbmod;
    cudaGetSymbolAddress((void**)&pS, g_S);
    cudaGetSymbolAddress((void**)&pP, g_P);
    cudaGetSymbolAddress((void**)&pW2, g_W2);
    cudaGetSymbolAddress((void**)&pbmod, g_bmod);

    __half *pHh, *pHl, *pRh, *pRl, *pMh, *pMl, *pX2h, *pX2l;
    __half *pWqh, *pWql, *pCh, *pCl, *pW2Th, *pW2Tl;
    cudaGetSymbolAddress((void**)&pHh, g_Hh);   cudaGetSymbolAddress((void**)&pHl, g_Hl);
    cudaGetSymbolAddress((void**)&pRh, g_Rh);   cudaGetSymbolAddress((void**)&pRl, g_Rl);
    cudaGetSymbolAddress((void**)&pMh, g_Mh);   cudaGetSymbolAddress((void**)&pMl, g_Ml);
    cudaGetSymbolAddress((void**)&pX2h, g_X2h); cudaGetSymbolAddress((void**)&pX2l, g_X2l);
    cudaGetSymbolAddress((void**)&pWqh, g_Wqh); cudaGetSymbolAddress((void**)&pWql, g_Wql);
    cudaGetSymbolAddress((void**)&pCh, g_Ch);   cudaGetSymbolAddress((void**)&pCl, g_Cl);
    cudaGetSymbolAddress((void**)&pW2Th, g_W2Th); cudaGetSymbolAddress((void**)&pW2Tl, g_W2Tl);

    __nv_bfloat16 *pQh, *pQl, *pKh, *pKl, *pVh, *pVl, *pVth, *pVtl;
    cudaGetSymbolAddress((void**)&pQh, g_Qh);   cudaGetSymbolAddress((void**)&pQl, g_Ql);
    cudaGetSymbolAddress((void**)&pKh, g_Kh);   cudaGetSymbolAddress((void**)&pKl, g_Kl);
    cudaGetSymbolAddress((void**)&pVh, g_Vh);   cudaGetSymbolAddress((void**)&pVl, g_Vl);
    cudaGetSymbolAddress((void**)&pVth, g_Vth); cudaGetSymbolAddress((void**)&pVtl, g_Vtl);

    cudaFuncSetAttribute(mma_gemm<0>, cudaFuncAttributeMaxDynamicSharedMemorySize, GEMM_SMEM);
    cudaFuncSetAttribute(mma_gemm<1>, cudaFuncAttributeMaxDynamicSharedMemorySize, GEMM_SMEM);
    cudaFuncSetAttribute(mma_gemm<2>, cudaFuncAttributeMaxDynamicSharedMemorySize, GEMM_SMEM);
    cudaFuncSetAttribute(attn_mma, cudaFuncAttributeMaxDynamicSharedMemorySize, ATTN2_SMEM);

    const dim3 blk(256);
    const int N4_2048 = (2048 * 2048) / 4;
    const int N4_W = (6144 * 2048) / 4;

    // input conversions (fp16 hi/lo)
    cvt_split_f16<<<N4_2048 / 256, 256>>>((const float4*)hidden, (__half2*)pHh, (__half2*)pHl, N4_2048);
    cvt_split_f16<<<N4_2048 / 256, 256>>>((const float4*)svd_tok, (__half2*)pRh, (__half2*)pRl, N4_2048);
    cvt_split_f16<<<N4_W / 256, 256>>>((const float4*)qkv_w, (__half2*)pWqh, (__half2*)pWql, N4_W);

    // S_h = svd_qk[h] @ svd_qk[h]^T ; P_h likewise (fp32)
    sgemm_kernel<true, 0><<<dim3(1, 1, 16), blk>>>(
        svd_qk, 128, 16384, svd_qk, 128, 16384, pS, nullptr, nullptr, 128, 16384, 128);
    sgemm_kernel<true, 0><<<dim3(1, 1, 16), blk>>>(
        svd_vl, 128, 16384, svd_vl, 128, 16384, pP, nullptr, nullptr, 128, 16384, 128);

    // fold S into q-rows of the qkv weight: Wq'_h = S_h @ Wq_h  (overwrite fp16 stripes)
    sgemm_kernel<false, 1><<<dim3(16, 1, 16), blk>>>(
        pS, 128, 16384, qkv_w, 2048, (long long)384 * 2048,
        nullptr, pWqh, pWql, 2048, (long long)384 * 2048, 128);
    bias_rot<<<24, 256>>>(pS, qkv_b, pbmod);

    // 1) M = R @ R^T -> fp16 hi/lo
    mma_gemm<1><<<dim3(16, 16), blk, GEMM_SMEM>>>(pRh, pRl, pRh,
        nullptr, pMh, pMl, 2048, nullptr, 2048, 2048, 2048);
    // 2) X2 = hidden @ M^T (M symmetric) -> fp16 hi/lo
    mma_gemm<1><<<dim3(16, 16), blk, GEMM_SMEM>>>(pHh, pHl, pMh,
        nullptr, pX2h, pX2l, 2048, nullptr, 2048, 2048, 2048);
    // 3) [q'|k|v] = X2 @ Wmod^T + bmod -> bf16 Q/K/V stripes [h][t][d]
    mma_gemm<2><<<dim3(48, 16), blk, GEMM_SMEM>>>(pX2h, pX2l, pWqh,
        nullptr, nullptr, nullptr, 0, pbmod, 2048, 2048, 2048);

    // V transpose for attention
    vtrans_bf<<<dim3(64, 4, 16), dim3(32, 8)>>>(pVh, pVl, pVth, pVtl);

    // W2_h = P_h @ dense_w[h] (fp32), then transpose+split to fp16
    sgemm_kernel<false, 0><<<dim3(16, 1, 16), blk>>>(
        pP, 128, 16384, dense_w, 2048, 262144, pW2, nullptr, nullptr, 2048, 262144, 128);
    trans_cvt_f16<<<dim3(64, 64), dim3(32, 8)>>>(pW2, pW2Th, pW2Tl);

    // attention -> ctx fp16 hi/lo
    attn_mma<<<dim3(16, 16), blk, ATTN2_SMEM>>>(pQh, pQl, pKh, pKl, pVth, pVtl, pCh, pCl);

    // out = ctx @ W2 + dense_b (fp32 out)
    mma_gemm<0><<<dim3(16, 16), blk, GEMM_SMEM>>>(pCh, pCl, pW2Th,
        out, nullptr, nullptr, 2048, dense_b, 2048, 2048, 2048);
}

// round 12
// speedup vs baseline: 3.4878x; 1.0335x over previous
#include <cuda_runtime.h>
#include <cuda_bf16.h>
#include <cuda_fp16.h>

#define SQN 2048
#define HIDN 2048
#define NHD 16
#define HDIM 128
#define H3 6144

// ---------------- fp32 scratch ----------------
__device__ float g_S[NHD * HDIM * HDIM];
__device__ float g_P[NHD * HDIM * HDIM];
__device__ float g_W2[HIDN * HIDN];
__device__ float g_bmod[H3];

// ---------------- fp16 hi/lo scratch (GEMM operands) ----------------
__device__ __half g_Hh[SQN * HIDN],  g_Hl[SQN * HIDN];
__device__ __half g_Rh[HIDN * HIDN], g_Rl[HIDN * HIDN];
__device__ __half g_Mh[HIDN * HIDN], g_Ml[HIDN * HIDN];
__device__ __half g_X2h[SQN * HIDN], g_X2l[SQN * HIDN];
__device__ __half g_Wqh[H3 * HIDN],  g_Wql[H3 * HIDN];
__device__ __half g_Ch[SQN * HIDN],  g_Cl[SQN * HIDN];
__device__ __half g_W2Th[HIDN * HIDN], g_W2Tl[HIDN * HIDN];

// ---------------- bf16 hi/lo scratch (attention operands) ----------------
__device__ __nv_bfloat16 g_Qh[NHD * SQN * HDIM], g_Ql[NHD * SQN * HDIM];
__device__ __nv_bfloat16 g_Kh[NHD * SQN * HDIM], g_Kl[NHD * SQN * HDIM];
__device__ __nv_bfloat16 g_Vh[NHD * SQN * HDIM], g_Vl[NHD * SQN * HDIM];

__device__ __forceinline__ unsigned smem_u32(const void* p) {
    unsigned a;
    asm("{ .reg .u64 t; cvta.to.shared.u64 t, %1; cvt.u32.u64 %0, t; }"
        : "=r"(a) : "l"(p));
    return a;
}

#define LDM_X4(r, a)                                                          \
    asm volatile("ldmatrix.sync.aligned.m8n8.x4.shared.b16 {%0,%1,%2,%3}, [%4];" \
                 : "=r"((r)[0]), "=r"((r)[1]), "=r"((r)[2]), "=r"((r)[3])     \
                 : "r"(a))

#define LDM_X4_T(r, a)                                                        \
    asm volatile("ldmatrix.sync.aligned.m8n8.x4.trans.shared.b16 {%0,%1,%2,%3}, [%4];" \
                 : "=r"((r)[0]), "=r"((r)[1]), "=r"((r)[2]), "=r"((r)[3])     \
                 : "r"(a))

#define MMA_BF(d, a, b0, b1)                                                  \
    asm volatile("mma.sync.aligned.m16n8k16.row.col.f32.bf16.bf16.f32 "       \
                 "{%0,%1,%2,%3}, {%4,%5,%6,%7}, {%8,%9}, {%0,%1,%2,%3};"      \
                 : "+f"((d)[0]), "+f"((d)[1]), "+f"((d)[2]), "+f"((d)[3])     \
                 : "r"((a)[0]), "r"((a)[1]), "r"((a)[2]), "r"((a)[3]),        \
                   "r"(b0), "r"(b1))

#define MMA_FP(d, a, b0, b1)                                                  \
    asm volatile("mma.sync.aligned.m16n8k16.row.col.f32.f16.f16.f32 "         \
                 "{%0,%1,%2,%3}, {%4,%5,%6,%7}, {%8,%9}, {%0,%1,%2,%3};"      \
                 : "+f"((d)[0]), "+f"((d)[1]), "+f"((d)[2]), "+f"((d)[3])     \
                 : "r"((a)[0]), "r"((a)[1]), "r"((a)[2]), "r"((a)[3]),        \
                   "r"(b0), "r"(b1))

#define CP_ASYNC16(s, g) \
    asm volatile("cp.async.cg.shared.global [%0], [%1], 16;" :: "r"(s), "l"(g))
#define CP_COMMIT() asm volatile("cp.async.commit_group;" ::: "memory")
#define CP_WAIT2()  asm volatile("cp.async.wait_group 2;" ::: "memory")
#define CP_WAIT1()  asm volatile("cp.async.wait_group 1;" ::: "memory")
#define CP_WAIT0()  asm volatile("cp.async.wait_group 0;" ::: "memory")

__device__ __forceinline__ unsigned pack_bf16(float lo, float hi) {
    unsigned r;
    asm("cvt.rn.bf16x2.f32 %0, %1, %2;" : "=r"(r) : "f"(hi), "f"(lo));
    return r;
}
__device__ __forceinline__ unsigned pack_res_bf(float lo, float hi, unsigned hp) {
    __nv_bfloat162 h = *reinterpret_cast<__nv_bfloat162*>(&hp);
    return pack_bf16(lo - __bfloat162float(h.x), hi - __bfloat162float(h.y));
}
__device__ __forceinline__ unsigned pack_f16(float lo, float hi) {
    unsigned r;
    asm("cvt.rn.f16x2.f32 %0, %1, %2;" : "=r"(r) : "f"(hi), "f"(lo));
    return r;
}
__device__ __forceinline__ unsigned pack_res_f16(float lo, float hi, unsigned hp) {
    __half2 h = *reinterpret_cast<__half2*>(&hp);
    return pack_f16(lo - __half2float(h.x), hi - __half2float(h.y));
}

// ---------------------------------------------------------------------------
// fp16x2 split conversion: x -> (hi, lo). skipq: skip rows with (row%384)<128.
// ---------------------------------------------------------------------------
__global__ void cvt_split_f16(const float4* __restrict__ in,
                              __half2* __restrict__ hi,
                              __half2* __restrict__ lo, int n4, int skipq)
{
    int i = blockIdx.x * blockDim.x + threadIdx.x;
    if (i >= n4) return;
    if (skipq) {
        int row = i >> 9;                 // 512 float4 per 2048-col row
        if ((row % 384) < 128) return;    // q rows get overwritten by the fold
    }
    float4 v = in[i];
    __half h0 = __float2half(v.x), h1 = __float2half(v.y);
    __half h2 = __float2half(v.z), h3 = __float2half(v.w);
    __half2 a, b;
    a.x = h0; a.y = h1; b.x = h2; b.y = h3;
    hi[i * 2] = a; hi[i * 2 + 1] = b;
    a.x = __float2half(v.x - __half2float(h0));
    a.y = __float2half(v.y - __half2float(h1));
    b.x = __float2half(v.z - __half2float(h2));
    b.y = __float2half(v.w - __half2float(h3));
    lo[i * 2] = a; lo[i * 2 + 1] = b;
}

// Transpose [2048,2048] fp32 -> hi/lo fp16 of the transpose
__global__ void trans_cvt_f16(const float* __restrict__ in,
                              __half* __restrict__ hi,
                              __half* __restrict__ lo)
{
    __shared__ float t[32][33];
    int xi = blockIdx.x * 32 + threadIdx.x;
    int yi = blockIdx.y * 32 + threadIdx.y;
#pragma unroll
    for (int j = 0; j < 32; j += 8)
        t[threadIdx.y + j][threadIdx.x] = in[(size_t)(yi + j) * 2048 + xi];
    __syncthreads();
    int xo = blockIdx.y * 32 + threadIdx.x;
    int yo = blockIdx.x * 32 + threadIdx.y;
#pragma unroll
    for (int j = 0; j < 32; j += 8) {
        float v = t[threadIdx.x][threadIdx.y + j];
        __half h = __float2half(v);
        hi[(size_t)(yo + j) * 2048 + xo] = h;
        lo[(size_t)(yo + j) * 2048 + xo] = __float2half(v - __half2float(h));
    }
}

// rotated bias: bmod[h*384+e] = sum_d S_h[d][e]*b[h*384+d] for e<128, else b
__global__ void bias_rot(const float* __restrict__ S, const float* __restrict__ b,
                         float* __restrict__ bmod)
{
    int e = blockIdx.x * 256 + threadIdx.x;
    if (e >= H3) return;
    int h = e / 384, r = e - h * 384;
    if (r < 128) {
        const float* Sh = S + h * 16384;
        const float* bh = b + h * 384;
        float s = 0.0f;
#pragma unroll 8
        for (int d = 0; d < 128; d++) s += Sh[d * 128 + r] * bh[d];
        bmod[e] = s;
    } else {
        bmod[e] = b[e];
    }
}

// ---------------------------------------------------------------------------
// fp32 SGEMM body (small GEMMs). OM: 0 fp32 out, 1 fp16 hi/lo pair out.
// ---------------------------------------------------------------------------
template <bool TB, int OM>
__device__ __forceinline__ void sgemm_body(
    const float* __restrict__ Ab, int lda,
    const float* __restrict__ Bb, int ldb,
    float* __restrict__ Cf, __half* __restrict__ Coh,
    __half* __restrict__ Col, int ldc, int K,
    float As[8][128], float Bs[8][128])
{
    const int m0 = blockIdx.y * 128;
    const int n0 = blockIdx.x * 128;
    const int tid = threadIdx.x;
    const int tx = tid & 15;
    const int ty = tid >> 4;

    float acc[8][8];
#pragma unroll
    for (int i = 0; i < 8; i++)
#pragma unroll
        for (int j = 0; j < 8; j++) acc[i][j] = 0.0f;

    const int arow = tid >> 1;
    const int ak = (tid & 1) * 4;

    for (int k0 = 0; k0 < K; k0 += 8) {
        float4 av = *(const float4*)(Ab + (long long)(m0 + arow) * lda + k0 + ak);
        As[ak + 0][arow] = av.x;
        As[ak + 1][arow] = av.y;
        As[ak + 2][arow] = av.z;
        As[ak + 3][arow] = av.w;
        if (!TB) {
            const int bk = tid >> 5;
            const int bn = (tid & 31) * 4;
            *(float4*)&Bs[bk][bn] =
                *(const float4*)(Bb + (long long)(k0 + bk) * ldb + n0 + bn);
        } else {
            const int bn = tid >> 1;
            const int bk = (tid & 1) * 4;
            float4 bv = *(const float4*)(Bb + (long long)(n0 + bn) * ldb + k0 + bk);
            Bs[bk + 0][bn] = bv.x;
            Bs[bk + 1][bn] = bv.y;
            Bs[bk + 2][bn] = bv.z;
            Bs[bk + 3][bn] = bv.w;
        }
        __syncthreads();
#pragma unroll
        for (int k = 0; k < 8; k++) {
            float a[8], b[8];
            *(float4*)&a[0] = *(const float4*)&As[k][ty * 8];
            *(float4*)&a[4] = *(const float4*)&As[k][ty * 8 + 4];
            *(float4*)&b[0] = *(const float4*)&Bs[k][tx * 8];
            *(float4*)&b[4] = *(const float4*)&Bs[k][tx * 8 + 4];
#pragma unroll
            for (int i = 0; i < 8; i++)
#pragma unroll
                for (int j = 0; j < 8; j++) acc[i][j] += a[i] * b[j];
        }
        __syncthreads();
    }

#pragma unroll
    for (int i = 0; i < 8; i++) {
        const int row = m0 + ty * 8 + i;
        const long long base = (long long)row * ldc;
#pragma unroll
        for (int j = 0; j < 8; j += 2) {
            const int col = n0 + tx * 8 + j;
            if (OM == 1) {
                unsigned hp = pack_f16(acc[i][j], acc[i][j + 1]);
                *(unsigned*)(Coh + base + col) = hp;
                *(unsigned*)(Col + base + col) = pack_res_f16(acc[i][j], acc[i][j + 1], hp);
            } else {
                *(float2*)(Cf + base + col) = make_float2(acc[i][j], acc[i][j + 1]);
            }
        }
    }
}

// S_h (z<16) and P_h (z>=16) in one launch. grid (1,1,32).
__global__ __launch_bounds__(256) void sgemm_SP(
    const float* __restrict__ Aq, const float* __restrict__ Av,
    float* __restrict__ Sout, float* __restrict__ Pout)
{
    __shared__ float As[8][128];
    __shared__ float Bs[8][128];
    const int z = blockIdx.z;
    const float* A = (z < 16 ? Aq : Av) + (long long)(z & 15) * 16384;
    float* C = (z < 16 ? Sout : Pout) + (long long)(z & 15) * 16384;
    sgemm_body<true, 0>(A, 128, A, 128, C, nullptr, nullptr, 128, 128, As, Bs);
}

// Wq' = S_h @ Wq_h (z<16, fp16 pair out) and W2_h = P_h @ dense_w[h] (z>=16,
// fp32 out) in one launch. grid (16,1,32).
__global__ __launch_bounds__(256) void sgemm_fold(
    const float* __restrict__ S, const float* __restrict__ P,
    const float* __restrict__ qkvw, const float* __restrict__ densew,
    __half* __restrict__ Wqh, __half* __restrict__ Wql, float* __restrict__ W2)
{
    __shared__ float As[8][128];
    __shared__ float Bs[8][128];
    const int z = blockIdx.z;
    if (z < 16) {
        const float* A = S + (long long)z * 16384;
        const float* B = qkvw + (long long)z * 384 * 2048;
        sgemm_body<false, 1>(A, 128, B, 2048, nullptr,
                             Wqh + (long long)z * 384 * 2048,
                             Wql + (long long)z * 384 * 2048, 2048, 128, As, Bs);
    } else {
        const float* A = P + (long long)(z - 16) * 16384;
        const float* B = densew + (long long)(z - 16) * 262144;
        sgemm_body<false, 0>(A, 128, B, 2048, W2 + (long long)(z - 16) * 262144,
                             nullptr, nullptr, 2048, 128, As, Bs);
    }
}

// ---------------------------------------------------------------------------
// fp16x2 GEMM via mma.sync (2 passes: (Ah+Al)@Bh^T). 3-stage cp.async,
// 2 CTAs/SM. BM=BN=128, BK=32, 8 warps (32x64 warp tile).
// OM: 0 = fp32 C (+bias), 1 = fp16 hi/lo pair, 2 = QKV bf16 stripes (+bias).
// SYM: output symmetric (A==B): compute upper triangle, mirror off-diag tiles.
// ---------------------------------------------------------------------------
#define TILE_B 10240
#define STAGE_B (3 * TILE_B)      // Ah | Al | Bh
#define GEMM_SMEM (3 * STAGE_B)   // 92160

template <int OM, bool SYM>
__global__ __launch_bounds__(256, 2)
void mma_gemm(const __half* __restrict__ Ah, const __half* __restrict__ Al,
              const __half* __restrict__ Bh,
              float* __restrict__ C, __half* __restrict__ Coh,
              __half* __restrict__ Col, int ldc,
              const float* __restrict__ bias, int K, int lda, int ldb)
{
    extern __shared__ __align__(16) char smem[];

    if (SYM && blockIdx.x < blockIdx.y) return;   // lower triangle: mirrored

    const int tid = threadIdx.x;
    const int wid = tid >> 5;
    const int lane = tid & 31;
    const int m0 = blockIdx.y * 128;
    const int n0 = blockIdx.x * 128;
    const int wm = (wid & 3) * 32;
    const int wn = (wid >> 2) * 64;

    float acc[2][8][4];
#pragma unroll
    for (int i = 0; i < 2; i++)
#pragma unroll
        for (int j = 0; j < 8; j++)
#pragma unroll
            for (int k = 0; k < 4; k++) acc[i][j][k] = 0.0f;

    const __half* srcs[3] = {Ah, Al, Bh};
    const int lds[3] = {lda, lda, ldb};
    const int r0s[3] = {m0, m0, n0};

    const unsigned smb = smem_u32(smem);

    auto issue_stage = [&](int t, int buf) {
        const int k0 = t * 32;
        const unsigned sb = smb + buf * STAGE_B;
#pragma unroll
        for (int i = 0; i < 6; i++) {
            const int id = i * 256 + tid;
            const int tile = id >> 9;
            const int cid = id & 511;
            const int row = cid >> 2;
            const int c = cid & 3;
            const __half* g =
                srcs[tile] + (size_t)(r0s[tile] + row) * lds[tile] + k0 + c * 8;
            CP_ASYNC16(sb + tile * TILE_B + row * 80 + c * 16, g);
        }
        CP_COMMIT();
    };

    const int T = K >> 5;
    issue_stage(0, 0);
    issue_stage(1, 1);

    const unsigned a_lrow = (lane & 15) * 80 + (lane >> 4) * 16;
    const unsigned b_lrow = ((lane & 7) + ((lane >> 4) << 3)) * 80 + ((lane >> 3) & 1) * 16;

    for (int t = 0; t < T; t++) {
        if (t + 2 < T) { issue_stage(t + 2, (t + 2) % 3); CP_WAIT2(); }
        else if (t + 1 < T) { CP_WAIT1(); }
        else { CP_WAIT0(); }
        __syncthreads();

        const unsigned st = smb + (t % 3) * STAGE_B;
        const unsigned aHb = st + wm * 80 + a_lrow;
        const unsigned aLb = st + TILE_B + wm * 80 + a_lrow;
        const unsigned bHb = st + 2 * TILE_B + wn * 80 + b_lrow;

#pragma unroll
        for (int ks = 0; ks < 2; ks++) {
            unsigned aH[2][4], aL[2][4];
#pragma unroll
            for (int mt = 0; mt < 2; mt++) {
                LDM_X4(aH[mt], aHb + mt * (16 * 80) + ks * 32);
                LDM_X4(aL[mt], aLb + mt * (16 * 80) + ks * 32);
            }
#pragma unroll
            for (int ng = 0; ng < 4; ng++) {
                unsigned bH[4];
                LDM_X4(bH, bHb + ng * (16 * 80) + ks * 32);
#pragma unroll
                for (int mt = 0; mt < 2; mt++) {
                    MMA_FP(acc[mt][2 * ng],     aH[mt], bH[0], bH[1]);
                    MMA_FP(acc[mt][2 * ng + 1], aH[mt], bH[2], bH[3]);
                    MMA_FP(acc[mt][2 * ng],     aL[mt], bH[0], bH[1]);
                    MMA_FP(acc[mt][2 * ng + 1], aL[mt], bH[2], bH[3]);
                }
            }
        }
        __syncthreads();
    }

#pragma unroll
    for (int mt = 0; mt < 2; mt++) {
        const int m = m0 + wm + mt * 16 + (lane >> 2);
#pragma unroll
        for (int nt = 0; nt < 8; nt++) {
            const int n = n0 + wn + nt * 8 + (lane & 3) * 2;
            float bx = 0.0f, by = 0.0f;
            if (OM != 1 && bias) { bx = bias[n]; by = bias[n + 1]; }
            float v00 = acc[mt][nt][0] + bx, v01 = acc[mt][nt][1] + by;
            float v10 = acc[mt][nt][2] + bx, v11 = acc[mt][nt][3] + by;
            if (OM == 0) {
                *(float2*)(C + (size_t)m * ldc + n) = make_float2(v00, v01);
                *(float2*)(C + (size_t)(m + 8) * ldc + n) = make_float2(v10, v11);
            } else if (OM == 1) {
                unsigned hp = pack_f16(v00, v01);
                *(unsigned*)(Coh + (size_t)m * ldc + n) = hp;
                *(unsigned*)(Col + (size_t)m * ldc + n) = pack_res_f16(v00, v01, hp);
                hp = pack_f16(v10, v11);
                *(unsigned*)(Coh + (size_t)(m + 8) * ldc + n) = hp;
                *(unsigned*)(Col + (size_t)(m + 8) * ldc + n) = pack_res_f16(v10, v11, hp);
            } else {
                const int h = n / 384;
                const int r = n - h * 384;
                const int stp = r >> 7;
                const int d = r & 127;
                __nv_bfloat16* Dh = (stp == 0) ? g_Qh : ((stp == 1) ? g_Kh : g_Vh);
                __nv_bfloat16* Dl = (stp == 0) ? g_Ql : ((stp == 1) ? g_Kl : g_Vl);
                size_t o = ((size_t)h * 2048 + m) * 128 + d;
                unsigned hp = pack_bf16(v00, v01);
                *(unsigned*)(Dh + o) = hp;
                *(unsigned*)(Dl + o) = pack_res_bf(v00, v01, hp);
                o += 8 * 128;
                hp = pack_bf16(v10, v11);
                *(unsigned*)(Dh + o) = hp;
                *(unsigned*)(Dl + o) = pack_res_bf(v10, v11, hp);
            }
        }
    }

    // symmetric mirror: stage transposed tile in smem, write to (n0, m0)
    if (SYM && OM == 1 && blockIdx.x != blockIdx.y) {
        __syncthreads();
        __half* sh = (__half*)smem;              // [128][136] hi
        __half* sl = sh + 128 * 136;             // [128][136] lo
#pragma unroll
        for (int mt = 0; mt < 2; mt++) {
            const int ml = wm + mt * 16 + (lane >> 2);
#pragma unroll
            for (int nt = 0; nt < 8; nt++) {
                const int nl = wn + nt * 8 + (lane & 3) * 2;
                float v00 = acc[mt][nt][0], v01 = acc[mt][nt][1];
                float v10 = acc[mt][nt][2], v11 = acc[mt][nt][3];
                __half h;
                h = __float2half(v00); sh[nl * 136 + ml] = h;
                sl[nl * 136 + ml] = __float2half(v00 - __half2float(h));
                h = __float2half(v01); sh[(nl + 1) * 136 + ml] = h;
                sl[(nl + 1) * 136 + ml] = __float2half(v01 - __half2float(h));
                h = __float2half(v10); sh[nl * 136 + ml + 8] = h;
                sl[nl * 136 + ml + 8] = __float2half(v10 - __half2float(h));
                h = __float2half(v11); sh[(nl + 1) * 136 + ml + 8] = h;
                sl[(nl + 1) * 136 + ml + 8] = __float2half(v11 - __half2float(h));
            }
        }
        __syncthreads();
        for (int e = tid; e < 128 * 16; e += 256) {
            const int r = e >> 4, c4 = e & 15;
            uint4 v = *(uint4*)(sh + r * 136 + c4 * 8);
            *(uint4*)(Coh + (size_t)(n0 + r) * ldc + m0 + c4 * 8) = v;
            v = *(uint4*)(sl + r * 136 + c4 * 8);
            *(uint4*)(Col + (size_t)(n0 + r) * ldc + m0 + c4 * 8) = v;
        }
    }
}

// ---------------------------------------------------------------------------
// Tensor-core causal flash attention (bf16x3). 128 Q rows x head per block.
// Q/K/V bf16 hi/lo [h][t][d]; V loaded via ldmatrix.trans (no pre-transpose).
// Output: ctx as fp16 hi/lo [t][2048].
// ---------------------------------------------------------------------------
#define AQ_PITCH 272
#define SQH_B (128 * AQ_PITCH)    // 34816
#define SKH_B (64 * AQ_PITCH)     // 17408
#define KV_STAGE (4 * SKH_B)      // Khi | Klo | Vhi | Vlo = 69632
#define ATTN2_SMEM (2 * SQH_B + 2 * KV_STAGE)   // 208896

__global__ __launch_bounds__(256, 1) void attn_mma(
    const __nv_bfloat16* __restrict__ Qh_, const __nv_bfloat16* __restrict__ Ql_,
    const __nv_bfloat16* __restrict__ Kh_, const __nv_bfloat16* __restrict__ Kl_,
    const __nv_bfloat16* __restrict__ Vh_, const __nv_bfloat16* __restrict__ Vl_,
    __half* __restrict__ Ch_, __half* __restrict__ Cl_)
{
    extern __shared__ __align__(16) char sm[];
    const int h = blockIdx.y;
    const int rb = (int)gridDim.x - 1 - (int)blockIdx.x;
    const int r0 = rb * 128;
    const int tid = threadIdx.x;
    const int wid = tid >> 5;
    const int lane = tid & 31;

    const unsigned sQh = smem_u32(sm);
    const unsigned sQl = sQh + SQH_B;
    const unsigned sKV0 = sQl + SQH_B;

    {
        const __nv_bfloat16* gq = Qh_ + ((size_t)h * 2048 + r0) * 128;
        const __nv_bfloat16* gql = Ql_ + ((size_t)h * 2048 + r0) * 128;
#pragma unroll
        for (int it = 0; it < 8; it++) {
            int id = it * 256 + tid;
            int row = id >> 4, c = id & 15;
            CP_ASYNC16(sQh + row * AQ_PITCH + c * 16, gq + (size_t)row * 128 + c * 8);
            CP_ASYNC16(sQl + row * AQ_PITCH + c * 16, gql + (size_t)row * 128 + c * 8);
        }
    }
    const __nv_bfloat16* gK = Kh_ + (size_t)h * 2048 * 128;
    const __nv_bfloat16* gKl = Kl_ + (size_t)h * 2048 * 128;
    const __nv_bfloat16* gV = Vh_ + (size_t)h * 2048 * 128;
    const __nv_bfloat16* gVl = Vl_ + (size_t)h * 2048 * 128;

    auto issue_kv = [&](int t, int buf) {
        const int t0 = t * 64;
        const unsigned sb = sKV0 + buf * KV_STAGE;
#pragma unroll
        for (int it = 0; it < 4; it++) {
            int id = it * 256 + tid;
            int row = id >> 4, c = id & 15;
            size_t go = (size_t)(t0 + row) * 128 + c * 8;
            unsigned so = row * AQ_PITCH + c * 16;
            CP_ASYNC16(sb + so, gK + go);
            CP_ASYNC16(sb + SKH_B + so, gKl + go);
            CP_ASYNC16(sb + 2 * SKH_B + so, gV + go);
            CP_ASYNC16(sb + 3 * SKH_B + so, gVl + go);
        }
    };

    issue_kv(0, 0);
    CP_COMMIT();

    float sacc[8][4];
    float Oacc[16][4];
#pragma unroll
    for (int i = 0; i < 16; i++)
#pragma unroll
        for (int j = 0; j < 4; j++) Oacc[i][j] = 0.0f;
    float m1 = -1e30f, m2 = -1e30f, l1 = 0.0f, l2 = 0.0f;

    const int gr1 = r0 + wid * 16 + (lane >> 2);
    const int gr2 = gr1 + 8;
    const float scale = 0.08838834764831845f;

    const unsigned a_off = (lane & 15) * AQ_PITCH + (lane >> 4) * 16;
    const unsigned kb_off = ((lane & 7) + ((lane >> 4) << 3)) * AQ_PITCH + ((lane >> 3) & 1) * 16;
    const unsigned aQh_b = sQh + wid * 16 * AQ_PITCH + a_off;
    const unsigned aQl_b = sQl + wid * 16 * AQ_PITCH + a_off;

    const int T = 2 * rb + 2;
    for (int t = 0; t < T; t++) {
        if (t + 1 < T) { issue_kv(t + 1, (t + 1) & 1); CP_COMMIT(); CP_WAIT1(); }
        else { CP_WAIT0(); }
        __syncthreads();

        const unsigned sb = sKV0 + (t & 1) * KV_STAGE;
        const unsigned kh_b = sb + kb_off;
        const unsigned kl_b = sb + SKH_B + kb_off;

#pragma unroll
        for (int i = 0; i < 8; i++)
#pragma unroll
            for (int j = 0; j < 4; j++) sacc[i][j] = 0.0f;

#pragma unroll
        for (int kd = 0; kd < 8; kd++) {
            unsigned qh[4], ql[4];
            LDM_X4(qh, aQh_b + kd * 32);
            LDM_X4(ql, aQl_b + kd * 32);
#pragma unroll
            for (int ng = 0; ng < 4; ng++) {
                unsigned bh[4], bl[4];
                LDM_X4(bh, kh_b + ng * (16 * AQ_PITCH) + kd * 32);
                LDM_X4(bl, kl_b + ng * (16 * AQ_PITCH) + kd * 32);
                MMA_BF(sacc[2 * ng],     qh, bh[0], bh[1]);
                MMA_BF(sacc[2 * ng + 1], qh, bh[2], bh[3]);
                MMA_BF(sacc[2 * ng],     qh, bl[0], bl[1]);
                MMA_BF(sacc[2 * ng + 1], qh, bl[2], bl[3]);
                MMA_BF(sacc[2 * ng],     ql, bh[0], bh[1]);
                MMA_BF(sacc[2 * ng + 1], ql, bh[2], bh[3]);
            }
        }

        const int c0 = t * 64;
#pragma unroll
        for (int nt = 0; nt < 8; nt++)
#pragma unroll
            for (int j = 0; j < 4; j++) sacc[nt][j] *= scale;

        if (t >= 2 * rb) {
#pragma unroll
            for (int nt = 0; nt < 8; nt++) {
                int col = c0 + nt * 8 + (lane & 3) * 2;
                if (col     > gr1) sacc[nt][0] = -1e30f;
                if (col + 1 > gr1) sacc[nt][1] = -1e30f;
                if (col     > gr2) sacc[nt][2] = -1e30f;
                if (col + 1 > gr2) sacc[nt][3] = -1e30f;
            }
        }

        float mx1 = -1e30f, mx2 = -1e30f;
#pragma unroll
        for (int nt = 0; nt < 8; nt++) {
            mx1 = fmaxf(mx1, fmaxf(sacc[nt][0], sacc[nt][1]));
            mx2 = fmaxf(mx2, fmaxf(sacc[nt][2], sacc[nt][3]));
        }
        mx1 = fmaxf(mx1, __shfl_xor_sync(0xffffffffu, mx1, 1));
        mx1 = fmaxf(mx1, __shfl_xor_sync(0xffffffffu, mx1, 2));
        mx2 = fmaxf(mx2, __shfl_xor_sync(0xffffffffu, mx2, 1));
        mx2 = fmaxf(mx2, __shfl_xor_sync(0xffffffffu, mx2, 2));
        const float mn1 = fmaxf(m1, mx1), mn2 = fmaxf(m2, mx2);
        const float corr1 = __expf(m1 - mn1), corr2 = __expf(m2 - mn2);
        m1 = mn1; m2 = mn2;
        float rs1 = 0.0f, rs2 = 0.0f;
#pragma unroll
        for (int nt = 0; nt < 8; nt++) {
            sacc[nt][0] = __expf(sacc[nt][0] - m1); rs1 += sacc[nt][0];
            sacc[nt][1] = __expf(sacc[nt][1] - m1); rs1 += sacc[nt][1];
            sacc[nt][2] = __expf(sacc[nt][2] - m2); rs2 += sacc[nt][2];
            sacc[nt][3] = __expf(sacc[nt][3] - m2); rs2 += sacc[nt][3];
        }
        rs1 += __shfl_xor_sync(0xffffffffu, rs1, 1);
        rs1 += __shfl_xor_sync(0xffffffffu, rs1, 2);
        rs2 += __shfl_xor_sync(0xffffffffu, rs2, 1);
        rs2 += __shfl_xor_sync(0xffffffffu, rs2, 2);
        l1 = l1 * corr1 + rs1;
        l2 = l2 * corr2 + rs2;
#pragma unroll
        for (int nt = 0; nt < 16; nt++) {
            Oacc[nt][0] *= corr1; Oacc[nt][1] *= corr1;
            Oacc[nt][2] *= corr2; Oacc[nt][3] *= corr2;
        }

        // O += P V: V row-major [t][d], B-fragments via ldmatrix.trans
        const unsigned vh_b = sb + 2 * SKH_B + a_off;
        const unsigned vl_b = sb + 3 * SKH_B + a_off;
#pragma unroll
        for (int kt = 0; kt < 4; kt++) {
            unsigned ph[4], pl[4];
            ph[0] = pack_bf16(sacc[2 * kt][0], sacc[2 * kt][1]);
            ph[1] = pack_bf16(sacc[2 * kt][2], sacc[2 * kt][3]);
            ph[2] = pack_bf16(sacc[2 * kt + 1][0], sacc[2 * kt + 1][1]);
            ph[3] = pack_bf16(sacc[2 * kt + 1][2], sacc[2 * kt + 1][3]);
            pl[0] = pack_res_bf(sacc[2 * kt][0], sacc[2 * kt][1], ph[0]);
            pl[1] = pack_res_bf(sacc[2 * kt][2], sacc[2 * kt][3], ph[1]);
            pl[2] = pack_res_bf(sacc[2 * kt + 1][0], sacc[2 * kt + 1][1], ph[2]);
            pl[3] = pack_res_bf(sacc[2 * kt + 1][2], sacc[2 * kt + 1][3], ph[3]);
#pragma unroll
            for (int ng = 0; ng < 8; ng++) {
                unsigned vh[4], vl[4];
                LDM_X4_T(vh, vh_b + kt * (16 * AQ_PITCH) + ng * 32);
                LDM_X4_T(vl, vl_b + kt * (16 * AQ_PITCH) + ng * 32);
                MMA_BF(Oacc[2 * ng],     ph, vh[0], vh[1]);
                MMA_BF(Oacc[2 * ng + 1], ph, vh[2], vh[3]);
                MMA_BF(Oacc[2 * ng],     ph, vl[0], vl[1]);
                MMA_BF(Oacc[2 * ng + 1], ph, vl[2], vl[3]);
                MMA_BF(Oacc[2 * ng],     pl, vh[0], vh[1]);
                MMA_BF(Oacc[2 * ng + 1], pl, vh[2], vh[3]);
            }
        }
        __syncthreads();
    }

    const float inv1 = 1.0f / l1, inv2 = 1.0f / l2;
#pragma unroll
    for (int nt = 0; nt < 16; nt++) {
        const int colb = h * 128 + nt * 8 + (lane & 3) * 2;
        float o0 = Oacc[nt][0] * inv1, o1 = Oacc[nt][1] * inv1;
        unsigned hp = pack_f16(o0, o1);
        *(unsigned*)(Ch_ + (size_t)gr1 * 2048 + colb) = hp;
        *(unsigned*)(Cl_ + (size_t)gr1 * 2048 + colb) = pack_res_f16(o0, o1, hp);
        o0 = Oacc[nt][2] * inv2; o1 = Oacc[nt][3] * inv2;
        hp = pack_f16(o0, o1);
        *(unsigned*)(Ch_ + (size_t)gr2 * 2048 + colb) = hp;
        *(unsigned*)(Cl_ + (size_t)gr2 * 2048 + colb) = pack_res_f16(o0, o1, hp);
    }
}

// ---------------------------------------------------------------------------
extern "C" void kernel_launch(void* const* d_in, const int* in_sizes, int n_in,
                              void* d_out, int out_size)
{
    (void)in_sizes; (void)n_in; (void)out_size;
    const float* hidden  = (const float*)d_in[0];
    const float* qkv_w   = (const float*)d_in[2];
    const float* qkv_b   = (const float*)d_in[3];
    const float* svd_tok = (const float*)d_in[4];
    const float* svd_qk  = (const float*)d_in[5];
    const float* svd_vl  = (const float*)d_in[6];
    const float* dense_w = (const float*)d_in[7];
    const float* dense_b = (const float*)d_in[8];
    float* out = (float*)d_out;

    float *pS, *pP, *pW2, *pbmod;
    cudaGetSymbolAddress((void**)&pS, g_S);
    cudaGetSymbolAddress((void**)&pP, g_P);
    cudaGetSymbolAddress((void**)&pW2, g_W2);
    cudaGetSymbolAddress((void**)&pbmod, g_bmod);

    __half *pHh, *pHl, *pRh, *pRl, *pMh, *pMl, *pX2h, *pX2l;
    __half *pWqh, *pWql, *pCh, *pCl, *pW2Th, *pW2Tl;
    cudaGetSymbolAddress((void**)&pHh, g_Hh);   cudaGetSymbolAddress((void**)&pHl, g_Hl);
    cudaGetSymbolAddress((void**)&pRh, g_Rh);   cudaGetSymbolAddress((void**)&pRl, g_Rl);
    cudaGetSymbolAddress((void**)&pMh, g_Mh);   cudaGetSymbolAddress((void**)&pMl, g_Ml);
    cudaGetSymbolAddress((void**)&pX2h, g_X2h); cudaGetSymbolAddress((void**)&pX2l, g_X2l);
    cudaGetSymbolAddress((void**)&pWqh, g_Wqh); cudaGetSymbolAddress((void**)&pWql, g_Wql);
    cudaGetSymbolAddress((void**)&pCh, g_Ch);   cudaGetSymbolAddress((void**)&pCl, g_Cl);
    cudaGetSymbolAddress((void**)&pW2Th, g_W2Th); cudaGetSymbolAddress((void**)&pW2Tl, g_W2Tl);

    __nv_bfloat16 *pQh, *pQl, *pKh, *pKl, *pVh, *pVl;
    cudaGetSymbolAddress((void**)&pQh, g_Qh);   cudaGetSymbolAddress((void**)&pQl, g_Ql);
    cudaGetSymbolAddress((void**)&pKh, g_Kh);   cudaGetSymbolAddress((void**)&pKl, g_Kl);
    cudaGetSymbolAddress((void**)&pVh, g_Vh);   cudaGetSymbolAddress((void**)&pVl, g_Vl);

    cudaFuncSetAttribute((const void*)mma_gemm<0, false>, cudaFuncAttributeMaxDynamicSharedMemorySize, GEMM_SMEM);
    cudaFuncSetAttribute((const void*)mma_gemm<1, false>, cudaFuncAttributeMaxDynamicSharedMemorySize, GEMM_SMEM);
    cudaFuncSetAttribute((const void*)mma_gemm<1, true>,  cudaFuncAttributeMaxDynamicSharedMemorySize, GEMM_SMEM);
    cudaFuncSetAttribute((const void*)mma_gemm<2, false>, cudaFuncAttributeMaxDynamicSharedMemorySize, GEMM_SMEM);
    cudaFuncSetAttribute((const void*)attn_mma, cudaFuncAttributeMaxDynamicSharedMemorySize, ATTN2_SMEM);

    const dim3 blk(256);
    const int N4_2048 = (2048 * 2048) / 4;
    const int N4_W = (6144 * 2048) / 4;

    // input conversions (fp16 hi/lo); qkv_w skips q-rows (fold overwrites them)
    cvt_split_f16<<<N4_2048 / 256, 256>>>((const float4*)hidden, (__half2*)pHh, (__half2*)pHl, N4_2048, 0);
    cvt_split_f16<<<N4_2048 / 256, 256>>>((const float4*)svd_tok, (__half2*)pRh, (__half2*)pRl, N4_2048, 0);
    cvt_split_f16<<<N4_W / 256, 256>>>((const float4*)qkv_w, (__half2*)pWqh, (__half2*)pWql, N4_W, 1);

    // S_h and P_h in one launch
    sgemm_SP<<<dim3(1, 1, 32), blk>>>(svd_qk, svd_vl, pS, pP);
    // Wq' = S@Wq (fp16 pairs) and W2 = P@dense_w (fp32) in one launch
    sgemm_fold<<<dim3(16, 1, 32), blk>>>(pS, pP, qkv_w, dense_w, pWqh, pWql, pW2);
    bias_rot<<<24, 256>>>(pS, qkv_b, pbmod);
    trans_cvt_f16<<<dim3(64, 64), dim3(32, 8)>>>(pW2, pW2Th, pW2Tl);

    // 1) M = R @ R^T -> fp16 hi/lo (symmetric: upper triangle + mirror)
    mma_gemm<1, true><<<dim3(16, 16), blk, GEMM_SMEM>>>(pRh, pRl, pRh,
        nullptr, pMh, pMl, 2048, nullptr, 2048, 2048, 2048);
    // 2) X2 = hidden @ M^T (M symmetric) -> fp16 hi/lo
    mma_gemm<1, false><<<dim3(16, 16), blk, GEMM_SMEM>>>(pHh, pHl, pMh,
        nullptr, pX2h, pX2l, 2048, nullptr, 2048, 2048, 2048);
    // 3) [q'|k|v] = X2 @ Wmod^T + bmod -> bf16 Q/K/V stripes [h][t][d]
    mma_gemm<2, false><<<dim3(48, 16), blk, GEMM_SMEM>>>(pX2h, pX2l, pWqh,
        nullptr, nullptr, nullptr, 0, pbmod, 2048, 2048, 2048);

    // attention -> ctx fp16 hi/lo (V loaded via ldmatrix.trans, no pre-transpose)
    attn_mma<<<dim3(16, 16), blk, ATTN2_SMEM>>>(pQh, pQl, pKh, pKl, pVh, pVl, pCh, pCl);

    // out = ctx @ W2 + dense_b (fp32 out)
    mma_gemm<0, false><<<dim3(16, 16), blk, GEMM_SMEM>>>(pCh, pCl, pW2Th,
        out, nullptr, nullptr, 2048, dense_b, 2048, 2048, 2048);
}

// round 13
// speedup vs baseline: 3.8580x; 1.1061x over previous
#include <cuda_runtime.h>
#include <cuda_bf16.h>
#include <cuda_fp16.h>

#define SQN 2048
#define HIDN 2048
#define NHD 16
#define HDIM 128
#define H3 6144

// ---------------- fp32 scratch ----------------
__device__ float g_S[NHD * HDIM * HDIM];
__device__ float g_P[NHD * HDIM * HDIM];
__device__ float g_W2[HIDN * HIDN];
__device__ float g_bmod[H3];

// ---------------- fp16 hi/lo scratch (GEMM operands) ----------------
__device__ __half g_Hh[SQN * HIDN],  g_Hl[SQN * HIDN];
__device__ __half g_Rh[HIDN * HIDN], g_Rl[HIDN * HIDN];
__device__ __half g_Mh[HIDN * HIDN], g_Ml[HIDN * HIDN];
__device__ __half g_X2h[SQN * HIDN], g_X2l[SQN * HIDN];
__device__ __half g_Wqh[H3 * HIDN],  g_Wql[H3 * HIDN];
__device__ __half g_Ch[SQN * HIDN],  g_Cl[SQN * HIDN];
__device__ __half g_W2Th[HIDN * HIDN], g_W2Tl[HIDN * HIDN];

// ---------------- bf16 hi/lo scratch (attention operands) ----------------
__device__ __nv_bfloat16 g_Qh[NHD * SQN * HDIM], g_Ql[NHD * SQN * HDIM];
__device__ __nv_bfloat16 g_Kh[NHD * SQN * HDIM], g_Kl[NHD * SQN * HDIM];
__device__ __nv_bfloat16 g_Vh[NHD * SQN * HDIM], g_Vl[NHD * SQN * HDIM];

__device__ __forceinline__ unsigned smem_u32(const void* p) {
    unsigned a;
    asm("{ .reg .u64 t; cvta.to.shared.u64 t, %1; cvt.u32.u64 %0, t; }"
        : "=r"(a) : "l"(p));
    return a;
}

#define LDM_X4(r, a)                                                          \
    asm volatile("ldmatrix.sync.aligned.m8n8.x4.shared.b16 {%0,%1,%2,%3}, [%4];" \
                 : "=r"((r)[0]), "=r"((r)[1]), "=r"((r)[2]), "=r"((r)[3])     \
                 : "r"(a))

#define LDM_X4_T(r, a)                                                        \
    asm volatile("ldmatrix.sync.aligned.m8n8.x4.trans.shared.b16 {%0,%1,%2,%3}, [%4];" \
                 : "=r"((r)[0]), "=r"((r)[1]), "=r"((r)[2]), "=r"((r)[3])     \
                 : "r"(a))

#define MMA_BF(d, a, b0, b1)                                                  \
    asm volatile("mma.sync.aligned.m16n8k16.row.col.f32.bf16.bf16.f32 "       \
                 "{%0,%1,%2,%3}, {%4,%5,%6,%7}, {%8,%9}, {%0,%1,%2,%3};"      \
                 : "+f"((d)[0]), "+f"((d)[1]), "+f"((d)[2]), "+f"((d)[3])     \
                 : "r"((a)[0]), "r"((a)[1]), "r"((a)[2]), "r"((a)[3]),        \
                   "r"(b0), "r"(b1))

#define MMA_FP(d, a, b0, b1)                                                  \
    asm volatile("mma.sync.aligned.m16n8k16.row.col.f32.f16.f16.f32 "         \
                 "{%0,%1,%2,%3}, {%4,%5,%6,%7}, {%8,%9}, {%0,%1,%2,%3};"      \
                 : "+f"((d)[0]), "+f"((d)[1]), "+f"((d)[2]), "+f"((d)[3])     \
                 : "r"((a)[0]), "r"((a)[1]), "r"((a)[2]), "r"((a)[3]),        \
                   "r"(b0), "r"(b1))

#define CP_ASYNC16(s, g) \
    asm volatile("cp.async.cg.shared.global [%0], [%1], 16;" :: "r"(s), "l"(g))
#define CP_COMMIT() asm volatile("cp.async.commit_group;" ::: "memory")
#define CP_WAIT2()  asm volatile("cp.async.wait_group 2;" ::: "memory")
#define CP_WAIT1()  asm volatile("cp.async.wait_group 1;" ::: "memory")
#define CP_WAIT0()  asm volatile("cp.async.wait_group 0;" ::: "memory")

__device__ __forceinline__ unsigned pack_bf16(float lo, float hi) {
    unsigned r;
    asm("cvt.rn.bf16x2.f32 %0, %1, %2;" : "=r"(r) : "f"(hi), "f"(lo));
    return r;
}
__device__ __forceinline__ unsigned pack_res_bf(float lo, float hi, unsigned hp) {
    __nv_bfloat162 h = *reinterpret_cast<__nv_bfloat162*>(&hp);
    return pack_bf16(lo - __bfloat162float(h.x), hi - __bfloat162float(h.y));
}
__device__ __forceinline__ unsigned pack_f16(float lo, float hi) {
    unsigned r;
    asm("cvt.rn.f16x2.f32 %0, %1, %2;" : "=r"(r) : "f"(hi), "f"(lo));
    return r;
}
__device__ __forceinline__ unsigned pack_res_f16(float lo, float hi, unsigned hp) {
    __half2 h = *reinterpret_cast<__half2*>(&hp);
    return pack_f16(lo - __half2float(h.x), hi - __half2float(h.y));
}

// ---------------------------------------------------------------------------
// fp16x2 split conversion: x -> (hi, lo). skipq: skip rows with (row%384)<128.
// ---------------------------------------------------------------------------
__global__ void cvt_split_f16(const float4* __restrict__ in,
                              __half2* __restrict__ hi,
                              __half2* __restrict__ lo, int n4, int skipq)
{
    int i = blockIdx.x * blockDim.x + threadIdx.x;
    if (i >= n4) return;
    if (skipq) {
        int row = i >> 9;
        if ((row % 384) < 128) return;
    }
    float4 v = in[i];
    __half h0 = __float2half(v.x), h1 = __float2half(v.y);
    __half h2 = __float2half(v.z), h3 = __float2half(v.w);
    __half2 a, b;
    a.x = h0; a.y = h1; b.x = h2; b.y = h3;
    hi[i * 2] = a; hi[i * 2 + 1] = b;
    a.x = __float2half(v.x - __half2float(h0));
    a.y = __float2half(v.y - __half2float(h1));
    b.x = __float2half(v.z - __half2float(h2));
    b.y = __float2half(v.w - __half2float(h3));
    lo[i * 2] = a; lo[i * 2 + 1] = b;
}

// Transpose [2048,2048] fp32 -> hi/lo fp16 of the transpose
__global__ void trans_cvt_f16(const float* __restrict__ in,
                              __half* __restrict__ hi,
                              __half* __restrict__ lo)
{
    __shared__ float t[32][33];
    int xi = blockIdx.x * 32 + threadIdx.x;
    int yi = blockIdx.y * 32 + threadIdx.y;
#pragma unroll
    for (int j = 0; j < 32; j += 8)
        t[threadIdx.y + j][threadIdx.x] = in[(size_t)(yi + j) * 2048 + xi];
    __syncthreads();
    int xo = blockIdx.y * 32 + threadIdx.x;
    int yo = blockIdx.x * 32 + threadIdx.y;
#pragma unroll
    for (int j = 0; j < 32; j += 8) {
        float v = t[threadIdx.x][threadIdx.y + j];
        __half h = __float2half(v);
        hi[(size_t)(yo + j) * 2048 + xo] = h;
        lo[(size_t)(yo + j) * 2048 + xo] = __float2half(v - __half2float(h));
    }
}

// rotated bias: bmod[h*384+e] = sum_d S_h[d][e]*b[h*384+d] for e<128, else b
__global__ void bias_rot(const float* __restrict__ S, const float* __restrict__ b,
                         float* __restrict__ bmod)
{
    int e = blockIdx.x * 256 + threadIdx.x;
    if (e >= H3) return;
    int h = e / 384, r = e - h * 384;
    if (r < 128) {
        const float* Sh = S + h * 16384;
        const float* bh = b + h * 384;
        float s = 0.0f;
#pragma unroll 8
        for (int d = 0; d < 128; d++) s += Sh[d * 128 + r] * bh[d];
        bmod[e] = s;
    } else {
        bmod[e] = b[e];
    }
}

// ---------------------------------------------------------------------------
// fp32 SGEMM body (small GEMMs). OM: 0 fp32 out, 1 fp16 hi/lo pair out.
// ---------------------------------------------------------------------------
template <bool TB, int OM>
__device__ __forceinline__ void sgemm_body(
    const float* __restrict__ Ab, int lda,
    const float* __restrict__ Bb, int ldb,
    float* __restrict__ Cf, __half* __restrict__ Coh,
    __half* __restrict__ Col, int ldc, int K,
    float As[8][128], float Bs[8][128])
{
    const int m0 = blockIdx.y * 128;
    const int n0 = blockIdx.x * 128;
    const int tid = threadIdx.x;
    const int tx = tid & 15;
    const int ty = tid >> 4;

    float acc[8][8];
#pragma unroll
    for (int i = 0; i < 8; i++)
#pragma unroll
        for (int j = 0; j < 8; j++) acc[i][j] = 0.0f;

    const int arow = tid >> 1;
    const int ak = (tid & 1) * 4;

    for (int k0 = 0; k0 < K; k0 += 8) {
        float4 av = *(const float4*)(Ab + (long long)(m0 + arow) * lda + k0 + ak);
        As[ak + 0][arow] = av.x;
        As[ak + 1][arow] = av.y;
        As[ak + 2][arow] = av.z;
        As[ak + 3][arow] = av.w;
        if (!TB) {
            const int bk = tid >> 5;
            const int bn = (tid & 31) * 4;
            *(float4*)&Bs[bk][bn] =
                *(const float4*)(Bb + (long long)(k0 + bk) * ldb + n0 + bn);
        } else {
            const int bn = tid >> 1;
            const int bk = (tid & 1) * 4;
            float4 bv = *(const float4*)(Bb + (long long)(n0 + bn) * ldb + k0 + bk);
            Bs[bk + 0][bn] = bv.x;
            Bs[bk + 1][bn] = bv.y;
            Bs[bk + 2][bn] = bv.z;
            Bs[bk + 3][bn] = bv.w;
        }
        __syncthreads();
#pragma unroll
        for (int k = 0; k < 8; k++) {
            float a[8], b[8];
            *(float4*)&a[0] = *(const float4*)&As[k][ty * 8];
            *(float4*)&a[4] = *(const float4*)&As[k][ty * 8 + 4];
            *(float4*)&b[0] = *(const float4*)&Bs[k][tx * 8];
            *(float4*)&b[4] = *(const float4*)&Bs[k][tx * 8 + 4];
#pragma unroll
            for (int i = 0; i < 8; i++)
#pragma unroll
                for (int j = 0; j < 8; j++) acc[i][j] += a[i] * b[j];
        }
        __syncthreads();
    }

#pragma unroll
    for (int i = 0; i < 8; i++) {
        const int row = m0 + ty * 8 + i;
        const long long base = (long long)row * ldc;
#pragma unroll
        for (int j = 0; j < 8; j += 2) {
            const int col = n0 + tx * 8 + j;
            if (OM == 1) {
                unsigned hp = pack_f16(acc[i][j], acc[i][j + 1]);
                *(unsigned*)(Coh + base + col) = hp;
                *(unsigned*)(Col + base + col) = pack_res_f16(acc[i][j], acc[i][j + 1], hp);
            } else {
                *(float2*)(Cf + base + col) = make_float2(acc[i][j], acc[i][j + 1]);
            }
        }
    }
}

// S_h (z<16) and P_h (z>=16) in one launch. grid (1,1,32).
__global__ __launch_bounds__(256) void sgemm_SP(
    const float* __restrict__ Aq, const float* __restrict__ Av,
    float* __restrict__ Sout, float* __restrict__ Pout)
{
    __shared__ float As[8][128];
    __shared__ float Bs[8][128];
    const int z = blockIdx.z;
    const float* A = (z < 16 ? Aq : Av) + (long long)(z & 15) * 16384;
    float* C = (z < 16 ? Sout : Pout) + (long long)(z & 15) * 16384;
    sgemm_body<true, 0>(A, 128, A, 128, C, nullptr, nullptr, 128, 128, As, Bs);
}

// Wq' = S_h @ Wq_h (z<16, fp16 pair out) and W2_h = P_h @ dense_w[h] (z>=16,
// fp32 out) in one launch. grid (16,1,32).
__global__ __launch_bounds__(256) void sgemm_fold(
    const float* __restrict__ S, const float* __restrict__ P,
    const float* __restrict__ qkvw, const float* __restrict__ densew,
    __half* __restrict__ Wqh, __half* __restrict__ Wql, float* __restrict__ W2)
{
    __shared__ float As[8][128];
    __shared__ float Bs[8][128];
    const int z = blockIdx.z;
    if (z < 16) {
        const float* A = S + (long long)z * 16384;
        const float* B = qkvw + (long long)z * 384 * 2048;
        sgemm_body<false, 1>(A, 128, B, 2048, nullptr,
                             Wqh + (long long)z * 384 * 2048,
                             Wql + (long long)z * 384 * 2048, 2048, 128, As, Bs);
    } else {
        const float* A = P + (long long)(z - 16) * 16384;
        const float* B = densew + (long long)(z - 16) * 262144;
        sgemm_body<false, 0>(A, 128, B, 2048, W2 + (long long)(z - 16) * 262144,
                             nullptr, nullptr, 2048, 128, As, Bs);
    }
}

// ---------------------------------------------------------------------------
// fp16x2 GEMM via mma.sync (2 passes: (Ah+Al)@Bh^T). 3-stage cp.async,
// 2 CTAs/SM. BM=BN=128, BK=32, 8 warps (32x64 warp tile).
// OM: 0 = fp32 C (+bias), 1 = fp16 hi/lo pair, 2 = QKV bf16 stripes (+bias).
// SYM: output symmetric (A==B): compute upper triangle, mirror off-diag tiles.
// ---------------------------------------------------------------------------
#define TILE_B 10240
#define STAGE_B (3 * TILE_B)      // Ah | Al | Bh
#define GEMM_SMEM (3 * STAGE_B)   // 92160

template <int OM, bool SYM>
__global__ __launch_bounds__(256, 2)
void mma_gemm(const __half* __restrict__ Ah, const __half* __restrict__ Al,
              const __half* __restrict__ Bh,
              float* __restrict__ C, __half* __restrict__ Coh,
              __half* __restrict__ Col, int ldc,
              const float* __restrict__ bias, int K, int lda, int ldb)
{
    extern __shared__ __align__(16) char smem[];

    if (SYM && blockIdx.x < blockIdx.y) return;

    const int tid = threadIdx.x;
    const int wid = tid >> 5;
    const int lane = tid & 31;
    const int m0 = blockIdx.y * 128;
    const int n0 = blockIdx.x * 128;
    const int wm = (wid & 3) * 32;
    const int wn = (wid >> 2) * 64;

    float acc[2][8][4];
#pragma unroll
    for (int i = 0; i < 2; i++)
#pragma unroll
        for (int j = 0; j < 8; j++)
#pragma unroll
            for (int k = 0; k < 4; k++) acc[i][j][k] = 0.0f;

    const __half* srcs[3] = {Ah, Al, Bh};
    const int lds[3] = {lda, lda, ldb};
    const int r0s[3] = {m0, m0, n0};

    const unsigned smb = smem_u32(smem);

    auto issue_stage = [&](int t, int buf) {
        const int k0 = t * 32;
        const unsigned sb = smb + buf * STAGE_B;
#pragma unroll
        for (int i = 0; i < 6; i++) {
            const int id = i * 256 + tid;
            const int tile = id >> 9;
            const int cid = id & 511;
            const int row = cid >> 2;
            const int c = cid & 3;
            const __half* g =
                srcs[tile] + (size_t)(r0s[tile] + row) * lds[tile] + k0 + c * 8;
            CP_ASYNC16(sb + tile * TILE_B + row * 80 + c * 16, g);
        }
        CP_COMMIT();
    };

    const int T = K >> 5;
    issue_stage(0, 0);
    issue_stage(1, 1);

    const unsigned a_lrow = (lane & 15) * 80 + (lane >> 4) * 16;
    const unsigned b_lrow = ((lane & 7) + ((lane >> 4) << 3)) * 80 + ((lane >> 3) & 1) * 16;

    for (int t = 0; t < T; t++) {
        if (t + 2 < T) { issue_stage(t + 2, (t + 2) % 3); CP_WAIT2(); }
        else if (t + 1 < T) { CP_WAIT1(); }
        else { CP_WAIT0(); }
        __syncthreads();

        const unsigned st = smb + (t % 3) * STAGE_B;
        const unsigned aHb = st + wm * 80 + a_lrow;
        const unsigned aLb = st + TILE_B + wm * 80 + a_lrow;
        const unsigned bHb = st + 2 * TILE_B + wn * 80 + b_lrow;

#pragma unroll
        for (int ks = 0; ks < 2; ks++) {
            unsigned aH[2][4], aL[2][4];
#pragma unroll
            for (int mt = 0; mt < 2; mt++) {
                LDM_X4(aH[mt], aHb + mt * (16 * 80) + ks * 32);
                LDM_X4(aL[mt], aLb + mt * (16 * 80) + ks * 32);
            }
#pragma unroll
            for (int ng = 0; ng < 4; ng++) {
                unsigned bH[4];
                LDM_X4(bH, bHb + ng * (16 * 80) + ks * 32);
#pragma unroll
                for (int mt = 0; mt < 2; mt++) {
                    MMA_FP(acc[mt][2 * ng],     aH[mt], bH[0], bH[1]);
                    MMA_FP(acc[mt][2 * ng + 1], aH[mt], bH[2], bH[3]);
                    MMA_FP(acc[mt][2 * ng],     aL[mt], bH[0], bH[1]);
                    MMA_FP(acc[mt][2 * ng + 1], aL[mt], bH[2], bH[3]);
                }
            }
        }
        __syncthreads();
    }

#pragma unroll
    for (int mt = 0; mt < 2; mt++) {
        const int m = m0 + wm + mt * 16 + (lane >> 2);
#pragma unroll
        for (int nt = 0; nt < 8; nt++) {
            const int n = n0 + wn + nt * 8 + (lane & 3) * 2;
            float bx = 0.0f, by = 0.0f;
            if (OM != 1 && bias) { bx = bias[n]; by = bias[n + 1]; }
            float v00 = acc[mt][nt][0] + bx, v01 = acc[mt][nt][1] + by;
            float v10 = acc[mt][nt][2] + bx, v11 = acc[mt][nt][3] + by;
            if (OM == 0) {
                *(float2*)(C + (size_t)m * ldc + n) = make_float2(v00, v01);
                *(float2*)(C + (size_t)(m + 8) * ldc + n) = make_float2(v10, v11);
            } else if (OM == 1) {
                unsigned hp = pack_f16(v00, v01);
                *(unsigned*)(Coh + (size_t)m * ldc + n) = hp;
                *(unsigned*)(Col + (size_t)m * ldc + n) = pack_res_f16(v00, v01, hp);
                hp = pack_f16(v10, v11);
                *(unsigned*)(Coh + (size_t)(m + 8) * ldc + n) = hp;
                *(unsigned*)(Col + (size_t)(m + 8) * ldc + n) = pack_res_f16(v10, v11, hp);
            } else {
                const int h = n / 384;
                const int r = n - h * 384;
                const int stp = r >> 7;
                const int d = r & 127;
                __nv_bfloat16* Dh = (stp == 0) ? g_Qh : ((stp == 1) ? g_Kh : g_Vh);
                __nv_bfloat16* Dl = (stp == 0) ? g_Ql : ((stp == 1) ? g_Kl : g_Vl);
                size_t o = ((size_t)h * 2048 + m) * 128 + d;
                unsigned hp = pack_bf16(v00, v01);
                *(unsigned*)(Dh + o) = hp;
                *(unsigned*)(Dl + o) = pack_res_bf(v00, v01, hp);
                o += 8 * 128;
                hp = pack_bf16(v10, v11);
                *(unsigned*)(Dh + o) = hp;
                *(unsigned*)(Dl + o) = pack_res_bf(v10, v11, hp);
            }
        }
    }

    // symmetric mirror: stage transposed tile in smem, write to (n0, m0)
    if (SYM && OM == 1 && blockIdx.x != blockIdx.y) {
        __syncthreads();
        __half* sh = (__half*)smem;
        __half* sl = sh + 128 * 136;
#pragma unroll
        for (int mt = 0; mt < 2; mt++) {
            const int ml = wm + mt * 16 + (lane >> 2);
#pragma unroll
            for (int nt = 0; nt < 8; nt++) {
                const int nl = wn + nt * 8 + (lane & 3) * 2;
                float v00 = acc[mt][nt][0], v01 = acc[mt][nt][1];
                float v10 = acc[mt][nt][2], v11 = acc[mt][nt][3];
                __half h;
                h = __float2half(v00); sh[nl * 136 + ml] = h;
                sl[nl * 136 + ml] = __float2half(v00 - __half2float(h));
                h = __float2half(v01); sh[(nl + 1) * 136 + ml] = h;
                sl[(nl + 1) * 136 + ml] = __float2half(v01 - __half2float(h));
                h = __float2half(v10); sh[nl * 136 + ml + 8] = h;
                sl[nl * 136 + ml + 8] = __float2half(v10 - __half2float(h));
                h = __float2half(v11); sh[(nl + 1) * 136 + ml + 8] = h;
                sl[(nl + 1) * 136 + ml + 8] = __float2half(v11 - __half2float(h));
            }
        }
        __syncthreads();
        for (int e = tid; e < 128 * 16; e += 256) {
            const int r = e >> 4, c4 = e & 15;
            uint4 v = *(uint4*)(sh + r * 136 + c4 * 8);
            *(uint4*)(Coh + (size_t)(n0 + r) * ldc + m0 + c4 * 8) = v;
            v = *(uint4*)(sl + r * 136 + c4 * 8);
            *(uint4*)(Col + (size_t)(n0 + r) * ldc + m0 + c4 * 8) = v;
        }
    }
}

// ---------------------------------------------------------------------------
// Tensor-core causal flash attention (bf16x3). 128 Q rows x head per block.
// Q/K/V bf16 hi/lo [h][t][d]; V loaded via ldmatrix.trans (no pre-transpose).
// Output: ctx as fp16 hi/lo [t][2048].
// ---------------------------------------------------------------------------
#define AQ_PITCH 272
#define SQH_B (128 * AQ_PITCH)
#define SKH_B (64 * AQ_PITCH)
#define KV_STAGE (4 * SKH_B)
#define ATTN2_SMEM (2 * SQH_B + 2 * KV_STAGE)

__global__ __launch_bounds__(256, 1) void attn_mma(
    const __nv_bfloat16* __restrict__ Qh_, const __nv_bfloat16* __restrict__ Ql_,
    const __nv_bfloat16* __restrict__ Kh_, const __nv_bfloat16* __restrict__ Kl_,
    const __nv_bfloat16* __restrict__ Vh_, const __nv_bfloat16* __restrict__ Vl_,
    __half* __restrict__ Ch_, __half* __restrict__ Cl_)
{
    extern __shared__ __align__(16) char sm[];
    const int h = blockIdx.y;
    const int rb = (int)gridDim.x - 1 - (int)blockIdx.x;
    const int r0 = rb * 128;
    const int tid = threadIdx.x;
    const int wid = tid >> 5;
    const int lane = tid & 31;

    const unsigned sQh = smem_u32(sm);
    const unsigned sQl = sQh + SQH_B;
    const unsigned sKV0 = sQl + SQH_B;

    {
        const __nv_bfloat16* gq = Qh_ + ((size_t)h * 2048 + r0) * 128;
        const __nv_bfloat16* gql = Ql_ + ((size_t)h * 2048 + r0) * 128;
#pragma unroll
        for (int it = 0; it < 8; it++) {
            int id = it * 256 + tid;
            int row = id >> 4, c = id & 15;
            CP_ASYNC16(sQh + row * AQ_PITCH + c * 16, gq + (size_t)row * 128 + c * 8);
            CP_ASYNC16(sQl + row * AQ_PITCH + c * 16, gql + (size_t)row * 128 + c * 8);
        }
    }
    const __nv_bfloat16* gK = Kh_ + (size_t)h * 2048 * 128;
    const __nv_bfloat16* gKl = Kl_ + (size_t)h * 2048 * 128;
    const __nv_bfloat16* gV = Vh_ + (size_t)h * 2048 * 128;
    const __nv_bfloat16* gVl = Vl_ + (size_t)h * 2048 * 128;

    auto issue_kv = [&](int t, int buf) {
        const int t0 = t * 64;
        const unsigned sb = sKV0 + buf * KV_STAGE;
#pragma unroll
        for (int it = 0; it < 4; it++) {
            int id = it * 256 + tid;
            int row = id >> 4, c = id & 15;
            size_t go = (size_t)(t0 + row) * 128 + c * 8;
            unsigned so = row * AQ_PITCH + c * 16;
            CP_ASYNC16(sb + so, gK + go);
            CP_ASYNC16(sb + SKH_B + so, gKl + go);
            CP_ASYNC16(sb + 2 * SKH_B + so, gV + go);
            CP_ASYNC16(sb + 3 * SKH_B + so, gVl + go);
        }
    };

    issue_kv(0, 0);
    CP_COMMIT();

    float sacc[8][4];
    float Oacc[16][4];
#pragma unroll
    for (int i = 0; i < 16; i++)
#pragma unroll
        for (int j = 0; j < 4; j++) Oacc[i][j] = 0.0f;
    float m1 = -1e30f, m2 = -1e30f, l1 = 0.0f, l2 = 0.0f;

    const int gr1 = r0 + wid * 16 + (lane >> 2);
    const int gr2 = gr1 + 8;
    const float scale = 0.08838834764831845f;

    const unsigned a_off = (lane & 15) * AQ_PITCH + (lane >> 4) * 16;
    const unsigned kb_off = ((lane & 7) + ((lane >> 4) << 3)) * AQ_PITCH + ((lane >> 3) & 1) * 16;
    const unsigned aQh_b = sQh + wid * 16 * AQ_PITCH + a_off;
    const unsigned aQl_b = sQl + wid * 16 * AQ_PITCH + a_off;

    const int T = 2 * rb + 2;
    for (int t = 0; t < T; t++) {
        if (t + 1 < T) { issue_kv(t + 1, (t + 1) & 1); CP_COMMIT(); CP_WAIT1(); }
        else { CP_WAIT0(); }
        __syncthreads();

        const unsigned sb = sKV0 + (t & 1) * KV_STAGE;
        const unsigned kh_b = sb + kb_off;
        const unsigned kl_b = sb + SKH_B + kb_off;

#pragma unroll
        for (int i = 0; i < 8; i++)
#pragma unroll
            for (int j = 0; j < 4; j++) sacc[i][j] = 0.0f;

#pragma unroll
        for (int kd = 0; kd < 8; kd++) {
            unsigned qh[4], ql[4];
            LDM_X4(qh, aQh_b + kd * 32);
            LDM_X4(ql, aQl_b + kd * 32);
#pragma unroll
            for (int ng = 0; ng < 4; ng++) {
                unsigned bh[4], bl[4];
                LDM_X4(bh, kh_b + ng * (16 * AQ_PITCH) + kd * 32);
                LDM_X4(bl, kl_b + ng * (16 * AQ_PITCH) + kd * 32);
                MMA_BF(sacc[2 * ng],     qh, bh[0], bh[1]);
                MMA_BF(sacc[2 * ng + 1], qh, bh[2], bh[3]);
                MMA_BF(sacc[2 * ng],     qh, bl[0], bl[1]);
                MMA_BF(sacc[2 * ng + 1], qh, bl[2], bl[3]);
                MMA_BF(sacc[2 * ng],     ql, bh[0], bh[1]);
                MMA_BF(sacc[2 * ng + 1], ql, bh[2], bh[3]);
            }
        }

        const int c0 = t * 64;
#pragma unroll
        for (int nt = 0; nt < 8; nt++)
#pragma unroll
            for (int j = 0; j < 4; j++) sacc[nt][j] *= scale;

        if (t >= 2 * rb) {
#pragma unroll
            for (int nt = 0; nt < 8; nt++) {
                int col = c0 + nt * 8 + (lane & 3) * 2;
                if (col     > gr1) sacc[nt][0] = -1e30f;
                if (col + 1 > gr1) sacc[nt][1] = -1e30f;
                if (col     > gr2) sacc[nt][2] = -1e30f;
                if (col + 1 > gr2) sacc[nt][3] = -1e30f;
            }
        }

        float mx1 = -1e30f, mx2 = -1e30f;
#pragma unroll
        for (int nt = 0; nt < 8; nt++) {
            mx1 = fmaxf(mx1, fmaxf(sacc[nt][0], sacc[nt][1]));
            mx2 = fmaxf(mx2, fmaxf(sacc[nt][2], sacc[nt][3]));
        }
        mx1 = fmaxf(mx1, __shfl_xor_sync(0xffffffffu, mx1, 1));
        mx1 = fmaxf(mx1, __shfl_xor_sync(0xffffffffu, mx1, 2));
        mx2 = fmaxf(mx2, __shfl_xor_sync(0xffffffffu, mx2, 1));
        mx2 = fmaxf(mx2, __shfl_xor_sync(0xffffffffu, mx2, 2));
        const float mn1 = fmaxf(m1, mx1), mn2 = fmaxf(m2, mx2);
        const float corr1 = __expf(m1 - mn1), corr2 = __expf(m2 - mn2);
        m1 = mn1; m2 = mn2;
        float rs1 = 0.0f, rs2 = 0.0f;
#pragma unroll
        for (int nt = 0; nt < 8; nt++) {
            sacc[nt][0] = __expf(sacc[nt][0] - m1); rs1 += sacc[nt][0];
            sacc[nt][1] = __expf(sacc[nt][1] - m1); rs1 += sacc[nt][1];
            sacc[nt][2] = __expf(sacc[nt][2] - m2); rs2 += sacc[nt][2];
            sacc[nt][3] = __expf(sacc[nt][3] - m2); rs2 += sacc[nt][3];
        }
        rs1 += __shfl_xor_sync(0xffffffffu, rs1, 1);
        rs1 += __shfl_xor_sync(0xffffffffu, rs1, 2);
        rs2 += __shfl_xor_sync(0xffffffffu, rs2, 1);
        rs2 += __shfl_xor_sync(0xffffffffu, rs2, 2);
        l1 = l1 * corr1 + rs1;
        l2 = l2 * corr2 + rs2;
#pragma unroll
        for (int nt = 0; nt < 16; nt++) {
            Oacc[nt][0] *= corr1; Oacc[nt][1] *= corr1;
            Oacc[nt][2] *= corr2; Oacc[nt][3] *= corr2;
        }

        const unsigned vh_b = sb + 2 * SKH_B + a_off;
        const unsigned vl_b = sb + 3 * SKH_B + a_off;
#pragma unroll
        for (int kt = 0; kt < 4; kt++) {
            unsigned ph[4], pl[4];
            ph[0] = pack_bf16(sacc[2 * kt][0], sacc[2 * kt][1]);
            ph[1] = pack_bf16(sacc[2 * kt][2], sacc[2 * kt][3]);
            ph[2] = pack_bf16(sacc[2 * kt + 1][0], sacc[2 * kt + 1][1]);
            ph[3] = pack_bf16(sacc[2 * kt + 1][2], sacc[2 * kt + 1][3]);
            pl[0] = pack_res_bf(sacc[2 * kt][0], sacc[2 * kt][1], ph[0]);
            pl[1] = pack_res_bf(sacc[2 * kt][2], sacc[2 * kt][3], ph[1]);
            pl[2] = pack_res_bf(sacc[2 * kt + 1][0], sacc[2 * kt + 1][1], ph[2]);
            pl[3] = pack_res_bf(sacc[2 * kt + 1][2], sacc[2 * kt + 1][3], ph[3]);
#pragma unroll
            for (int ng = 0; ng < 8; ng++) {
                unsigned vh[4], vl[4];
                LDM_X4_T(vh, vh_b + kt * (16 * AQ_PITCH) + ng * 32);
                LDM_X4_T(vl, vl_b + kt * (16 * AQ_PITCH) + ng * 32);
                MMA_BF(Oacc[2 * ng],     ph, vh[0], vh[1]);
                MMA_BF(Oacc[2 * ng + 1], ph, vh[2], vh[3]);
                MMA_BF(Oacc[2 * ng],     ph, vl[0], vl[1]);
                MMA_BF(Oacc[2 * ng + 1], ph, vl[2], vl[3]);
                MMA_BF(Oacc[2 * ng],     pl, vh[0], vh[1]);
                MMA_BF(Oacc[2 * ng + 1], pl, vh[2], vh[3]);
            }
        }
        __syncthreads();
    }

    const float inv1 = 1.0f / l1, inv2 = 1.0f / l2;
#pragma unroll
    for (int nt = 0; nt < 16; nt++) {
        const int colb = h * 128 + nt * 8 + (lane & 3) * 2;
        float o0 = Oacc[nt][0] * inv1, o1 = Oacc[nt][1] * inv1;
        unsigned hp = pack_f16(o0, o1);
        *(unsigned*)(Ch_ + (size_t)gr1 * 2048 + colb) = hp;
        *(unsigned*)(Cl_ + (size_t)gr1 * 2048 + colb) = pack_res_f16(o0, o1, hp);
        o0 = Oacc[nt][2] * inv2; o1 = Oacc[nt][3] * inv2;
        hp = pack_f16(o0, o1);
        *(unsigned*)(Ch_ + (size_t)gr2 * 2048 + colb) = hp;
        *(unsigned*)(Cl_ + (size_t)gr2 * 2048 + colb) = pack_res_f16(o0, o1, hp);
    }
}

// ---------------------------------------------------------------------------
extern "C" void kernel_launch(void* const* d_in, const int* in_sizes, int n_in,
                              void* d_out, int out_size)
{
    (void)in_sizes; (void)n_in; (void)out_size;
    const float* hidden  = (const float*)d_in[0];
    const float* qkv_w   = (const float*)d_in[2];
    const float* qkv_b   = (const float*)d_in[3];
    const float* svd_tok = (const float*)d_in[4];
    const float* svd_qk  = (const float*)d_in[5];
    const float* svd_vl  = (const float*)d_in[6];
    const float* dense_w = (const float*)d_in[7];
    const float* dense_b = (const float*)d_in[8];
    float* out = (float*)d_out;

    float *pS, *pP, *pW2, *pbmod;
    cudaGetSymbolAddress((void**)&pS, g_S);
    cudaGetSymbolAddress((void**)&pP, g_P);
    cudaGetSymbolAddress((void**)&pW2, g_W2);
    cudaGetSymbolAddress((void**)&pbmod, g_bmod);

    __half *pHh, *pHl, *pRh, *pRl, *pMh, *pMl, *pX2h, *pX2l;
    __half *pWqh, *pWql, *pCh, *pCl, *pW2Th, *pW2Tl;
    cudaGetSymbolAddress((void**)&pHh, g_Hh);   cudaGetSymbolAddress((void**)&pHl, g_Hl);
    cudaGetSymbolAddress((void**)&pRh, g_Rh);   cudaGetSymbolAddress((void**)&pRl, g_Rl);
    cudaGetSymbolAddress((void**)&pMh, g_Mh);   cudaGetSymbolAddress((void**)&pMl, g_Ml);
    cudaGetSymbolAddress((void**)&pX2h, g_X2h); cudaGetSymbolAddress((void**)&pX2l, g_X2l);
    cudaGetSymbolAddress((void**)&pWqh, g_Wqh); cudaGetSymbolAddress((void**)&pWql, g_Wql);
    cudaGetSymbolAddress((void**)&pCh, g_Ch);   cudaGetSymbolAddress((void**)&pCl, g_Cl);
    cudaGetSymbolAddress((void**)&pW2Th, g_W2Th); cudaGetSymbolAddress((void**)&pW2Tl, g_W2Tl);

    __nv_bfloat16 *pQh, *pQl, *pKh, *pKl, *pVh, *pVl;
    cudaGetSymbolAddress((void**)&pQh, g_Qh);   cudaGetSymbolAddress((void**)&pQl, g_Ql);
    cudaGetSymbolAddress((void**)&pKh, g_Kh);   cudaGetSymbolAddress((void**)&pKl, g_Kl);
    cudaGetSymbolAddress((void**)&pVh, g_Vh);   cudaGetSymbolAddress((void**)&pVl, g_Vl);

    cudaFuncSetAttribute((const void*)mma_gemm<0, false>, cudaFuncAttributeMaxDynamicSharedMemorySize, GEMM_SMEM);
    cudaFuncSetAttribute((const void*)mma_gemm<1, false>, cudaFuncAttributeMaxDynamicSharedMemorySize, GEMM_SMEM);
    cudaFuncSetAttribute((const void*)mma_gemm<1, true>,  cudaFuncAttributeMaxDynamicSharedMemorySize, GEMM_SMEM);
    cudaFuncSetAttribute((const void*)mma_gemm<2, false>, cudaFuncAttributeMaxDynamicSharedMemorySize, GEMM_SMEM);
    cudaFuncSetAttribute((const void*)attn_mma, cudaFuncAttributeMaxDynamicSharedMemorySize, ATTN2_SMEM);

    // Side stream + join events (created once; same graph content every call).
    static cudaStream_t s2 = nullptr;
    static cudaEvent_t eFork = nullptr, eH = nullptr, ePrep = nullptr, eW2 = nullptr;
    if (!s2) {
        cudaStreamCreateWithFlags(&s2, cudaStreamNonBlocking);
        cudaEventCreateWithFlags(&eFork, cudaEventDisableTiming);
        cudaEventCreateWithFlags(&eH, cudaEventDisableTiming);
        cudaEventCreateWithFlags(&ePrep, cudaEventDisableTiming);
        cudaEventCreateWithFlags(&eW2, cudaEventDisableTiming);
    }

    const dim3 blk(256);
    const int N4_2048 = (2048 * 2048) / 4;
    const int N4_W = (6144 * 2048) / 4;

    // ---- fork: side chain on s2, critical path on stream 0 ----
    cudaEventRecord(eFork, 0);
    cudaStreamWaitEvent(s2, eFork, 0);

    // s2: hidden conversion (needed by X2)
    cvt_split_f16<<<N4_2048 / 256, 256, 0, s2>>>((const float4*)hidden,
        (__half2*)pHh, (__half2*)pHl, N4_2048, 0);
    cudaEventRecord(eH, s2);
    // s2: qkv_w conversion (k/v rows), S/P, weight folds, rotated bias
    cvt_split_f16<<<N4_W / 256, 256, 0, s2>>>((const float4*)qkv_w,
        (__half2*)pWqh, (__half2*)pWql, N4_W, 1);
    sgemm_SP<<<dim3(1, 1, 32), blk, 0, s2>>>(svd_qk, svd_vl, pS, pP);
    sgemm_fold<<<dim3(16, 1, 32), blk, 0, s2>>>(pS, pP, qkv_w, dense_w, pWqh, pWql, pW2);
    bias_rot<<<24, 256, 0, s2>>>(pS, qkv_b, pbmod);
    cudaEventRecord(ePrep, s2);
    trans_cvt_f16<<<dim3(64, 64), dim3(32, 8), 0, s2>>>(pW2, pW2Th, pW2Tl);
    cudaEventRecord(eW2, s2);

    // stream 0 (critical path): R conversion -> M
    cvt_split_f16<<<N4_2048 / 256, 256>>>((const float4*)svd_tok,
        (__half2*)pRh, (__half2*)pRl, N4_2048, 0);
    // 1) M = R @ R^T -> fp16 hi/lo (symmetric: upper triangle + mirror)
    mma_gemm<1, true><<<dim3(16, 16), blk, GEMM_SMEM>>>(pRh, pRl, pRh,
        nullptr, pMh, pMl, 2048, nullptr, 2048, 2048, 2048);

    // 2) X2 = hidden @ M^T (needs Hh from s2)
    cudaStreamWaitEvent(0, eH, 0);
    mma_gemm<1, false><<<dim3(16, 16), blk, GEMM_SMEM>>>(pHh, pHl, pMh,
        nullptr, pX2h, pX2l, 2048, nullptr, 2048, 2048, 2048);

    // 3) [q'|k|v] = X2 @ Wmod^T + bmod (needs fold + cvtW + bias from s2)
    cudaStreamWaitEvent(0, ePrep, 0);
    mma_gemm<2, false><<<dim3(48, 16), blk, GEMM_SMEM>>>(pX2h, pX2l, pWqh,
        nullptr, nullptr, nullptr, 0, pbmod, 2048, 2048, 2048);

    // 4) attention -> ctx fp16 hi/lo
    attn_mma<<<dim3(16, 16), blk, ATTN2_SMEM>>>(pQh, pQl, pKh, pKl, pVh, pVl, pCh, pCl);

    // 5) out = ctx @ W2 + dense_b (needs W2T from s2)
    cudaStreamWaitEvent(0, eW2, 0);
    mma_gemm<0, false><<<dim3(16, 16), blk, GEMM_SMEM>>>(pCh, pCl, pW2Th,
        out, nullptr, nullptr, 2048, dense_b, 2048, 2048, 2048);
}